// round 2
// baseline (speedup 1.0000x reference)
#include <cuda_runtime.h>
#include <math.h>

// Problem constants
#define BB 4
#define TT 2048
#define EE 1024
#define HH 16
#define HD 64
#define MM (BB*TT)          // 8192 rows
#define E2 (EE/2)           // 512 pairs

// ---------------- scratch (device globals; no allocation allowed) ----------
__device__ float g_sin[TT*E2];
__device__ float g_cos[TT*E2];
__device__ float g_rx [MM*EE];
__device__ float g_q  [MM*EE];
__device__ float g_k  [MM*EE];
__device__ float g_v  [MM*EE];
__device__ float g_at [MM*EE];

// ---------------- RoPE tables ----------------------------------------------
__global__ void rope_table_kernel() {
    int idx = blockIdx.x * blockDim.x + threadIdx.x;
    if (idx >= TT*E2) return;
    int t = idx / E2;
    int p = idx % E2;
    double theta_d = exp((-(double)(2*p) / (double)EE) * log(10000.0));
    float theta = (float)theta_d;
    float ang = (float)t * theta;          // fp32 rounding as in reference
    double s, c;
    sincos((double)ang, &s, &c);           // near-exact sin/cos of the fp32 angle
    g_sin[idx] = (float)s;
    g_cos[idx] = (float)c;
}

__global__ void rope_apply_kernel(const float* __restrict__ x) {
    int idx = blockIdx.x * blockDim.x + threadIdx.x;   // over MM*E2 pairs
    if (idx >= MM*E2) return;
    int bt = idx / E2;
    int p  = idx % E2;
    int t  = bt % TT;
    float2 v = ((const float2*)x)[idx];
    float s = g_sin[t*E2 + p];
    float c = g_cos[t*E2 + p];
    float2 r;
    r.x = v.x * c - v.y * s;
    r.y = v.y * c + v.x * s;
    ((float2*)g_rx)[idx] = r;
}

// ---------------- fp32 NT GEMM: C[m][n] = sum_k A[m][k]*W[n][k] (+bias[n]) --
#define GK 1024
#define APAD 68

__global__ __launch_bounds__(256)
void gemm_nt_kernel(const float* __restrict__ A, const float* __restrict__ W,
                    float* __restrict__ C, const float* __restrict__ bias) {
    __shared__ float As[16][APAD];
    __shared__ float Bs[16][APAD];

    const int tid = threadIdx.x;
    const int tx = tid & 15;        // col group
    const int ty = tid >> 4;        // row group
    const int row0 = blockIdx.y * 64;
    const int col0 = blockIdx.x * 64;

    const int lr = tid >> 2;        // 0..63 (tile row to load)
    const int lk = (tid & 3) * 4;   // 0,4,8,12 (k offset)

    const float* Aptr = A + (size_t)(row0 + lr) * GK + lk;
    const float* Wptr = W + (size_t)(col0 + lr) * GK + lk;

    float acc[4][4] = {};

    for (int k0 = 0; k0 < GK; k0 += 16) {
        float4 a4 = *(const float4*)(Aptr + k0);
        float4 w4 = *(const float4*)(Wptr + k0);
        __syncthreads();
        As[lk+0][lr] = a4.x; As[lk+1][lr] = a4.y;
        As[lk+2][lr] = a4.z; As[lk+3][lr] = a4.w;
        Bs[lk+0][lr] = w4.x; Bs[lk+1][lr] = w4.y;
        Bs[lk+2][lr] = w4.z; Bs[lk+3][lr] = w4.w;
        __syncthreads();
        #pragma unroll
        for (int k = 0; k < 16; k++) {
            float4 av = *(const float4*)&As[k][ty*4];
            float4 bv = *(const float4*)&Bs[k][tx*4];
            float a[4] = {av.x, av.y, av.z, av.w};
            float b[4] = {bv.x, bv.y, bv.z, bv.w};
            #pragma unroll
            for (int i = 0; i < 4; i++)
                #pragma unroll
                for (int j = 0; j < 4; j++)
                    acc[i][j] = fmaf(a[i], b[j], acc[i][j]);
        }
    }

    float bv[4] = {0.f, 0.f, 0.f, 0.f};
    if (bias) {
        bv[0] = bias[col0 + tx*4 + 0];
        bv[1] = bias[col0 + tx*4 + 1];
        bv[2] = bias[col0 + tx*4 + 2];
        bv[3] = bias[col0 + tx*4 + 3];
    }
    #pragma unroll
    for (int i = 0; i < 4; i++) {
        float4 o;
        o.x = acc[i][0] + bv[0];
        o.y = acc[i][1] + bv[1];
        o.z = acc[i][2] + bv[2];
        o.w = acc[i][3] + bv[3];
        *(float4*)(C + (size_t)(row0 + ty*4 + i) * GK + col0 + tx*4) = o;
    }
}

// ---------------- flash attention (causal, fp32) ----------------------------
#define QPAD 68
#define SPAD 65
#define FLASH_SMEM_FLOATS (3*64*QPAD + 64*SPAD + 3*64)

__global__ __launch_bounds__(256)
void flash_kernel(const float* __restrict__ q, const float* __restrict__ k,
                  const float* __restrict__ v, float* __restrict__ o) {
    extern __shared__ float sm[];
    float* Qs   = sm;                    // [d][q] : 64 x QPAD
    float* Ks   = Qs + 64*QPAD;          // [d][c]
    float* Vs   = Ks + 64*QPAD;          // [c][d]
    float* Ss   = Vs + 64*QPAD;          // [q][c] : 64 x SPAD
    float* mrow = Ss + 64*SPAD;
    float* lrow = mrow + 64;
    float* resc = lrow + 64;

    const int tid = threadIdx.x;
    const int tx = tid & 15;
    const int ty = tid >> 4;
    const int qtile = blockIdx.x;
    const int bh = blockIdx.y;
    const int b = bh >> 4;
    const int h = bh & 15;
    const int row_base = b*TT + qtile*64;
    const int col_base = h*HD;

    const int fr = tid >> 4;    // 0..15 (tile row for loads)
    const int fc = tid & 15;    // 0..15 (float4 column)

    // Load Q tile transposed into Qs[d][q]
    #pragma unroll
    for (int l = 0; l < 4; l++) {
        int r = fr + 16*l;
        float4 qv = *(const float4*)(q + (size_t)(row_base + r)*EE + col_base + fc*4);
        Qs[(fc*4+0)*QPAD + r] = qv.x;
        Qs[(fc*4+1)*QPAD + r] = qv.y;
        Qs[(fc*4+2)*QPAD + r] = qv.z;
        Qs[(fc*4+3)*QPAD + r] = qv.w;
    }
    if (tid < 64) { mrow[tid] = -INFINITY; lrow[tid] = 0.f; }

    float acc[4][4] = {};

    for (int kt = 0; kt <= qtile; kt++) {
        __syncthreads();   // prior-iter GEMM2 done with Ss/Vs; Qs/mrow ready (iter 0)
        const int kv_row = b*TT + kt*64;
        #pragma unroll
        for (int l = 0; l < 4; l++) {
            int r = fr + 16*l;
            float4 k4 = *(const float4*)(k + (size_t)(kv_row + r)*EE + col_base + fc*4);
            Ks[(fc*4+0)*QPAD + r] = k4.x;
            Ks[(fc*4+1)*QPAD + r] = k4.y;
            Ks[(fc*4+2)*QPAD + r] = k4.z;
            Ks[(fc*4+3)*QPAD + r] = k4.w;
            float4 v4 = *(const float4*)(v + (size_t)(kv_row + r)*EE + col_base + fc*4);
            *(float4*)&Vs[r*QPAD + fc*4] = v4;
        }
        __syncthreads();

        // GEMM1: S[q][c] = sum_d Q[q][d] * K[c][d]
        float s[4][4] = {};
        #pragma unroll
        for (int d = 0; d < 64; d++) {
            float4 qv = *(const float4*)&Qs[d*QPAD + ty*4];
            float4 kv = *(const float4*)&Ks[d*QPAD + tx*4];
            float a[4] = {qv.x, qv.y, qv.z, qv.w};
            float bq[4] = {kv.x, kv.y, kv.z, kv.w};
            #pragma unroll
            for (int i = 0; i < 4; i++)
                #pragma unroll
                for (int j = 0; j < 4; j++)
                    s[i][j] = fmaf(a[i], bq[j], s[i][j]);
        }
        // epilogue: scale + causal mask, write Ss[q][c]
        const bool diag = (kt == qtile);
        #pragma unroll
        for (int i = 0; i < 4; i++) {
            int qq = ty*4 + i;
            #pragma unroll
            for (int j = 0; j < 4; j++) {
                int cc = tx*4 + j;
                float val = s[i][j] * 0.125f;   // 1/sqrt(64)
                if (diag && cc > qq) val = -INFINITY;
                Ss[qq*SPAD + cc] = val;
            }
        }
        __syncthreads();

        // Online softmax: thread t<64 owns row t
        if (tid < 64) {
            float mOld = mrow[tid];
            float mNew = mOld;
            #pragma unroll 8
            for (int c = 0; c < 64; c++)
                mNew = fmaxf(mNew, Ss[tid*SPAD + c]);
            float rsc = __expf(mOld - mNew);
            float ls = 0.f;
            #pragma unroll 8
            for (int c = 0; c < 64; c++) {
                float p = __expf(Ss[tid*SPAD + c] - mNew);
                Ss[tid*SPAD + c] = p;
                ls += p;
            }
            lrow[tid] = lrow[tid] * rsc + ls;
            mrow[tid] = mNew;
            resc[tid] = rsc;
        }
        __syncthreads();

        // GEMM2: O[q][d] = O*resc + P[q][c] * V[c][d]
        float rs[4];
        #pragma unroll
        for (int i = 0; i < 4; i++) rs[i] = resc[ty*4 + i];
        #pragma unroll
        for (int i = 0; i < 4; i++)
            #pragma unroll
            for (int j = 0; j < 4; j++)
                acc[i][j] *= rs[i];
        #pragma unroll
        for (int c = 0; c < 64; c++) {
            float4 vv = *(const float4*)&Vs[c*QPAD + tx*4];
            float p0 = Ss[(ty*4+0)*SPAD + c];
            float p1 = Ss[(ty*4+1)*SPAD + c];
            float p2 = Ss[(ty*4+2)*SPAD + c];
            float p3 = Ss[(ty*4+3)*SPAD + c];
            acc[0][0]=fmaf(p0,vv.x,acc[0][0]); acc[0][1]=fmaf(p0,vv.y,acc[0][1]);
            acc[0][2]=fmaf(p0,vv.z,acc[0][2]); acc[0][3]=fmaf(p0,vv.w,acc[0][3]);
            acc[1][0]=fmaf(p1,vv.x,acc[1][0]); acc[1][1]=fmaf(p1,vv.y,acc[1][1]);
            acc[1][2]=fmaf(p1,vv.z,acc[1][2]); acc[1][3]=fmaf(p1,vv.w,acc[1][3]);
            acc[2][0]=fmaf(p2,vv.x,acc[2][0]); acc[2][1]=fmaf(p2,vv.y,acc[2][1]);
            acc[2][2]=fmaf(p2,vv.z,acc[2][2]); acc[2][3]=fmaf(p2,vv.w,acc[2][3]);
            acc[3][0]=fmaf(p3,vv.x,acc[3][0]); acc[3][1]=fmaf(p3,vv.y,acc[3][1]);
            acc[3][2]=fmaf(p3,vv.z,acc[3][2]); acc[3][3]=fmaf(p3,vv.w,acc[3][3]);
        }
    }

    // normalize and write out (B,T,E) with head offset
    #pragma unroll
    for (int i = 0; i < 4; i++) {
        int qq = ty*4 + i;
        float inv = 1.f / lrow[qq];
        float4 ov;
        ov.x = acc[i][0] * inv;
        ov.y = acc[i][1] * inv;
        ov.z = acc[i][2] * inv;
        ov.w = acc[i][3] * inv;
        *(float4*)(o + (size_t)(row_base + qq)*EE + col_base + tx*4) = ov;
    }
}

// ---------------- launch ----------------------------------------------------
extern "C" void kernel_launch(void* const* d_in, const int* in_sizes, int n_in,
                              void* d_out, int out_size) {
    const float* x  = (const float*)d_in[0];
    const float* Wq = (const float*)d_in[1];
    const float* Wk = (const float*)d_in[2];
    const float* Wv = (const float*)d_in[3];
    const float* Wo = (const float*)d_in[4];
    const float* bo = (const float*)d_in[5];
    float* out = (float*)d_out;

    // Resolve REAL device addresses of the scratch globals.
    // (Passing the symbols directly from host code passes the host shadow
    //  address — on GB300 ATS the GPU silently reads host memory. Round-1 bug.)
    float *p_rx, *p_q, *p_k, *p_v, *p_at;
    cudaGetSymbolAddress((void**)&p_rx, g_rx);
    cudaGetSymbolAddress((void**)&p_q,  g_q);
    cudaGetSymbolAddress((void**)&p_k,  g_k);
    cudaGetSymbolAddress((void**)&p_v,  g_v);
    cudaGetSymbolAddress((void**)&p_at, g_at);

    const int flash_smem = FLASH_SMEM_FLOATS * (int)sizeof(float);
    cudaFuncSetAttribute(flash_kernel,
                         cudaFuncAttributeMaxDynamicSharedMemorySize, flash_smem);

    rope_table_kernel<<<(TT*E2 + 255)/256, 256>>>();
    rope_apply_kernel<<<(MM*E2 + 255)/256, 256>>>(x);

    dim3 ggrid(EE/64, MM/64);   // (16, 128)
    gemm_nt_kernel<<<ggrid, 256>>>(p_rx, Wq, p_q, nullptr);
    gemm_nt_kernel<<<ggrid, 256>>>(p_rx, Wk, p_k, nullptr);
    gemm_nt_kernel<<<ggrid, 256>>>(x,    Wv, p_v, nullptr);

    dim3 fgrid(TT/64, BB*HH);   // (32, 64)
    flash_kernel<<<fgrid, 256, flash_smem>>>(p_q, p_k, p_v, p_at);

    gemm_nt_kernel<<<ggrid, 256>>>(p_at, Wo, out, bo);
}

// round 4
// speedup vs baseline: 1.5596x; 1.5596x over previous
#include <cuda_runtime.h>
#include <cuda_bf16.h>
#include <math.h>
#include <stdint.h>

// Problem constants
#define BB 4
#define TT 2048
#define EE 1024
#define HH 16
#define HD 64
#define MM (BB*TT)          // 8192 rows
#define E2 (EE/2)           // 512 pairs
#define GK 1024

// ---------------- scratch (device globals; no allocation allowed) ----------
__device__ float g_sin[TT*E2];
__device__ float g_cos[TT*E2];
__device__ float g_q  [MM*EE];
__device__ float g_k  [MM*EE];
__device__ float g_v  [MM*EE];
__device__ float g_at [MM*EE];

// bf16 split buffers (hi + lo ~= fp32), 16B-aligned for cp.async
__device__ __align__(256) __nv_bfloat16 g_rxhi[MM*EE];
__device__ __align__(256) __nv_bfloat16 g_rxlo[MM*EE];
__device__ __align__(256) __nv_bfloat16 g_xhi [MM*EE];
__device__ __align__(256) __nv_bfloat16 g_xlo [MM*EE];
__device__ __align__(256) __nv_bfloat16 g_athi[MM*EE];
__device__ __align__(256) __nv_bfloat16 g_atlo[MM*EE];
__device__ __align__(256) __nv_bfloat16 g_wqhi[EE*EE];
__device__ __align__(256) __nv_bfloat16 g_wqlo[EE*EE];
__device__ __align__(256) __nv_bfloat16 g_wkhi[EE*EE];
__device__ __align__(256) __nv_bfloat16 g_wklo[EE*EE];
__device__ __align__(256) __nv_bfloat16 g_wvhi[EE*EE];
__device__ __align__(256) __nv_bfloat16 g_wvlo[EE*EE];
__device__ __align__(256) __nv_bfloat16 g_wohi[EE*EE];
__device__ __align__(256) __nv_bfloat16 g_wolo[EE*EE];

// ================= helpers (compute_80-level PTX only!) =====================
__device__ __forceinline__ uint32_t smem_u32(const void* p) {
    uint32_t a;
    asm("{ .reg .u64 t; cvta.to.shared.u64 t, %1; cvt.u32.u64 %0, t; }"
        : "=r"(a) : "l"(p));
    return a;
}
__device__ __forceinline__ void cp16(uint32_t saddr, const void* g) {
    asm volatile("cp.async.cg.shared.global [%0], [%1], 16;"
                 :: "r"(saddr), "l"(g) : "memory");
}
#define CP_COMMIT() asm volatile("cp.async.commit_group;" ::: "memory")
#define CP_WAIT(n)  asm volatile("cp.async.wait_group %0;" :: "n"(n) : "memory")

__device__ __forceinline__ void ldsm_x4(uint32_t* r, uint32_t addr) {
    asm volatile("ldmatrix.sync.aligned.m8n8.x4.shared.b16 {%0,%1,%2,%3}, [%4];"
                 : "=r"(r[0]), "=r"(r[1]), "=r"(r[2]), "=r"(r[3]) : "r"(addr));
}
__device__ __forceinline__ void mma_bf16(float* c, const uint32_t* a,
                                         const uint32_t* b) {
    asm volatile(
        "mma.sync.aligned.m16n8k16.row.col.f32.bf16.bf16.f32 "
        "{%0,%1,%2,%3}, {%4,%5,%6,%7}, {%8,%9}, {%0,%1,%2,%3};"
        : "+f"(c[0]), "+f"(c[1]), "+f"(c[2]), "+f"(c[3])
        : "r"(a[0]), "r"(a[1]), "r"(a[2]), "r"(a[3]), "r"(b[0]), "r"(b[1]));
}

// ---------------- RoPE tables ----------------------------------------------
__global__ void rope_table_kernel() {
    int idx = blockIdx.x * blockDim.x + threadIdx.x;
    if (idx >= TT*E2) return;
    int t = idx / E2;
    int p = idx % E2;
    double theta_d = exp((-(double)(2*p) / (double)EE) * log(10000.0));
    float theta = (float)theta_d;
    float ang = (float)t * theta;          // fp32 rounding as in reference
    double s, c;
    sincos((double)ang, &s, &c);
    g_sin[idx] = (float)s;
    g_cos[idx] = (float)c;
}

// RoPE apply, writing bf16 hi/lo split directly
__global__ void rope_apply_split_kernel(const float* __restrict__ x) {
    int idx = blockIdx.x * blockDim.x + threadIdx.x;   // over MM*E2 pairs
    if (idx >= MM*E2) return;
    int bt = idx / E2;
    int p  = idx % E2;
    int t  = bt % TT;
    float2 v = ((const float2*)x)[idx];
    float s = g_sin[t*E2 + p];
    float c = g_cos[t*E2 + p];
    float rx = v.x * c - v.y * s;
    float ry = v.y * c + v.x * s;
    __nv_bfloat16 hx = __float2bfloat16_rn(rx);
    __nv_bfloat16 hy = __float2bfloat16_rn(ry);
    __nv_bfloat16 lx = __float2bfloat16_rn(rx - __bfloat162float(hx));
    __nv_bfloat16 ly = __float2bfloat16_rn(ry - __bfloat162float(hy));
    ((__nv_bfloat162*)g_rxhi)[idx] = __nv_bfloat162(hx, hy);
    ((__nv_bfloat162*)g_rxlo)[idx] = __nv_bfloat162(lx, ly);
}

// fp32 -> bf16 hi/lo split
__global__ void split_kernel(const float* __restrict__ src,
                             __nv_bfloat16* __restrict__ hi,
                             __nv_bfloat16* __restrict__ lo, int n) {
    int i = blockIdx.x * blockDim.x + threadIdx.x;
    if (i >= n) return;
    float x = src[i];
    __nv_bfloat16 h = __float2bfloat16_rn(x);
    hi[i] = h;
    lo[i] = __float2bfloat16_rn(x - __bfloat162float(h));
}

// ---------------- HMMA bf16-split NT GEMM -----------------------------------
// C[m][n] = sum_k A[m][k]*W[n][k] (+bias) with A=Ahi+Alo, W=Whi+Wlo (3 terms).
// CTA tile 128x128, 8 warps of 64x32, K-chunk 64, double-buffered cp.async.
#define KSTEPS (GK/64)          // 16
#define TILE_B 16384            // 128 rows x 128 bytes
#define STAGE_B (4*TILE_B)      // Ahi|Alo|Whi|Wlo = 64 KB
#define GEMM_SMEM (2*STAGE_B)   // 128 KB

__global__ __launch_bounds__(256)
void hmma_gemm_kernel(const __nv_bfloat16* __restrict__ Ahi,
                      const __nv_bfloat16* __restrict__ Alo,
                      const __nv_bfloat16* __restrict__ Whi,
                      const __nv_bfloat16* __restrict__ Wlo,
                      float* __restrict__ C, const float* __restrict__ bias) {
    extern __shared__ char sm[];
    const int tid  = threadIdx.x;
    const int wid  = tid >> 5;
    const int lane = tid & 31;
    const int row0 = blockIdx.y * 128;
    const int col0 = blockIdx.x * 128;
    const uint32_t sbase = smem_u32(sm);
    const int wm = wid >> 2;         // 0..1 : warp m offset = wm*64
    const int wn = wid & 3;          // 0..3 : warp n offset = wn*32

    float acc[4][4][4] = {};

    const __nv_bfloat16* srcs[4] = { Ahi, Alo, Whi, Wlo };

    // ---- stage loader: 16 cp.async x 16B per thread -------------------------
    auto load_stage = [&](int s, int ks) {
        const int k0 = ks * 64;
        const uint32_t st = sbase + s * STAGE_B;
        #pragma unroll
        for (int t = 0; t < 4; t++) {
            const int rb = (t < 2) ? row0 : col0;
            #pragma unroll
            for (int it = 0; it < 4; it++) {
                int u = tid + 256 * it;          // 0..1023 16B units
                int r = u >> 3, c = u & 7;
                const __nv_bfloat16* g = srcs[t] + (size_t)(rb + r) * GK + k0 + c * 8;
                uint32_t sa = st + t * TILE_B + r * 128 + ((c ^ (r & 7)) * 16);
                cp16(sa, g);
            }
        }
    };

    load_stage(0, 0);
    CP_COMMIT();

    for (int ks = 0; ks < KSTEPS; ks++) {
        if (ks + 1 < KSTEPS) {
            load_stage((ks + 1) & 1, ks + 1);
            CP_COMMIT();
            CP_WAIT(1);
        } else {
            CP_WAIT(0);
        }
        __syncthreads();

        const uint32_t st = sbase + (ks & 1) * STAGE_B;
        const uint32_t ahB = st, alB = st + TILE_B;
        const uint32_t whB = st + 2*TILE_B, wlB = st + 3*TILE_B;
        const int lr = lane & 15, lc = lane >> 4;

        #pragma unroll
        for (int k16 = 0; k16 < 4; k16++) {
            uint32_t ah[4][4], al[4][4], wh[4][2], wl[4][2];
            #pragma unroll
            for (int i = 0; i < 4; i++) {
                int row = wm*64 + i*16 + lr;
                int c = k16*2 + lc;
                uint32_t off = row*128 + ((c ^ (row & 7)) * 16);
                ldsm_x4(ah[i], ahB + off);
                ldsm_x4(al[i], alB + off);
            }
            #pragma unroll
            for (int jj = 0; jj < 2; jj++) {
                int row = wn*32 + jj*16 + lr;
                int c = k16*2 + lc;
                uint32_t off = row*128 + ((c ^ (row & 7)) * 16);
                uint32_t t0[4], t1[4];
                ldsm_x4(t0, whB + off);
                wh[jj*2][0] = t0[0]; wh[jj*2][1] = t0[2];
                wh[jj*2+1][0] = t0[1]; wh[jj*2+1][1] = t0[3];
                ldsm_x4(t1, wlB + off);
                wl[jj*2][0] = t1[0]; wl[jj*2][1] = t1[2];
                wl[jj*2+1][0] = t1[1]; wl[jj*2+1][1] = t1[3];
            }
            #pragma unroll
            for (int i = 0; i < 4; i++)
                #pragma unroll
                for (int j = 0; j < 4; j++) {
                    mma_bf16(acc[i][j], ah[i], wh[j]);  // hi*hi
                    mma_bf16(acc[i][j], ah[i], wl[j]);  // hi*lo
                    mma_bf16(acc[i][j], al[i], wh[j]);  // lo*hi
                }
        }
        __syncthreads();
    }

    // ---- epilogue: direct stores (float2 per fragment half) -----------------
    const int gq = lane >> 2, tig = lane & 3;
    #pragma unroll
    for (int j = 0; j < 4; j++) {
        const int n = col0 + wn*32 + j*8 + tig*2;
        float b0 = 0.f, b1 = 0.f;
        if (bias) { b0 = bias[n]; b1 = bias[n+1]; }
        #pragma unroll
        for (int i = 0; i < 4; i++) {
            const int m0 = row0 + wm*64 + i*16 + gq;
            float2 v0 = make_float2(acc[i][j][0] + b0, acc[i][j][1] + b1);
            float2 v1 = make_float2(acc[i][j][2] + b0, acc[i][j][3] + b1);
            *(float2*)(C + (size_t)m0 * GK + n) = v0;
            *(float2*)(C + (size_t)(m0 + 8) * GK + n) = v1;
        }
    }
}

// ---------------- flash attention (causal, fp32) ----------------------------
#define QPAD 68
#define SPAD 65
#define FLASH_SMEM_FLOATS (3*64*QPAD + 64*SPAD + 3*64)

__global__ __launch_bounds__(256)
void flash_kernel(const float* __restrict__ q, const float* __restrict__ k,
                  const float* __restrict__ v, float* __restrict__ o) {
    extern __shared__ float smf[];
    float* Qs   = smf;                   // [d][q] : 64 x QPAD
    float* Ks   = Qs + 64*QPAD;          // [d][c]
    float* Vs   = Ks + 64*QPAD;          // [c][d]
    float* Ss   = Vs + 64*QPAD;          // [q][c] : 64 x SPAD
    float* mrow = Ss + 64*SPAD;
    float* lrow = mrow + 64;
    float* resc = lrow + 64;

    const int tid = threadIdx.x;
    const int tx = tid & 15;
    const int ty = tid >> 4;
    const int qtile = blockIdx.x;
    const int bh = blockIdx.y;
    const int b = bh >> 4;
    const int h = bh & 15;
    const int row_base = b*TT + qtile*64;
    const int col_base = h*HD;

    const int fr = tid >> 4;
    const int fc = tid & 15;

    #pragma unroll
    for (int l = 0; l < 4; l++) {
        int r = fr + 16*l;
        float4 qv = *(const float4*)(q + (size_t)(row_base + r)*EE + col_base + fc*4);
        Qs[(fc*4+0)*QPAD + r] = qv.x;
        Qs[(fc*4+1)*QPAD + r] = qv.y;
        Qs[(fc*4+2)*QPAD + r] = qv.z;
        Qs[(fc*4+3)*QPAD + r] = qv.w;
    }
    if (tid < 64) { mrow[tid] = -INFINITY; lrow[tid] = 0.f; }

    float acc[4][4] = {};

    for (int kt = 0; kt <= qtile; kt++) {
        __syncthreads();
        const int kv_row = b*TT + kt*64;
        #pragma unroll
        for (int l = 0; l < 4; l++) {
            int r = fr + 16*l;
            float4 k4 = *(const float4*)(k + (size_t)(kv_row + r)*EE + col_base + fc*4);
            Ks[(fc*4+0)*QPAD + r] = k4.x;
            Ks[(fc*4+1)*QPAD + r] = k4.y;
            Ks[(fc*4+2)*QPAD + r] = k4.z;
            Ks[(fc*4+3)*QPAD + r] = k4.w;
            float4 v4 = *(const float4*)(v + (size_t)(kv_row + r)*EE + col_base + fc*4);
            *(float4*)&Vs[r*QPAD + fc*4] = v4;
        }
        __syncthreads();

        float s[4][4] = {};
        #pragma unroll
        for (int d = 0; d < 64; d++) {
            float4 qv = *(const float4*)&Qs[d*QPAD + ty*4];
            float4 kv = *(const float4*)&Ks[d*QPAD + tx*4];
            float a[4] = {qv.x, qv.y, qv.z, qv.w};
            float bq[4] = {kv.x, kv.y, kv.z, kv.w};
            #pragma unroll
            for (int i = 0; i < 4; i++)
                #pragma unroll
                for (int jj = 0; jj < 4; jj++)
                    s[i][jj] = fmaf(a[i], bq[jj], s[i][jj]);
        }
        const bool diag = (kt == qtile);
        #pragma unroll
        for (int i = 0; i < 4; i++) {
            int qq = ty*4 + i;
            #pragma unroll
            for (int jj = 0; jj < 4; jj++) {
                int cc = tx*4 + jj;
                float val = s[i][jj] * 0.125f;
                if (diag && cc > qq) val = -INFINITY;
                Ss[qq*SPAD + cc] = val;
            }
        }
        __syncthreads();

        if (tid < 64) {
            float mOld = mrow[tid];
            float mNew = mOld;
            #pragma unroll 8
            for (int c = 0; c < 64; c++)
                mNew = fmaxf(mNew, Ss[tid*SPAD + c]);
            float rsc = __expf(mOld - mNew);
            float ls = 0.f;
            #pragma unroll 8
            for (int c = 0; c < 64; c++) {
                float p = __expf(Ss[tid*SPAD + c] - mNew);
                Ss[tid*SPAD + c] = p;
                ls += p;
            }
            lrow[tid] = lrow[tid] * rsc + ls;
            mrow[tid] = mNew;
            resc[tid] = rsc;
        }
        __syncthreads();

        float rs[4];
        #pragma unroll
        for (int i = 0; i < 4; i++) rs[i] = resc[ty*4 + i];
        #pragma unroll
        for (int i = 0; i < 4; i++)
            #pragma unroll
            for (int jj = 0; jj < 4; jj++)
                acc[i][jj] *= rs[i];
        #pragma unroll
        for (int c = 0; c < 64; c++) {
            float4 vv = *(const float4*)&Vs[c*QPAD + tx*4];
            float p0 = Ss[(ty*4+0)*SPAD + c];
            float p1 = Ss[(ty*4+1)*SPAD + c];
            float p2 = Ss[(ty*4+2)*SPAD + c];
            float p3 = Ss[(ty*4+3)*SPAD + c];
            acc[0][0]=fmaf(p0,vv.x,acc[0][0]); acc[0][1]=fmaf(p0,vv.y,acc[0][1]);
            acc[0][2]=fmaf(p0,vv.z,acc[0][2]); acc[0][3]=fmaf(p0,vv.w,acc[0][3]);
            acc[1][0]=fmaf(p1,vv.x,acc[1][0]); acc[1][1]=fmaf(p1,vv.y,acc[1][1]);
            acc[1][2]=fmaf(p1,vv.z,acc[1][2]); acc[1][3]=fmaf(p1,vv.w,acc[1][3]);
            acc[2][0]=fmaf(p2,vv.x,acc[2][0]); acc[2][1]=fmaf(p2,vv.y,acc[2][1]);
            acc[2][2]=fmaf(p2,vv.z,acc[2][2]); acc[2][3]=fmaf(p2,vv.w,acc[2][3]);
            acc[3][0]=fmaf(p3,vv.x,acc[3][0]); acc[3][1]=fmaf(p3,vv.y,acc[3][1]);
            acc[3][2]=fmaf(p3,vv.z,acc[3][2]); acc[3][3]=fmaf(p3,vv.w,acc[3][3]);
        }
    }

    #pragma unroll
    for (int i = 0; i < 4; i++) {
        int qq = ty*4 + i;
        float inv = 1.f / lrow[qq];
        float4 ov;
        ov.x = acc[i][0] * inv;
        ov.y = acc[i][1] * inv;
        ov.z = acc[i][2] * inv;
        ov.w = acc[i][3] * inv;
        *(float4*)(o + (size_t)(row_base + qq)*EE + col_base + tx*4) = ov;
    }
}

// ---------------- launch ----------------------------------------------------
extern "C" void kernel_launch(void* const* d_in, const int* in_sizes, int n_in,
                              void* d_out, int out_size) {
    const float* x  = (const float*)d_in[0];
    const float* Wq = (const float*)d_in[1];
    const float* Wk = (const float*)d_in[2];
    const float* Wv = (const float*)d_in[3];
    const float* Wo = (const float*)d_in[4];
    const float* bo = (const float*)d_in[5];
    float* out = (float*)d_out;

    // Resolve REAL device addresses of scratch globals (host shadow trap).
    float *p_q, *p_k, *p_v, *p_at;
    __nv_bfloat16 *p_rxhi, *p_rxlo, *p_xhi, *p_xlo, *p_athi, *p_atlo;
    __nv_bfloat16 *p_wqhi, *p_wqlo, *p_wkhi, *p_wklo, *p_wvhi, *p_wvlo, *p_wohi, *p_wolo;
    cudaGetSymbolAddress((void**)&p_q,  g_q);
    cudaGetSymbolAddress((void**)&p_k,  g_k);
    cudaGetSymbolAddress((void**)&p_v,  g_v);
    cudaGetSymbolAddress((void**)&p_at, g_at);
    cudaGetSymbolAddress((void**)&p_rxhi, g_rxhi);
    cudaGetSymbolAddress((void**)&p_rxlo, g_rxlo);
    cudaGetSymbolAddress((void**)&p_xhi,  g_xhi);
    cudaGetSymbolAddress((void**)&p_xlo,  g_xlo);
    cudaGetSymbolAddress((void**)&p_athi, g_athi);
    cudaGetSymbolAddress((void**)&p_atlo, g_atlo);
    cudaGetSymbolAddress((void**)&p_wqhi, g_wqhi);
    cudaGetSymbolAddress((void**)&p_wqlo, g_wqlo);
    cudaGetSymbolAddress((void**)&p_wkhi, g_wkhi);
    cudaGetSymbolAddress((void**)&p_wklo, g_wklo);
    cudaGetSymbolAddress((void**)&p_wvhi, g_wvhi);
    cudaGetSymbolAddress((void**)&p_wvlo, g_wvlo);
    cudaGetSymbolAddress((void**)&p_wohi, g_wohi);
    cudaGetSymbolAddress((void**)&p_wolo, g_wolo);

    const int flash_smem = FLASH_SMEM_FLOATS * (int)sizeof(float);
    cudaFuncSetAttribute(flash_kernel,
                         cudaFuncAttributeMaxDynamicSharedMemorySize, flash_smem);
    cudaFuncSetAttribute(hmma_gemm_kernel,
                         cudaFuncAttributeMaxDynamicSharedMemorySize, GEMM_SMEM);

    rope_table_kernel<<<(TT*E2 + 255)/256, 256>>>();
    rope_apply_split_kernel<<<(MM*E2 + 255)/256, 256>>>(x);
    split_kernel<<<(MM*EE + 255)/256, 256>>>(x, p_xhi, p_xlo, MM*EE);
    split_kernel<<<(EE*EE + 255)/256, 256>>>(Wq, p_wqhi, p_wqlo, EE*EE);
    split_kernel<<<(EE*EE + 255)/256, 256>>>(Wk, p_wkhi, p_wklo, EE*EE);
    split_kernel<<<(EE*EE + 255)/256, 256>>>(Wv, p_wvhi, p_wvlo, EE*EE);
    split_kernel<<<(EE*EE + 255)/256, 256>>>(Wo, p_wohi, p_wolo, EE*EE);

    dim3 mgrid(EE/128, MM/128);   // (8, 64)
    hmma_gemm_kernel<<<mgrid, 256, GEMM_SMEM>>>(p_rxhi, p_rxlo, p_wqhi, p_wqlo, p_q, nullptr);
    hmma_gemm_kernel<<<mgrid, 256, GEMM_SMEM>>>(p_rxhi, p_rxlo, p_wkhi, p_wklo, p_k, nullptr);
    hmma_gemm_kernel<<<mgrid, 256, GEMM_SMEM>>>(p_xhi,  p_xlo,  p_wvhi, p_wvlo, p_v, nullptr);

    dim3 fgrid(TT/64, BB*HH);   // (32, 64)
    flash_kernel<<<fgrid, 256, flash_smem>>>(p_q, p_k, p_v, p_at);

    split_kernel<<<(MM*EE + 255)/256, 256>>>(p_at, p_athi, p_atlo, MM*EE);
    hmma_gemm_kernel<<<mgrid, 256, GEMM_SMEM>>>(p_athi, p_atlo, p_wohi, p_wolo, out, bo);
}

// round 5
// speedup vs baseline: 2.4420x; 1.5658x over previous
#include <cuda_runtime.h>
#include <cuda_bf16.h>
#include <math.h>
#include <stdint.h>

// Problem constants
#define BB 4
#define TT 2048
#define EE 1024
#define HH 16
#define HD 64
#define MM (BB*TT)          // 8192 rows
#define E2 (EE/2)           // 512 pairs
#define GK 1024

// ---------------- scratch (device globals; no allocation allowed) ----------
__device__ float g_sin[TT*E2];
__device__ float g_cos[TT*E2];

__device__ __align__(256) __nv_bfloat16 g_rxhi[MM*EE];
__device__ __align__(256) __nv_bfloat16 g_rxlo[MM*EE];
__device__ __align__(256) __nv_bfloat16 g_xhi [MM*EE];
__device__ __align__(256) __nv_bfloat16 g_xlo [MM*EE];
__device__ __align__(256) __nv_bfloat16 g_qhi [MM*EE];
__device__ __align__(256) __nv_bfloat16 g_qlo [MM*EE];
__device__ __align__(256) __nv_bfloat16 g_khi [MM*EE];
__device__ __align__(256) __nv_bfloat16 g_klo [MM*EE];
__device__ __align__(256) __nv_bfloat16 g_vhi [MM*EE];
__device__ __align__(256) __nv_bfloat16 g_vlo [MM*EE];
__device__ __align__(256) __nv_bfloat16 g_athi[MM*EE];
__device__ __align__(256) __nv_bfloat16 g_atlo[MM*EE];
__device__ __align__(256) __nv_bfloat16 g_wqhi[EE*EE];
__device__ __align__(256) __nv_bfloat16 g_wqlo[EE*EE];
__device__ __align__(256) __nv_bfloat16 g_wkhi[EE*EE];
__device__ __align__(256) __nv_bfloat16 g_wklo[EE*EE];
__device__ __align__(256) __nv_bfloat16 g_wvhi[EE*EE];
__device__ __align__(256) __nv_bfloat16 g_wvlo[EE*EE];
__device__ __align__(256) __nv_bfloat16 g_wohi[EE*EE];
__device__ __align__(256) __nv_bfloat16 g_wolo[EE*EE];

// ================= helpers (compute_80-level PTX only!) =====================
__device__ __forceinline__ uint32_t smem_u32(const void* p) {
    uint32_t a;
    asm("{ .reg .u64 t; cvta.to.shared.u64 t, %1; cvt.u32.u64 %0, t; }"
        : "=r"(a) : "l"(p));
    return a;
}
__device__ __forceinline__ void cp16(uint32_t saddr, const void* g) {
    asm volatile("cp.async.cg.shared.global [%0], [%1], 16;"
                 :: "r"(saddr), "l"(g) : "memory");
}
#define CP_COMMIT() asm volatile("cp.async.commit_group;" ::: "memory")
#define CP_WAIT(n)  asm volatile("cp.async.wait_group %0;" :: "n"(n) : "memory")

__device__ __forceinline__ void ldsm_x4(uint32_t* r, uint32_t addr) {
    asm volatile("ldmatrix.sync.aligned.m8n8.x4.shared.b16 {%0,%1,%2,%3}, [%4];"
                 : "=r"(r[0]), "=r"(r[1]), "=r"(r[2]), "=r"(r[3]) : "r"(addr));
}
__device__ __forceinline__ void ldsm_x4_t(uint32_t* r, uint32_t addr) {
    asm volatile("ldmatrix.sync.aligned.m8n8.x4.trans.shared.b16 {%0,%1,%2,%3}, [%4];"
                 : "=r"(r[0]), "=r"(r[1]), "=r"(r[2]), "=r"(r[3]) : "r"(addr));
}
__device__ __forceinline__ void mma_bf16(float* c, const uint32_t* a,
                                         const uint32_t* b) {
    asm volatile(
        "mma.sync.aligned.m16n8k16.row.col.f32.bf16.bf16.f32 "
        "{%0,%1,%2,%3}, {%4,%5,%6,%7}, {%8,%9}, {%0,%1,%2,%3};"
        : "+f"(c[0]), "+f"(c[1]), "+f"(c[2]), "+f"(c[3])
        : "r"(a[0]), "r"(a[1]), "r"(a[2]), "r"(a[3]), "r"(b[0]), "r"(b[1]));
}
__device__ __forceinline__ uint32_t pack_bf16x2(float a, float b) {
    __nv_bfloat162 t = __floats2bfloat162_rn(a, b);
    return *(uint32_t*)&t;
}

// ---------------- RoPE tables ----------------------------------------------
__global__ void rope_table_kernel() {
    int idx = blockIdx.x * blockDim.x + threadIdx.x;
    if (idx >= TT*E2) return;
    int t = idx / E2;
    int p = idx % E2;
    double theta_d = exp((-(double)(2*p) / (double)EE) * log(10000.0));
    float theta = (float)theta_d;
    float ang = (float)t * theta;          // fp32 rounding as in reference
    double s, c;
    sincos((double)ang, &s, &c);
    g_sin[idx] = (float)s;
    g_cos[idx] = (float)c;
}

__global__ void rope_apply_split_kernel(const float* __restrict__ x) {
    int idx = blockIdx.x * blockDim.x + threadIdx.x;   // over MM*E2 pairs
    if (idx >= MM*E2) return;
    int bt = idx / E2;
    int p  = idx % E2;
    int t  = bt % TT;
    float2 v = ((const float2*)x)[idx];
    float s = g_sin[t*E2 + p];
    float c = g_cos[t*E2 + p];
    float rx = v.x * c - v.y * s;
    float ry = v.y * c + v.x * s;
    __nv_bfloat16 hx = __float2bfloat16_rn(rx);
    __nv_bfloat16 hy = __float2bfloat16_rn(ry);
    __nv_bfloat16 lx = __float2bfloat16_rn(rx - __bfloat162float(hx));
    __nv_bfloat16 ly = __float2bfloat16_rn(ry - __bfloat162float(hy));
    ((__nv_bfloat162*)g_rxhi)[idx] = __nv_bfloat162(hx, hy);
    ((__nv_bfloat162*)g_rxlo)[idx] = __nv_bfloat162(lx, ly);
}

__global__ void split_kernel(const float* __restrict__ src,
                             __nv_bfloat16* __restrict__ hi,
                             __nv_bfloat16* __restrict__ lo, int n) {
    int i = blockIdx.x * blockDim.x + threadIdx.x;
    if (i >= n) return;
    float x = src[i];
    __nv_bfloat16 h = __float2bfloat16_rn(x);
    hi[i] = h;
    lo[i] = __float2bfloat16_rn(x - __bfloat162float(h));
}

// ---------------- HMMA bf16-split NT GEMM -----------------------------------
// C[m][n] = sum_k A[m][k]*W[n][k] (+bias), 3-term hi/lo split.
// Output either fp32 C or bf16 hi/lo split (Chi/Clo).
#define KSTEPS (GK/64)          // 16
#define TILE_B 16384            // 128 rows x 128 bytes
#define STAGE_B (4*TILE_B)      // Ahi|Alo|Whi|Wlo = 64 KB
#define GEMM_SMEM (2*STAGE_B)   // 128 KB

__global__ __launch_bounds__(256)
void hmma_gemm_kernel(const __nv_bfloat16* __restrict__ Ahi,
                      const __nv_bfloat16* __restrict__ Alo,
                      const __nv_bfloat16* __restrict__ Whi,
                      const __nv_bfloat16* __restrict__ Wlo,
                      float* __restrict__ C,
                      __nv_bfloat16* __restrict__ Chi,
                      __nv_bfloat16* __restrict__ Clo,
                      const float* __restrict__ bias) {
    extern __shared__ char sm[];
    const int tid  = threadIdx.x;
    const int wid  = tid >> 5;
    const int lane = tid & 31;
    const int row0 = blockIdx.y * 128;
    const int col0 = blockIdx.x * 128;
    const uint32_t sbase = smem_u32(sm);
    const int wm = wid >> 2;
    const int wn = wid & 3;

    float acc[4][4][4] = {};
    const __nv_bfloat16* srcs[4] = { Ahi, Alo, Whi, Wlo };

    auto load_stage = [&](int s, int ks) {
        const int k0 = ks * 64;
        const uint32_t st = sbase + s * STAGE_B;
        #pragma unroll
        for (int t = 0; t < 4; t++) {
            const int rb = (t < 2) ? row0 : col0;
            #pragma unroll
            for (int it = 0; it < 4; it++) {
                int u = tid + 256 * it;
                int r = u >> 3, c = u & 7;
                const __nv_bfloat16* g = srcs[t] + (size_t)(rb + r) * GK + k0 + c * 8;
                uint32_t sa = st + t * TILE_B + r * 128 + ((c ^ (r & 7)) * 16);
                cp16(sa, g);
            }
        }
    };

    load_stage(0, 0);
    CP_COMMIT();

    for (int ks = 0; ks < KSTEPS; ks++) {
        if (ks + 1 < KSTEPS) {
            load_stage((ks + 1) & 1, ks + 1);
            CP_COMMIT();
            CP_WAIT(1);
        } else {
            CP_WAIT(0);
        }
        __syncthreads();

        const uint32_t st = sbase + (ks & 1) * STAGE_B;
        const uint32_t ahB = st, alB = st + TILE_B;
        const uint32_t whB = st + 2*TILE_B, wlB = st + 3*TILE_B;
        const int lr = lane & 15, lc = lane >> 4;

        #pragma unroll
        for (int k16 = 0; k16 < 4; k16++) {
            uint32_t ah[4][4], al[4][4], wh[4][2], wl[4][2];
            #pragma unroll
            for (int i = 0; i < 4; i++) {
                int row = wm*64 + i*16 + lr;
                int c = k16*2 + lc;
                uint32_t off = row*128 + ((c ^ (row & 7)) * 16);
                ldsm_x4(ah[i], ahB + off);
                ldsm_x4(al[i], alB + off);
            }
            #pragma unroll
            for (int jj = 0; jj < 2; jj++) {
                int row = wn*32 + jj*16 + lr;
                int c = k16*2 + lc;
                uint32_t off = row*128 + ((c ^ (row & 7)) * 16);
                uint32_t t0[4], t1[4];
                ldsm_x4(t0, whB + off);
                wh[jj*2][0] = t0[0]; wh[jj*2][1] = t0[2];
                wh[jj*2+1][0] = t0[1]; wh[jj*2+1][1] = t0[3];
                ldsm_x4(t1, wlB + off);
                wl[jj*2][0] = t1[0]; wl[jj*2][1] = t1[2];
                wl[jj*2+1][0] = t1[1]; wl[jj*2+1][1] = t1[3];
            }
            #pragma unroll
            for (int i = 0; i < 4; i++)
                #pragma unroll
                for (int j = 0; j < 4; j++) {
                    mma_bf16(acc[i][j], ah[i], wh[j]);
                    mma_bf16(acc[i][j], ah[i], wl[j]);
                    mma_bf16(acc[i][j], al[i], wh[j]);
                }
        }
        __syncthreads();
    }

    const int gq = lane >> 2, tig = lane & 3;
    #pragma unroll
    for (int j = 0; j < 4; j++) {
        const int n = col0 + wn*32 + j*8 + tig*2;
        float b0 = 0.f, b1 = 0.f;
        if (bias) { b0 = bias[n]; b1 = bias[n+1]; }
        #pragma unroll
        for (int i = 0; i < 4; i++) {
            const int m0 = row0 + wm*64 + i*16 + gq;
            float v00 = acc[i][j][0] + b0, v01 = acc[i][j][1] + b1;
            float v10 = acc[i][j][2] + b0, v11 = acc[i][j][3] + b1;
            if (C) {
                *(float2*)(C + (size_t)m0 * GK + n) = make_float2(v00, v01);
                *(float2*)(C + (size_t)(m0 + 8) * GK + n) = make_float2(v10, v11);
            } else {
                __nv_bfloat16 h00 = __float2bfloat16_rn(v00);
                __nv_bfloat16 h01 = __float2bfloat16_rn(v01);
                __nv_bfloat16 h10 = __float2bfloat16_rn(v10);
                __nv_bfloat16 h11 = __float2bfloat16_rn(v11);
                *(__nv_bfloat162*)(Chi + (size_t)m0*GK + n) = __nv_bfloat162(h00, h01);
                *(__nv_bfloat162*)(Chi + (size_t)(m0+8)*GK + n) = __nv_bfloat162(h10, h11);
                *(__nv_bfloat162*)(Clo + (size_t)m0*GK + n) = __nv_bfloat162(
                    __float2bfloat16_rn(v00 - __bfloat162float(h00)),
                    __float2bfloat16_rn(v01 - __bfloat162float(h01)));
                *(__nv_bfloat162*)(Clo + (size_t)(m0+8)*GK + n) = __nv_bfloat162(
                    __float2bfloat16_rn(v10 - __bfloat162float(h10)),
                    __float2bfloat16_rn(v11 - __bfloat162float(h11)));
            }
        }
    }
}

// ---------------- HMMA flash attention (causal) ------------------------------
// Br=128 (8 warps x 16 rows), Bc=64, d=64. 3-term split on QK^T and PV.
#define FL_QB   16384                  // 128 rows x 128B per Q tile
#define FL_TB   8192                   // 64 rows x 128B per K/V tile
#define FL_STG  (4*FL_TB)              // Kh|Kl|Vh|Vl = 32 KB
#define FL_SMEM (2*FL_QB + 2*FL_STG)   // 96 KB

__global__ __launch_bounds__(256)
void flash_hmma_kernel(const __nv_bfloat16* __restrict__ qhi,
                       const __nv_bfloat16* __restrict__ qlo,
                       const __nv_bfloat16* __restrict__ khi,
                       const __nv_bfloat16* __restrict__ klo,
                       const __nv_bfloat16* __restrict__ vhi,
                       const __nv_bfloat16* __restrict__ vlo,
                       __nv_bfloat16* __restrict__ ohi,
                       __nv_bfloat16* __restrict__ olo) {
    extern __shared__ char sm[];
    const int tid  = threadIdx.x;
    const int wid  = tid >> 5;
    const int lane = tid & 31;
    const int qt = blockIdx.x;
    const int bh = blockIdx.y;
    const int b = bh >> 4, h = bh & 15;
    const int qrow0 = qt * 128;                    // within T
    const size_t grow0 = (size_t)b * TT + qrow0;   // global row
    const int colb = h * HD;

    const uint32_t sb  = smem_u32(sm);
    const uint32_t qhB = sb, qlB = sb + FL_QB;
    const uint32_t stB = sb + 2*FL_QB;

    // ---- load Q tiles (hi, lo) ----
    {
        const __nv_bfloat16* srcs[2] = { qhi, qlo };
        #pragma unroll
        for (int t = 0; t < 2; t++) {
            uint32_t dst = t ? qlB : qhB;
            #pragma unroll
            for (int it = 0; it < 4; it++) {
                int u = tid + 256 * it;          // 0..1023
                int r = u >> 3, c = u & 7;
                cp16(dst + r*128 + ((c ^ (r & 7)) * 16),
                     srcs[t] + (grow0 + r) * EE + colb + c * 8);
            }
        }
    }
    const __nv_bfloat16* ksrc[4] = { khi, klo, vhi, vlo };
    auto load_stage = [&](int s, int kt) {
        const size_t krow = (size_t)b * TT + kt * 64;
        const uint32_t st = stB + s * FL_STG;
        #pragma unroll
        for (int t = 0; t < 4; t++) {
            #pragma unroll
            for (int it = 0; it < 2; it++) {
                int u = tid + 256 * it;          // 0..511
                int r = u >> 3, c = u & 7;
                cp16(st + t*FL_TB + r*128 + ((c ^ (r & 7)) * 16),
                     ksrc[t] + (krow + r) * EE + colb + c * 8);
            }
        }
    };
    load_stage(0, 0);
    CP_COMMIT();

    const int nkv = 2*qt + 2;
    CP_WAIT(0);
    __syncthreads();

    // ---- Q fragments to registers ----
    uint32_t qfh[4][4], qfl[4][4];
    const int lr = lane & 15, lc = lane >> 4;
    #pragma unroll
    for (int k16 = 0; k16 < 4; k16++) {
        int row = wid*16 + lr;
        int c = k16*2 + lc;
        uint32_t off = row*128 + ((c ^ (row & 7)) * 16);
        ldsm_x4(qfh[k16], qhB + off);
        ldsm_x4(qfl[k16], qlB + off);
    }

    float m0 = -INFINITY, m1 = -INFINITY, l0 = 0.f, l1 = 0.f;
    float o[8][4] = {};
    const int rg0 = qrow0 + wid*16 + (lane >> 2);   // global q row (c0/c1 rows)
    const int tig = lane & 3;

    for (int kt = 0; kt < nkv; kt++) {
        if (kt + 1 < nkv) {
            load_stage((kt + 1) & 1, kt + 1);
            CP_COMMIT();
            CP_WAIT(1);
        } else {
            CP_WAIT(0);
        }
        __syncthreads();

        const uint32_t st  = stB + (kt & 1) * FL_STG;
        const uint32_t khB = st, klB = st + FL_TB;
        const uint32_t vhB = st + 2*FL_TB, vlB = st + 3*FL_TB;

        // ---- S = Q K^T (3 terms) ----
        float s[8][4] = {};
        #pragma unroll
        for (int k16 = 0; k16 < 4; k16++) {
            uint32_t kh[8][2], kl[8][2];
            #pragma unroll
            for (int jj = 0; jj < 4; jj++) {
                int row = jj*16 + lr;
                int c = k16*2 + lc;
                uint32_t off = row*128 + ((c ^ (row & 7)) * 16);
                uint32_t t0[4], t1[4];
                ldsm_x4(t0, khB + off);
                kh[jj*2][0] = t0[0]; kh[jj*2][1] = t0[2];
                kh[jj*2+1][0] = t0[1]; kh[jj*2+1][1] = t0[3];
                ldsm_x4(t1, klB + off);
                kl[jj*2][0] = t1[0]; kl[jj*2][1] = t1[2];
                kl[jj*2+1][0] = t1[1]; kl[jj*2+1][1] = t1[3];
            }
            #pragma unroll
            for (int j = 0; j < 8; j++) {
                mma_bf16(s[j], qfh[k16], kh[j]);
                mma_bf16(s[j], qfh[k16], kl[j]);
                mma_bf16(s[j], qfl[k16], kh[j]);
            }
        }

        // ---- scale + causal mask ----
        const bool maskt = (kt >= 2*qt);
        #pragma unroll
        for (int j = 0; j < 8; j++) {
            s[j][0] *= 0.125f; s[j][1] *= 0.125f;
            s[j][2] *= 0.125f; s[j][3] *= 0.125f;
            if (maskt) {
                int c0 = kt*64 + j*8 + tig*2;
                if (c0     > rg0)     s[j][0] = -INFINITY;
                if (c0 + 1 > rg0)     s[j][1] = -INFINITY;
                if (c0     > rg0 + 8) s[j][2] = -INFINITY;
                if (c0 + 1 > rg0 + 8) s[j][3] = -INFINITY;
            }
        }

        // ---- online softmax (rows rg0, rg0+8) ----
        float tm0 = -INFINITY, tm1 = -INFINITY;
        #pragma unroll
        for (int j = 0; j < 8; j++) {
            tm0 = fmaxf(tm0, fmaxf(s[j][0], s[j][1]));
            tm1 = fmaxf(tm1, fmaxf(s[j][2], s[j][3]));
        }
        tm0 = fmaxf(tm0, __shfl_xor_sync(0xffffffff, tm0, 1));
        tm0 = fmaxf(tm0, __shfl_xor_sync(0xffffffff, tm0, 2));
        tm1 = fmaxf(tm1, __shfl_xor_sync(0xffffffff, tm1, 1));
        tm1 = fmaxf(tm1, __shfl_xor_sync(0xffffffff, tm1, 2));
        float mn0 = fmaxf(m0, tm0), mn1 = fmaxf(m1, tm1);
        float a0 = __expf(m0 - mn0), a1 = __expf(m1 - mn1);

        uint32_t pH01[8], pH23[8], pL01[8], pL23[8];
        float rs0 = 0.f, rs1 = 0.f;
        #pragma unroll
        for (int j = 0; j < 8; j++) {
            float p0 = __expf(s[j][0] - mn0);
            float p1 = __expf(s[j][1] - mn0);
            float p2 = __expf(s[j][2] - mn1);
            float p3 = __expf(s[j][3] - mn1);
            rs0 += p0 + p1; rs1 += p2 + p3;
            __nv_bfloat16 h0 = __float2bfloat16_rn(p0);
            __nv_bfloat16 h1 = __float2bfloat16_rn(p1);
            __nv_bfloat16 h2 = __float2bfloat16_rn(p2);
            __nv_bfloat16 h3 = __float2bfloat16_rn(p3);
            pH01[j] = ((uint32_t)*(uint16_t*)&h1 << 16) | *(uint16_t*)&h0;
            pH23[j] = ((uint32_t)*(uint16_t*)&h3 << 16) | *(uint16_t*)&h2;
            pL01[j] = pack_bf16x2(p0 - __bfloat162float(h0), p1 - __bfloat162float(h1));
            pL23[j] = pack_bf16x2(p2 - __bfloat162float(h2), p3 - __bfloat162float(h3));
        }
        rs0 += __shfl_xor_sync(0xffffffff, rs0, 1);
        rs0 += __shfl_xor_sync(0xffffffff, rs0, 2);
        rs1 += __shfl_xor_sync(0xffffffff, rs1, 1);
        rs1 += __shfl_xor_sync(0xffffffff, rs1, 2);
        l0 = l0 * a0 + rs0;
        l1 = l1 * a1 + rs1;
        m0 = mn0; m1 = mn1;

        #pragma unroll
        for (int j = 0; j < 8; j++) {
            o[j][0] *= a0; o[j][1] *= a0;
            o[j][2] *= a1; o[j][3] *= a1;
        }

        // ---- O += P V (3 terms), V^T via ldmatrix.trans ----
        const int mi = lane >> 3, li = lane & 7;
        #pragma unroll
        for (int c16 = 0; c16 < 4; c16++) {
            uint32_t aH[4] = { pH01[2*c16], pH23[2*c16], pH01[2*c16+1], pH23[2*c16+1] };
            uint32_t aL[4] = { pL01[2*c16], pL23[2*c16], pL01[2*c16+1], pL23[2*c16+1] };
            #pragma unroll
            for (int dj = 0; dj < 4; dj++) {
                int row = c16*16 + ((mi >> 1) ? 8 : 0) + li;
                int ch  = dj*2 + (mi & 1);
                uint32_t off = row*128 + ((ch ^ (row & 7)) * 16);
                uint32_t t0[4], t1[4];
                ldsm_x4_t(t0, vhB + off);
                ldsm_x4_t(t1, vlB + off);
                uint32_t vh0[2] = { t0[0], t0[2] }, vh1[2] = { t0[1], t0[3] };
                uint32_t vl0[2] = { t1[0], t1[2] }, vl1[2] = { t1[1], t1[3] };
                mma_bf16(o[dj*2],   aH, vh0);
                mma_bf16(o[dj*2],   aH, vl0);
                mma_bf16(o[dj*2],   aL, vh0);
                mma_bf16(o[dj*2+1], aH, vh1);
                mma_bf16(o[dj*2+1], aH, vl1);
                mma_bf16(o[dj*2+1], aL, vh1);
            }
        }
        __syncthreads();   // compute done before next prefetch overwrites buffer
    }

    // ---- normalize + split-write output ----
    const float i0 = 1.f / l0, i1 = 1.f / l1;
    const size_t r0g = grow0 + wid*16 + (lane >> 2);
    #pragma unroll
    for (int j = 0; j < 8; j++) {
        const int n = colb + j*8 + tig*2;
        float v00 = o[j][0] * i0, v01 = o[j][1] * i0;
        float v10 = o[j][2] * i1, v11 = o[j][3] * i1;
        __nv_bfloat16 h00 = __float2bfloat16_rn(v00);
        __nv_bfloat16 h01 = __float2bfloat16_rn(v01);
        __nv_bfloat16 h10 = __float2bfloat16_rn(v10);
        __nv_bfloat16 h11 = __float2bfloat16_rn(v11);
        *(__nv_bfloat162*)(ohi + r0g*EE + n)     = __nv_bfloat162(h00, h01);
        *(__nv_bfloat162*)(ohi + (r0g+8)*EE + n) = __nv_bfloat162(h10, h11);
        *(__nv_bfloat162*)(olo + r0g*EE + n)     = __nv_bfloat162(
            __float2bfloat16_rn(v00 - __bfloat162float(h00)),
            __float2bfloat16_rn(v01 - __bfloat162float(h01)));
        *(__nv_bfloat162*)(olo + (r0g+8)*EE + n) = __nv_bfloat162(
            __float2bfloat16_rn(v10 - __bfloat162float(h10)),
            __float2bfloat16_rn(v11 - __bfloat162float(h11)));
    }
}

// ---------------- launch ----------------------------------------------------
extern "C" void kernel_launch(void* const* d_in, const int* in_sizes, int n_in,
                              void* d_out, int out_size) {
    const float* x  = (const float*)d_in[0];
    const float* Wq = (const float*)d_in[1];
    const float* Wk = (const float*)d_in[2];
    const float* Wv = (const float*)d_in[3];
    const float* Wo = (const float*)d_in[4];
    const float* bo = (const float*)d_in[5];
    float* out = (float*)d_out;

    __nv_bfloat16 *p_rxhi, *p_rxlo, *p_xhi, *p_xlo;
    __nv_bfloat16 *p_qhi, *p_qlo, *p_khi, *p_klo, *p_vhi, *p_vlo, *p_athi, *p_atlo;
    __nv_bfloat16 *p_wqhi, *p_wqlo, *p_wkhi, *p_wklo, *p_wvhi, *p_wvlo, *p_wohi, *p_wolo;
    cudaGetSymbolAddress((void**)&p_rxhi, g_rxhi);
    cudaGetSymbolAddress((void**)&p_rxlo, g_rxlo);
    cudaGetSymbolAddress((void**)&p_xhi,  g_xhi);
    cudaGetSymbolAddress((void**)&p_xlo,  g_xlo);
    cudaGetSymbolAddress((void**)&p_qhi,  g_qhi);
    cudaGetSymbolAddress((void**)&p_qlo,  g_qlo);
    cudaGetSymbolAddress((void**)&p_khi,  g_khi);
    cudaGetSymbolAddress((void**)&p_klo,  g_klo);
    cudaGetSymbolAddress((void**)&p_vhi,  g_vhi);
    cudaGetSymbolAddress((void**)&p_vlo,  g_vlo);
    cudaGetSymbolAddress((void**)&p_athi, g_athi);
    cudaGetSymbolAddress((void**)&p_atlo, g_atlo);
    cudaGetSymbolAddress((void**)&p_wqhi, g_wqhi);
    cudaGetSymbolAddress((void**)&p_wqlo, g_wqlo);
    cudaGetSymbolAddress((void**)&p_wkhi, g_wkhi);
    cudaGetSymbolAddress((void**)&p_wklo, g_wklo);
    cudaGetSymbolAddress((void**)&p_wvhi, g_wvhi);
    cudaGetSymbolAddress((void**)&p_wvlo, g_wvlo);
    cudaGetSymbolAddress((void**)&p_wohi, g_wohi);
    cudaGetSymbolAddress((void**)&p_wolo, g_wolo);

    cudaFuncSetAttribute(hmma_gemm_kernel,
                         cudaFuncAttributeMaxDynamicSharedMemorySize, GEMM_SMEM);
    cudaFuncSetAttribute(flash_hmma_kernel,
                         cudaFuncAttributeMaxDynamicSharedMemorySize, FL_SMEM);

    rope_table_kernel<<<(TT*E2 + 255)/256, 256>>>();
    rope_apply_split_kernel<<<(MM*E2 + 255)/256, 256>>>(x);
    split_kernel<<<(MM*EE + 255)/256, 256>>>(x, p_xhi, p_xlo, MM*EE);
    split_kernel<<<(EE*EE + 255)/256, 256>>>(Wq, p_wqhi, p_wqlo, EE*EE);
    split_kernel<<<(EE*EE + 255)/256, 256>>>(Wk, p_wkhi, p_wklo, EE*EE);
    split_kernel<<<(EE*EE + 255)/256, 256>>>(Wv, p_wvhi, p_wvlo, EE*EE);
    split_kernel<<<(EE*EE + 255)/256, 256>>>(Wo, p_wohi, p_wolo, EE*EE);

    dim3 mgrid(EE/128, MM/128);   // (8, 64)
    hmma_gemm_kernel<<<mgrid, 256, GEMM_SMEM>>>(p_rxhi, p_rxlo, p_wqhi, p_wqlo,
                                                nullptr, p_qhi, p_qlo, nullptr);
    hmma_gemm_kernel<<<mgrid, 256, GEMM_SMEM>>>(p_rxhi, p_rxlo, p_wkhi, p_wklo,
                                                nullptr, p_khi, p_klo, nullptr);
    hmma_gemm_kernel<<<mgrid, 256, GEMM_SMEM>>>(p_xhi,  p_xlo,  p_wvhi, p_wvlo,
                                                nullptr, p_vhi, p_vlo, nullptr);

    dim3 fgrid(TT/128, BB*HH);    // (16, 64)
    flash_hmma_kernel<<<fgrid, 256, FL_SMEM>>>(p_qhi, p_qlo, p_khi, p_klo,
                                               p_vhi, p_vlo, p_athi, p_atlo);

    hmma_gemm_kernel<<<mgrid, 256, GEMM_SMEM>>>(p_athi, p_atlo, p_wohi, p_wolo,
                                                out, nullptr, nullptr, bo);
}

// round 6
// speedup vs baseline: 2.7316x; 1.1186x over previous
#include <cuda_runtime.h>
#include <cuda_bf16.h>
#include <cuda_fp16.h>
#include <math.h>
#include <stdint.h>

// Problem constants
#define BB 4
#define TT 2048
#define EE 1024
#define HH 16
#define HD 64
#define MM (BB*TT)          // 8192 rows
#define E2 (EE/2)           // 512 pairs
#define GK 1024

// ---------------- scratch (device globals; no allocation allowed) ----------
__device__ float g_sin[TT*E2];
__device__ float g_cos[TT*E2];

__device__ __align__(256) __nv_bfloat16 g_rxhi[MM*EE];
__device__ __align__(256) __nv_bfloat16 g_rxlo[MM*EE];
__device__ __align__(256) __nv_bfloat16 g_xhi [MM*EE];
__device__ __align__(256) __nv_bfloat16 g_xlo [MM*EE];
__device__ __align__(256) __nv_bfloat16 g_qhi [MM*EE];
__device__ __align__(256) __nv_bfloat16 g_qlo [MM*EE];
__device__ __align__(256) __nv_bfloat16 g_khi [MM*EE];
__device__ __align__(256) __nv_bfloat16 g_klo [MM*EE];
__device__ __align__(256) __half        g_vhi [MM*EE];   // fp16 split for PV
__device__ __align__(256) __half        g_vlo [MM*EE];
__device__ __align__(256) __nv_bfloat16 g_athi[MM*EE];
__device__ __align__(256) __nv_bfloat16 g_atlo[MM*EE];
__device__ __align__(256) __nv_bfloat16 g_wqhi[EE*EE];
__device__ __align__(256) __nv_bfloat16 g_wqlo[EE*EE];
__device__ __align__(256) __nv_bfloat16 g_wkhi[EE*EE];
__device__ __align__(256) __nv_bfloat16 g_wklo[EE*EE];
__device__ __align__(256) __nv_bfloat16 g_wvhi[EE*EE];
__device__ __align__(256) __nv_bfloat16 g_wvlo[EE*EE];
__device__ __align__(256) __nv_bfloat16 g_wohi[EE*EE];
__device__ __align__(256) __nv_bfloat16 g_wolo[EE*EE];

// ================= helpers (compute_80-level PTX only!) =====================
__device__ __forceinline__ uint32_t smem_u32(const void* p) {
    uint32_t a;
    asm("{ .reg .u64 t; cvta.to.shared.u64 t, %1; cvt.u32.u64 %0, t; }"
        : "=r"(a) : "l"(p));
    return a;
}
__device__ __forceinline__ void cp16(uint32_t saddr, const void* g) {
    asm volatile("cp.async.cg.shared.global [%0], [%1], 16;"
                 :: "r"(saddr), "l"(g) : "memory");
}
#define CP_COMMIT() asm volatile("cp.async.commit_group;" ::: "memory")
#define CP_WAIT(n)  asm volatile("cp.async.wait_group %0;" :: "n"(n) : "memory")

__device__ __forceinline__ void ldsm_x4(uint32_t* r, uint32_t addr) {
    asm volatile("ldmatrix.sync.aligned.m8n8.x4.shared.b16 {%0,%1,%2,%3}, [%4];"
                 : "=r"(r[0]), "=r"(r[1]), "=r"(r[2]), "=r"(r[3]) : "r"(addr));
}
__device__ __forceinline__ void ldsm_x4_t(uint32_t* r, uint32_t addr) {
    asm volatile("ldmatrix.sync.aligned.m8n8.x4.trans.shared.b16 {%0,%1,%2,%3}, [%4];"
                 : "=r"(r[0]), "=r"(r[1]), "=r"(r[2]), "=r"(r[3]) : "r"(addr));
}
__device__ __forceinline__ void mma_bf16(float* c, const uint32_t* a,
                                         const uint32_t* b) {
    asm volatile(
        "mma.sync.aligned.m16n8k16.row.col.f32.bf16.bf16.f32 "
        "{%0,%1,%2,%3}, {%4,%5,%6,%7}, {%8,%9}, {%0,%1,%2,%3};"
        : "+f"(c[0]), "+f"(c[1]), "+f"(c[2]), "+f"(c[3])
        : "r"(a[0]), "r"(a[1]), "r"(a[2]), "r"(a[3]), "r"(b[0]), "r"(b[1]));
}
__device__ __forceinline__ void mma_fp16(float* c, const uint32_t* a,
                                         const uint32_t* b) {
    asm volatile(
        "mma.sync.aligned.m16n8k16.row.col.f32.f16.f16.f32 "
        "{%0,%1,%2,%3}, {%4,%5,%6,%7}, {%8,%9}, {%0,%1,%2,%3};"
        : "+f"(c[0]), "+f"(c[1]), "+f"(c[2]), "+f"(c[3])
        : "r"(a[0]), "r"(a[1]), "r"(a[2]), "r"(a[3]), "r"(b[0]), "r"(b[1]));
}

// ---------------- RoPE tables ----------------------------------------------
__global__ void rope_table_kernel() {
    int idx = blockIdx.x * blockDim.x + threadIdx.x;
    if (idx >= TT*E2) return;
    int t = idx / E2;
    int p = idx % E2;
    double theta_d = exp((-(double)(2*p) / (double)EE) * log(10000.0));
    float theta = (float)theta_d;
    float ang = (float)t * theta;          // fp32 rounding as in reference
    double s, c;
    sincos((double)ang, &s, &c);
    g_sin[idx] = (float)s;
    g_cos[idx] = (float)c;
}

__global__ void rope_apply_split_kernel(const float* __restrict__ x) {
    int idx = blockIdx.x * blockDim.x + threadIdx.x;   // over MM*E2 pairs
    if (idx >= MM*E2) return;
    int bt = idx / E2;
    int p  = idx % E2;
    int t  = bt % TT;
    float2 v = ((const float2*)x)[idx];
    float s = g_sin[t*E2 + p];
    float c = g_cos[t*E2 + p];
    float rx = v.x * c - v.y * s;
    float ry = v.y * c + v.x * s;
    __nv_bfloat16 hx = __float2bfloat16_rn(rx);
    __nv_bfloat16 hy = __float2bfloat16_rn(ry);
    __nv_bfloat16 lx = __float2bfloat16_rn(rx - __bfloat162float(hx));
    __nv_bfloat16 ly = __float2bfloat16_rn(ry - __bfloat162float(hy));
    ((__nv_bfloat162*)g_rxhi)[idx] = __nv_bfloat162(hx, hy);
    ((__nv_bfloat162*)g_rxlo)[idx] = __nv_bfloat162(lx, ly);
}

__global__ void split_kernel(const float* __restrict__ src,
                             __nv_bfloat16* __restrict__ hi,
                             __nv_bfloat16* __restrict__ lo, int n) {
    int i = blockIdx.x * blockDim.x + threadIdx.x;
    if (i >= n) return;
    float x = src[i];
    __nv_bfloat16 h = __float2bfloat16_rn(x);
    hi[i] = h;
    lo[i] = __float2bfloat16_rn(x - __bfloat162float(h));
}

// ---------------- HMMA bf16-split NT GEMM (3-stage pipeline) -----------------
// C[m][n] = sum_k A[m][k]*W[n][k] (+bias), 3-term hi/lo split.
// OUT: 0 = fp32 C, 1 = bf16 hi/lo split, 2 = fp16 hi/lo split.
#define KSTEPS (GK/64)          // 16
#define TILE_B 16384            // 128 rows x 128 bytes
#define STAGE_B (4*TILE_B)      // Ahi|Alo|Whi|Wlo = 64 KB
#define NSTG 3
#define GEMM_SMEM (NSTG*STAGE_B)   // 192 KB

template<int OUT>
__global__ __launch_bounds__(256)
void hmma_gemm_kernel(const __nv_bfloat16* __restrict__ Ahi,
                      const __nv_bfloat16* __restrict__ Alo,
                      const __nv_bfloat16* __restrict__ Whi,
                      const __nv_bfloat16* __restrict__ Wlo,
                      float* __restrict__ C,
                      void* __restrict__ Chi_v,
                      void* __restrict__ Clo_v,
                      const float* __restrict__ bias) {
    extern __shared__ char sm[];
    const int tid  = threadIdx.x;
    const int wid  = tid >> 5;
    const int lane = tid & 31;
    const int row0 = blockIdx.y * 128;
    const int col0 = blockIdx.x * 128;
    const uint32_t sbase = smem_u32(sm);
    const int wm = wid >> 2;
    const int wn = wid & 3;

    float acc[4][4][4] = {};
    const __nv_bfloat16* srcs[4] = { Ahi, Alo, Whi, Wlo };

    auto load_stage = [&](int s, int ks) {
        const int k0 = ks * 64;
        const uint32_t st = sbase + s * STAGE_B;
        #pragma unroll
        for (int t = 0; t < 4; t++) {
            const int rb = (t < 2) ? row0 : col0;
            #pragma unroll
            for (int it = 0; it < 4; it++) {
                int u = tid + 256 * it;
                int r = u >> 3, c = u & 7;
                const __nv_bfloat16* g = srcs[t] + (size_t)(rb + r) * GK + k0 + c * 8;
                uint32_t sa = st + t * TILE_B + r * 128 + ((c ^ (r & 7)) * 16);
                cp16(sa, g);
            }
        }
    };

    load_stage(0, 0); CP_COMMIT();
    load_stage(1, 1); CP_COMMIT();

    for (int ks = 0; ks < KSTEPS; ks++) {
        CP_WAIT(1);
        __syncthreads();
        if (ks + 2 < KSTEPS) load_stage((ks + 2) % NSTG, ks + 2);
        CP_COMMIT();

        const uint32_t st = sbase + (ks % NSTG) * STAGE_B;
        const uint32_t ahB = st, alB = st + TILE_B;
        const uint32_t whB = st + 2*TILE_B, wlB = st + 3*TILE_B;
        const int lr = lane & 15, lc = lane >> 4;

        #pragma unroll
        for (int k16 = 0; k16 < 4; k16++) {
            uint32_t ah[4][4], al[4][4], wh[4][2], wl[4][2];
            #pragma unroll
            for (int i = 0; i < 4; i++) {
                int row = wm*64 + i*16 + lr;
                int c = k16*2 + lc;
                uint32_t off = row*128 + ((c ^ (row & 7)) * 16);
                ldsm_x4(ah[i], ahB + off);
                ldsm_x4(al[i], alB + off);
            }
            #pragma unroll
            for (int jj = 0; jj < 2; jj++) {
                int row = wn*32 + jj*16 + lr;
                int c = k16*2 + lc;
                uint32_t off = row*128 + ((c ^ (row & 7)) * 16);
                uint32_t t0[4], t1[4];
                ldsm_x4(t0, whB + off);
                wh[jj*2][0] = t0[0]; wh[jj*2][1] = t0[2];
                wh[jj*2+1][0] = t0[1]; wh[jj*2+1][1] = t0[3];
                ldsm_x4(t1, wlB + off);
                wl[jj*2][0] = t1[0]; wl[jj*2][1] = t1[2];
                wl[jj*2+1][0] = t1[1]; wl[jj*2+1][1] = t1[3];
            }
            #pragma unroll
            for (int i = 0; i < 4; i++)
                #pragma unroll
                for (int j = 0; j < 4; j++) {
                    mma_bf16(acc[i][j], ah[i], wh[j]);
                    mma_bf16(acc[i][j], ah[i], wl[j]);
                    mma_bf16(acc[i][j], al[i], wh[j]);
                }
        }
    }

    const int gq = lane >> 2, tig = lane & 3;
    #pragma unroll
    for (int j = 0; j < 4; j++) {
        const int n = col0 + wn*32 + j*8 + tig*2;
        float b0 = 0.f, b1 = 0.f;
        if (OUT == 0 && bias) { b0 = bias[n]; b1 = bias[n+1]; }
        #pragma unroll
        for (int i = 0; i < 4; i++) {
            const int m0 = row0 + wm*64 + i*16 + gq;
            float v00 = acc[i][j][0] + b0, v01 = acc[i][j][1] + b1;
            float v10 = acc[i][j][2] + b0, v11 = acc[i][j][3] + b1;
            if (OUT == 0) {
                *(float2*)(C + (size_t)m0 * GK + n) = make_float2(v00, v01);
                *(float2*)(C + (size_t)(m0 + 8) * GK + n) = make_float2(v10, v11);
            } else if (OUT == 1) {
                __nv_bfloat16* Chi = (__nv_bfloat16*)Chi_v;
                __nv_bfloat16* Clo = (__nv_bfloat16*)Clo_v;
                __nv_bfloat16 h00 = __float2bfloat16_rn(v00);
                __nv_bfloat16 h01 = __float2bfloat16_rn(v01);
                __nv_bfloat16 h10 = __float2bfloat16_rn(v10);
                __nv_bfloat16 h11 = __float2bfloat16_rn(v11);
                *(__nv_bfloat162*)(Chi + (size_t)m0*GK + n) = __nv_bfloat162(h00, h01);
                *(__nv_bfloat162*)(Chi + (size_t)(m0+8)*GK + n) = __nv_bfloat162(h10, h11);
                *(__nv_bfloat162*)(Clo + (size_t)m0*GK + n) = __nv_bfloat162(
                    __float2bfloat16_rn(v00 - __bfloat162float(h00)),
                    __float2bfloat16_rn(v01 - __bfloat162float(h01)));
                *(__nv_bfloat162*)(Clo + (size_t)(m0+8)*GK + n) = __nv_bfloat162(
                    __float2bfloat16_rn(v10 - __bfloat162float(h10)),
                    __float2bfloat16_rn(v11 - __bfloat162float(h11)));
            } else {
                __half* Chi = (__half*)Chi_v;
                __half* Clo = (__half*)Clo_v;
                __half h00 = __float2half_rn(v00);
                __half h01 = __float2half_rn(v01);
                __half h10 = __float2half_rn(v10);
                __half h11 = __float2half_rn(v11);
                *(__half2*)(Chi + (size_t)m0*GK + n) = __half2(h00, h01);
                *(__half2*)(Chi + (size_t)(m0+8)*GK + n) = __half2(h10, h11);
                *(__half2*)(Clo + (size_t)m0*GK + n) = __half2(
                    __float2half_rn(v00 - __half2float(h00)),
                    __float2half_rn(v01 - __half2float(h01)));
                *(__half2*)(Clo + (size_t)(m0+8)*GK + n) = __half2(
                    __float2half_rn(v10 - __half2float(h10)),
                    __float2half_rn(v11 - __half2float(h11)));
            }
        }
    }
}

// ---------------- HMMA flash attention (causal) ------------------------------
// Br=128 (8 warps x 16 rows), Bc=64, d=64.
// QK: 3-term bf16 split. PV: fp16, P rounded-consistent (l from rounded P),
// V fp16 hi/lo -> 2 MMAs. 2 CTAs/SM.
#define FL_QB   16384                  // 128 rows x 128B per Q tile
#define FL_TB   8192                   // 64 rows x 128B per K/V tile
#define FL_STG  (4*FL_TB)              // Kh|Kl|Vh|Vl = 32 KB
#define FL_SMEM (2*FL_QB + 2*FL_STG)   // 96 KB

__global__ __launch_bounds__(256, 2)
void flash_hmma_kernel(const __nv_bfloat16* __restrict__ qhi,
                       const __nv_bfloat16* __restrict__ qlo,
                       const __nv_bfloat16* __restrict__ khi,
                       const __nv_bfloat16* __restrict__ klo,
                       const __half* __restrict__ vhi,
                       const __half* __restrict__ vlo,
                       __nv_bfloat16* __restrict__ ohi,
                       __nv_bfloat16* __restrict__ olo) {
    extern __shared__ char sm[];
    const int tid  = threadIdx.x;
    const int wid  = tid >> 5;
    const int lane = tid & 31;
    const int qt = (int)(gridDim.x - 1 - blockIdx.x);   // heavy tiles first
    const int bh = blockIdx.y;
    const int b = bh >> 4, h = bh & 15;
    const int qrow0 = qt * 128;
    const size_t grow0 = (size_t)b * TT + qrow0;
    const int colb = h * HD;

    const uint32_t sb  = smem_u32(sm);
    const uint32_t qhB = sb, qlB = sb + FL_QB;
    const uint32_t stB = sb + 2*FL_QB;

    // ---- load Q tiles (hi, lo) ----
    {
        const __nv_bfloat16* srcs[2] = { qhi, qlo };
        #pragma unroll
        for (int t = 0; t < 2; t++) {
            uint32_t dst = t ? qlB : qhB;
            #pragma unroll
            for (int it = 0; it < 4; it++) {
                int u = tid + 256 * it;          // 0..1023
                int r = u >> 3, c = u & 7;
                cp16(dst + r*128 + ((c ^ (r & 7)) * 16),
                     srcs[t] + (grow0 + r) * EE + colb + c * 8);
            }
        }
    }
    const void* ksrc[4] = { khi, klo, vhi, vlo };
    auto load_stage = [&](int s, int kt) {
        const size_t krow = (size_t)b * TT + kt * 64;
        const uint32_t st = stB + s * FL_STG;
        #pragma unroll
        for (int t = 0; t < 4; t++) {
            #pragma unroll
            for (int it = 0; it < 2; it++) {
                int u = tid + 256 * it;          // 0..511
                int r = u >> 3, c = u & 7;
                const char* g = (const char*)ksrc[t] + ((krow + r) * EE + colb + c * 8) * 2;
                cp16(st + t*FL_TB + r*128 + ((c ^ (r & 7)) * 16), g);
            }
        }
    };
    load_stage(0, 0);
    CP_COMMIT();

    const int nkv = 2*qt + 2;
    CP_WAIT(0);
    __syncthreads();

    // ---- Q hi fragments to registers (lo reloaded per tile from SMEM) ----
    uint32_t qfh[4][4];
    const int lr = lane & 15, lc = lane >> 4;
    #pragma unroll
    for (int k16 = 0; k16 < 4; k16++) {
        int row = wid*16 + lr;
        int c = k16*2 + lc;
        uint32_t off = row*128 + ((c ^ (row & 7)) * 16);
        ldsm_x4(qfh[k16], qhB + off);
    }

    float m0 = -INFINITY, m1 = -INFINITY, l0 = 0.f, l1 = 0.f;
    float o[8][4] = {};
    const int rg0 = qrow0 + wid*16 + (lane >> 2);
    const int tig = lane & 3;

    for (int kt = 0; kt < nkv; kt++) {
        if (kt + 1 < nkv) {
            load_stage((kt + 1) & 1, kt + 1);
            CP_COMMIT();
            CP_WAIT(1);
        } else {
            CP_WAIT(0);
        }
        __syncthreads();

        const uint32_t st  = stB + (kt & 1) * FL_STG;
        const uint32_t khB = st, klB = st + FL_TB;
        const uint32_t vhB = st + 2*FL_TB, vlB = st + 3*FL_TB;

        // ---- S = Q K^T (3 terms) ----
        float s[8][4] = {};
        #pragma unroll
        for (int k16 = 0; k16 < 4; k16++) {
            uint32_t qfl[4];
            {
                int row = wid*16 + lr;
                int c = k16*2 + lc;
                uint32_t off = row*128 + ((c ^ (row & 7)) * 16);
                ldsm_x4(qfl, qlB + off);
            }
            uint32_t kh[8][2], kl[8][2];
            #pragma unroll
            for (int jj = 0; jj < 4; jj++) {
                int row = jj*16 + lr;
                int c = k16*2 + lc;
                uint32_t off = row*128 + ((c ^ (row & 7)) * 16);
                uint32_t t0[4], t1[4];
                ldsm_x4(t0, khB + off);
                kh[jj*2][0] = t0[0]; kh[jj*2][1] = t0[2];
                kh[jj*2+1][0] = t0[1]; kh[jj*2+1][1] = t0[3];
                ldsm_x4(t1, klB + off);
                kl[jj*2][0] = t1[0]; kl[jj*2][1] = t1[2];
                kl[jj*2+1][0] = t1[1]; kl[jj*2+1][1] = t1[3];
            }
            #pragma unroll
            for (int j = 0; j < 8; j++) {
                mma_bf16(s[j], qfh[k16], kh[j]);
                mma_bf16(s[j], qfh[k16], kl[j]);
                mma_bf16(s[j], qfl,      kh[j]);
            }
        }

        // ---- scale + causal mask ----
        const bool maskt = (kt >= 2*qt);
        #pragma unroll
        for (int j = 0; j < 8; j++) {
            s[j][0] *= 0.125f; s[j][1] *= 0.125f;
            s[j][2] *= 0.125f; s[j][3] *= 0.125f;
            if (maskt) {
                int c0 = kt*64 + j*8 + tig*2;
                if (c0     > rg0)     s[j][0] = -INFINITY;
                if (c0 + 1 > rg0)     s[j][1] = -INFINITY;
                if (c0     > rg0 + 8) s[j][2] = -INFINITY;
                if (c0 + 1 > rg0 + 8) s[j][3] = -INFINITY;
            }
        }

        // ---- online softmax; P rounded to fp16, l summed from ROUNDED p ----
        float tm0 = -INFINITY, tm1 = -INFINITY;
        #pragma unroll
        for (int j = 0; j < 8; j++) {
            tm0 = fmaxf(tm0, fmaxf(s[j][0], s[j][1]));
            tm1 = fmaxf(tm1, fmaxf(s[j][2], s[j][3]));
        }
        tm0 = fmaxf(tm0, __shfl_xor_sync(0xffffffff, tm0, 1));
        tm0 = fmaxf(tm0, __shfl_xor_sync(0xffffffff, tm0, 2));
        tm1 = fmaxf(tm1, __shfl_xor_sync(0xffffffff, tm1, 1));
        tm1 = fmaxf(tm1, __shfl_xor_sync(0xffffffff, tm1, 2));
        float mn0 = fmaxf(m0, tm0), mn1 = fmaxf(m1, tm1);
        float a0 = __expf(m0 - mn0), a1 = __expf(m1 - mn1);

        uint32_t pH01[8], pH23[8];
        float rs0 = 0.f, rs1 = 0.f;
        #pragma unroll
        for (int j = 0; j < 8; j++) {
            __half h0 = __float2half_rn(__expf(s[j][0] - mn0));
            __half h1 = __float2half_rn(__expf(s[j][1] - mn0));
            __half h2 = __float2half_rn(__expf(s[j][2] - mn1));
            __half h3 = __float2half_rn(__expf(s[j][3] - mn1));
            rs0 += __half2float(h0) + __half2float(h1);
            rs1 += __half2float(h2) + __half2float(h3);
            pH01[j] = ((uint32_t)*(uint16_t*)&h1 << 16) | *(uint16_t*)&h0;
            pH23[j] = ((uint32_t)*(uint16_t*)&h3 << 16) | *(uint16_t*)&h2;
        }
        rs0 += __shfl_xor_sync(0xffffffff, rs0, 1);
        rs0 += __shfl_xor_sync(0xffffffff, rs0, 2);
        rs1 += __shfl_xor_sync(0xffffffff, rs1, 1);
        rs1 += __shfl_xor_sync(0xffffffff, rs1, 2);
        l0 = l0 * a0 + rs0;
        l1 = l1 * a1 + rs1;
        m0 = mn0; m1 = mn1;

        #pragma unroll
        for (int j = 0; j < 8; j++) {
            o[j][0] *= a0; o[j][1] *= a0;
            o[j][2] *= a1; o[j][3] *= a1;
        }

        // ---- O += P (Vh + Vl), fp16, 2 MMAs per fragment ----
        const int mi = lane >> 3, li = lane & 7;
        #pragma unroll
        for (int c16 = 0; c16 < 4; c16++) {
            uint32_t aH[4] = { pH01[2*c16], pH23[2*c16], pH01[2*c16+1], pH23[2*c16+1] };
            #pragma unroll
            for (int dj = 0; dj < 4; dj++) {
                int row = c16*16 + ((mi >> 1) ? 8 : 0) + li;
                int ch  = dj*2 + (mi & 1);
                uint32_t off = row*128 + ((ch ^ (row & 7)) * 16);
                uint32_t t0[4], t1[4];
                ldsm_x4_t(t0, vhB + off);
                ldsm_x4_t(t1, vlB + off);
                uint32_t vh0[2] = { t0[0], t0[2] }, vh1[2] = { t0[1], t0[3] };
                uint32_t vl0[2] = { t1[0], t1[2] }, vl1[2] = { t1[1], t1[3] };
                mma_fp16(o[dj*2],   aH, vh0);
                mma_fp16(o[dj*2],   aH, vl0);
                mma_fp16(o[dj*2+1], aH, vh1);
                mma_fp16(o[dj*2+1], aH, vl1);
            }
        }
        __syncthreads();   // compute done before next prefetch overwrites buffer
    }

    // ---- normalize + split-write output ----
    const float i0 = 1.f / l0, i1 = 1.f / l1;
    const size_t r0g = grow0 + wid*16 + (lane >> 2);
    #pragma unroll
    for (int j = 0; j < 8; j++) {
        const int n = colb + j*8 + tig*2;
        float v00 = o[j][0] * i0, v01 = o[j][1] * i0;
        float v10 = o[j][2] * i1, v11 = o[j][3] * i1;
        __nv_bfloat16 h00 = __float2bfloat16_rn(v00);
        __nv_bfloat16 h01 = __float2bfloat16_rn(v01);
        __nv_bfloat16 h10 = __float2bfloat16_rn(v10);
        __nv_bfloat16 h11 = __float2bfloat16_rn(v11);
        *(__nv_bfloat162*)(ohi + r0g*EE + n)     = __nv_bfloat162(h00, h01);
        *(__nv_bfloat162*)(ohi + (r0g+8)*EE + n) = __nv_bfloat162(h10, h11);
        *(__nv_bfloat162*)(olo + r0g*EE + n)     = __nv_bfloat162(
            __float2bfloat16_rn(v00 - __bfloat162float(h00)),
            __float2bfloat16_rn(v01 - __bfloat162float(h01)));
        *(__nv_bfloat162*)(olo + (r0g+8)*EE + n) = __nv_bfloat162(
            __float2bfloat16_rn(v10 - __bfloat162float(h10)),
            __float2bfloat16_rn(v11 - __bfloat162float(h11)));
    }
}

// ---------------- launch ----------------------------------------------------
extern "C" void kernel_launch(void* const* d_in, const int* in_sizes, int n_in,
                              void* d_out, int out_size) {
    const float* x  = (const float*)d_in[0];
    const float* Wq = (const float*)d_in[1];
    const float* Wk = (const float*)d_in[2];
    const float* Wv = (const float*)d_in[3];
    const float* Wo = (const float*)d_in[4];
    const float* bo = (const float*)d_in[5];
    float* out = (float*)d_out;

    __nv_bfloat16 *p_rxhi, *p_rxlo, *p_xhi, *p_xlo;
    __nv_bfloat16 *p_qhi, *p_qlo, *p_khi, *p_klo, *p_athi, *p_atlo;
    __half *p_vhi, *p_vlo;
    __nv_bfloat16 *p_wqhi, *p_wqlo, *p_wkhi, *p_wklo, *p_wvhi, *p_wvlo, *p_wohi, *p_wolo;
    cudaGetSymbolAddress((void**)&p_rxhi, g_rxhi);
    cudaGetSymbolAddress((void**)&p_rxlo, g_rxlo);
    cudaGetSymbolAddress((void**)&p_xhi,  g_xhi);
    cudaGetSymbolAddress((void**)&p_xlo,  g_xlo);
    cudaGetSymbolAddress((void**)&p_qhi,  g_qhi);
    cudaGetSymbolAddress((void**)&p_qlo,  g_qlo);
    cudaGetSymbolAddress((void**)&p_khi,  g_khi);
    cudaGetSymbolAddress((void**)&p_klo,  g_klo);
    cudaGetSymbolAddress((void**)&p_vhi,  g_vhi);
    cudaGetSymbolAddress((void**)&p_vlo,  g_vlo);
    cudaGetSymbolAddress((void**)&p_athi, g_athi);
    cudaGetSymbolAddress((void**)&p_atlo, g_atlo);
    cudaGetSymbolAddress((void**)&p_wqhi, g_wqhi);
    cudaGetSymbolAddress((void**)&p_wqlo, g_wqlo);
    cudaGetSymbolAddress((void**)&p_wkhi, g_wkhi);
    cudaGetSymbolAddress((void**)&p_wklo, g_wklo);
    cudaGetSymbolAddress((void**)&p_wvhi, g_wvhi);
    cudaGetSymbolAddress((void**)&p_wvlo, g_wvlo);
    cudaGetSymbolAddress((void**)&p_wohi, g_wohi);
    cudaGetSymbolAddress((void**)&p_wolo, g_wolo);

    cudaFuncSetAttribute(hmma_gemm_kernel<0>,
                         cudaFuncAttributeMaxDynamicSharedMemorySize, GEMM_SMEM);
    cudaFuncSetAttribute(hmma_gemm_kernel<1>,
                         cudaFuncAttributeMaxDynamicSharedMemorySize, GEMM_SMEM);
    cudaFuncSetAttribute(hmma_gemm_kernel<2>,
                         cudaFuncAttributeMaxDynamicSharedMemorySize, GEMM_SMEM);
    cudaFuncSetAttribute(flash_hmma_kernel,
                         cudaFuncAttributeMaxDynamicSharedMemorySize, FL_SMEM);

    rope_table_kernel<<<(TT*E2 + 255)/256, 256>>>();
    rope_apply_split_kernel<<<(MM*E2 + 255)/256, 256>>>(x);
    split_kernel<<<(MM*EE + 255)/256, 256>>>(x, p_xhi, p_xlo, MM*EE);
    split_kernel<<<(EE*EE + 255)/256, 256>>>(Wq, p_wqhi, p_wqlo, EE*EE);
    split_kernel<<<(EE*EE + 255)/256, 256>>>(Wk, p_wkhi, p_wklo, EE*EE);
    split_kernel<<<(EE*EE + 255)/256, 256>>>(Wv, p_wvhi, p_wvlo, EE*EE);
    split_kernel<<<(EE*EE + 255)/256, 256>>>(Wo, p_wohi, p_wolo, EE*EE);

    dim3 mgrid(EE/128, MM/128);   // (8, 64)
    hmma_gemm_kernel<1><<<mgrid, 256, GEMM_SMEM>>>(p_rxhi, p_rxlo, p_wqhi, p_wqlo,
                                                   nullptr, p_qhi, p_qlo, nullptr);
    hmma_gemm_kernel<1><<<mgrid, 256, GEMM_SMEM>>>(p_rxhi, p_rxlo, p_wkhi, p_wklo,
                                                   nullptr, p_khi, p_klo, nullptr);
    hmma_gemm_kernel<2><<<mgrid, 256, GEMM_SMEM>>>(p_xhi,  p_xlo,  p_wvhi, p_wvlo,
                                                   nullptr, p_vhi, p_vlo, nullptr);

    dim3 fgrid(TT/128, BB*HH);    // (16, 64)
    flash_hmma_kernel<<<fgrid, 256, FL_SMEM>>>(p_qhi, p_qlo, p_khi, p_klo,
                                               p_vhi, p_vlo, p_athi, p_atlo);

    hmma_gemm_kernel<0><<<mgrid, 256, GEMM_SMEM>>>(p_athi, p_atlo, p_wohi, p_wolo,
                                                   out, nullptr, nullptr, bo);
}

// round 7
// speedup vs baseline: 3.3249x; 1.2172x over previous
#include <cuda_runtime.h>
#include <cuda_bf16.h>
#include <cuda_fp16.h>
#include <math.h>
#include <stdint.h>

// Problem constants
#define BB 4
#define TT 2048
#define EE 1024
#define HH 16
#define HD 64
#define MM (BB*TT)          // 8192 rows
#define E2 (EE/2)           // 512 pairs
#define GK 1024

// ---------------- scratch (device globals; no allocation allowed) ----------
__device__ float g_theta[E2];

__device__ __align__(256) __nv_bfloat16 g_rxhi[MM*EE];
__device__ __align__(256) __nv_bfloat16 g_rxlo[MM*EE];
__device__ __align__(256) __nv_bfloat16 g_xhi [MM*EE];
__device__ __align__(256) __nv_bfloat16 g_xlo [MM*EE];
__device__ __align__(256) __half        g_qh  [MM*EE];   // Q: single fp16
__device__ __align__(256) __half        g_khi [MM*EE];   // K: fp16 hi/lo
__device__ __align__(256) __half        g_klo [MM*EE];
__device__ __align__(256) __half        g_vhi [MM*EE];   // V: fp16 hi/lo
__device__ __align__(256) __half        g_vlo [MM*EE];
__device__ __align__(256) __nv_bfloat16 g_athi[MM*EE];
__device__ __align__(256) __nv_bfloat16 g_atlo[MM*EE];
__device__ __align__(256) __nv_bfloat16 g_wqhi[EE*EE];
__device__ __align__(256) __nv_bfloat16 g_wqlo[EE*EE];
__device__ __align__(256) __nv_bfloat16 g_wkhi[EE*EE];
__device__ __align__(256) __nv_bfloat16 g_wklo[EE*EE];
__device__ __align__(256) __nv_bfloat16 g_wvhi[EE*EE];
__device__ __align__(256) __nv_bfloat16 g_wvlo[EE*EE];
__device__ __align__(256) __nv_bfloat16 g_wohi[EE*EE];
__device__ __align__(256) __nv_bfloat16 g_wolo[EE*EE];

// ================= helpers (compute_80-level PTX only!) =====================
__device__ __forceinline__ uint32_t smem_u32(const void* p) {
    uint32_t a;
    asm("{ .reg .u64 t; cvta.to.shared.u64 t, %1; cvt.u32.u64 %0, t; }"
        : "=r"(a) : "l"(p));
    return a;
}
__device__ __forceinline__ void cp16(uint32_t saddr, const void* g) {
    asm volatile("cp.async.cg.shared.global [%0], [%1], 16;"
                 :: "r"(saddr), "l"(g) : "memory");
}
#define CP_COMMIT() asm volatile("cp.async.commit_group;" ::: "memory")
#define CP_WAIT(n)  asm volatile("cp.async.wait_group %0;" :: "n"(n) : "memory")

__device__ __forceinline__ void ldsm_x4(uint32_t* r, uint32_t addr) {
    asm volatile("ldmatrix.sync.aligned.m8n8.x4.shared.b16 {%0,%1,%2,%3}, [%4];"
                 : "=r"(r[0]), "=r"(r[1]), "=r"(r[2]), "=r"(r[3]) : "r"(addr));
}
__device__ __forceinline__ void ldsm_x4_t(uint32_t* r, uint32_t addr) {
    asm volatile("ldmatrix.sync.aligned.m8n8.x4.trans.shared.b16 {%0,%1,%2,%3}, [%4];"
                 : "=r"(r[0]), "=r"(r[1]), "=r"(r[2]), "=r"(r[3]) : "r"(addr));
}
__device__ __forceinline__ void mma_bf16(float* c, const uint32_t* a,
                                         const uint32_t* b) {
    asm volatile(
        "mma.sync.aligned.m16n8k16.row.col.f32.bf16.bf16.f32 "
        "{%0,%1,%2,%3}, {%4,%5,%6,%7}, {%8,%9}, {%0,%1,%2,%3};"
        : "+f"(c[0]), "+f"(c[1]), "+f"(c[2]), "+f"(c[3])
        : "r"(a[0]), "r"(a[1]), "r"(a[2]), "r"(a[3]), "r"(b[0]), "r"(b[1]));
}
__device__ __forceinline__ void mma_fp16(float* c, const uint32_t* a,
                                         const uint32_t* b) {
    asm volatile(
        "mma.sync.aligned.m16n8k16.row.col.f32.f16.f16.f32 "
        "{%0,%1,%2,%3}, {%4,%5,%6,%7}, {%8,%9}, {%0,%1,%2,%3};"
        : "+f"(c[0]), "+f"(c[1]), "+f"(c[2]), "+f"(c[3])
        : "r"(a[0]), "r"(a[1]), "r"(a[2]), "r"(a[3]), "r"(b[0]), "r"(b[1]));
}

// ---------------- theta table (tiny, fp64 once) ------------------------------
__global__ void theta_kernel() {
    int p = blockIdx.x * blockDim.x + threadIdx.x;
    if (p >= E2) return;
    g_theta[p] = (float)exp((-(double)(2*p) / (double)EE) * log(10000.0));
}

// ---------------- fused RoPE + split of x ------------------------------------
// ang = fp32(t*theta) like reference; reduce mod 2pi with fp32 FMA Cody-Waite,
// then sinf/cosf on the reduced argument (|r| <= pi).
#define P2HI 6.2831854820251465f            // fp32(2*pi)
#define P2LO -1.7484555e-7f                 // 2*pi - P2HI
#define INV2PI 0.15915494309189535f

__global__ void rope_fused_kernel(const float* __restrict__ x) {
    int idx = blockIdx.x * blockDim.x + threadIdx.x;   // over MM*E2 pairs
    if (idx >= MM*E2) return;
    int bt = idx / E2;
    int p  = idx % E2;
    int t  = bt % TT;
    float2 v = ((const float2*)x)[idx];
    float ang = (float)t * g_theta[p];      // fp32 rounding as in reference
    float n = rintf(ang * INV2PI);
    float r = fmaf(-n, P2HI, ang);
    r = fmaf(-n, P2LO, r);
    float s, c;
    sincosf(r, &s, &c);
    float rx = v.x * c - v.y * s;
    float ry = v.y * c + v.x * s;
    __nv_bfloat16 hx = __float2bfloat16_rn(rx);
    __nv_bfloat16 hy = __float2bfloat16_rn(ry);
    ((__nv_bfloat162*)g_rxhi)[idx] = __nv_bfloat162(hx, hy);
    ((__nv_bfloat162*)g_rxlo)[idx] = __nv_bfloat162(
        __float2bfloat16_rn(rx - __bfloat162float(hx)),
        __float2bfloat16_rn(ry - __bfloat162float(hy)));
    __nv_bfloat16 xh0 = __float2bfloat16_rn(v.x);
    __nv_bfloat16 xh1 = __float2bfloat16_rn(v.y);
    ((__nv_bfloat162*)g_xhi)[idx] = __nv_bfloat162(xh0, xh1);
    ((__nv_bfloat162*)g_xlo)[idx] = __nv_bfloat162(
        __float2bfloat16_rn(v.x - __bfloat162float(xh0)),
        __float2bfloat16_rn(v.y - __bfloat162float(xh1)));
}

__global__ void split_kernel(const float* __restrict__ src,
                             __nv_bfloat16* __restrict__ hi,
                             __nv_bfloat16* __restrict__ lo, int n) {
    int i = blockIdx.x * blockDim.x + threadIdx.x;
    if (i >= n) return;
    float x = src[i];
    __nv_bfloat16 h = __float2bfloat16_rn(x);
    hi[i] = h;
    lo[i] = __float2bfloat16_rn(x - __bfloat162float(h));
}

// ---------------- HMMA bf16-split NT GEMM (3-stage pipeline) -----------------
// C[m][n] = sum_k A[m][k]*W[n][k] (+bias), 3-term hi/lo split.
// OUT: 0 = fp32 C, 2 = fp16 hi/lo split, 3 = fp16 single (Chi only),
//      1 = bf16 hi/lo split.
#define KSTEPS (GK/64)          // 16
#define TILE_B 16384            // 128 rows x 128 bytes
#define STAGE_B (4*TILE_B)      // Ahi|Alo|Whi|Wlo = 64 KB
#define NSTG 3
#define GEMM_SMEM (NSTG*STAGE_B)   // 192 KB

template<int OUT>
__global__ __launch_bounds__(256)
void hmma_gemm_kernel(const __nv_bfloat16* __restrict__ Ahi,
                      const __nv_bfloat16* __restrict__ Alo,
                      const __nv_bfloat16* __restrict__ Whi,
                      const __nv_bfloat16* __restrict__ Wlo,
                      float* __restrict__ C,
                      void* __restrict__ Chi_v,
                      void* __restrict__ Clo_v,
                      const float* __restrict__ bias) {
    extern __shared__ char sm[];
    const int tid  = threadIdx.x;
    const int wid  = tid >> 5;
    const int lane = tid & 31;
    const int row0 = blockIdx.y * 128;
    const int col0 = blockIdx.x * 128;
    const uint32_t sbase = smem_u32(sm);
    const int wm = wid >> 2;
    const int wn = wid & 3;

    float acc[4][4][4] = {};
    const __nv_bfloat16* srcs[4] = { Ahi, Alo, Whi, Wlo };

    auto load_stage = [&](int s, int ks) {
        const int k0 = ks * 64;
        const uint32_t st = sbase + s * STAGE_B;
        #pragma unroll
        for (int t = 0; t < 4; t++) {
            const int rb = (t < 2) ? row0 : col0;
            #pragma unroll
            for (int it = 0; it < 4; it++) {
                int u = tid + 256 * it;
                int r = u >> 3, c = u & 7;
                const __nv_bfloat16* g = srcs[t] + (size_t)(rb + r) * GK + k0 + c * 8;
                uint32_t sa = st + t * TILE_B + r * 128 + ((c ^ (r & 7)) * 16);
                cp16(sa, g);
            }
        }
    };

    load_stage(0, 0); CP_COMMIT();
    load_stage(1, 1); CP_COMMIT();

    for (int ks = 0; ks < KSTEPS; ks++) {
        CP_WAIT(1);
        __syncthreads();
        if (ks + 2 < KSTEPS) load_stage((ks + 2) % NSTG, ks + 2);
        CP_COMMIT();

        const uint32_t st = sbase + (ks % NSTG) * STAGE_B;
        const uint32_t ahB = st, alB = st + TILE_B;
        const uint32_t whB = st + 2*TILE_B, wlB = st + 3*TILE_B;
        const int lr = lane & 15, lc = lane >> 4;

        #pragma unroll
        for (int k16 = 0; k16 < 4; k16++) {
            uint32_t ah[4][4], al[4][4], wh[4][2], wl[4][2];
            #pragma unroll
            for (int i = 0; i < 4; i++) {
                int row = wm*64 + i*16 + lr;
                int c = k16*2 + lc;
                uint32_t off = row*128 + ((c ^ (row & 7)) * 16);
                ldsm_x4(ah[i], ahB + off);
                ldsm_x4(al[i], alB + off);
            }
            #pragma unroll
            for (int jj = 0; jj < 2; jj++) {
                int row = wn*32 + jj*16 + lr;
                int c = k16*2 + lc;
                uint32_t off = row*128 + ((c ^ (row & 7)) * 16);
                uint32_t t0[4], t1[4];
                ldsm_x4(t0, whB + off);
                wh[jj*2][0] = t0[0]; wh[jj*2][1] = t0[2];
                wh[jj*2+1][0] = t0[1]; wh[jj*2+1][1] = t0[3];
                ldsm_x4(t1, wlB + off);
                wl[jj*2][0] = t1[0]; wl[jj*2][1] = t1[2];
                wl[jj*2+1][0] = t1[1]; wl[jj*2+1][1] = t1[3];
            }
            #pragma unroll
            for (int i = 0; i < 4; i++)
                #pragma unroll
                for (int j = 0; j < 4; j++) {
                    mma_bf16(acc[i][j], ah[i], wh[j]);
                    mma_bf16(acc[i][j], ah[i], wl[j]);
                    mma_bf16(acc[i][j], al[i], wh[j]);
                }
        }
    }

    const int gq = lane >> 2, tig = lane & 3;
    #pragma unroll
    for (int j = 0; j < 4; j++) {
        const int n = col0 + wn*32 + j*8 + tig*2;
        float b0 = 0.f, b1 = 0.f;
        if (OUT == 0 && bias) { b0 = bias[n]; b1 = bias[n+1]; }
        #pragma unroll
        for (int i = 0; i < 4; i++) {
            const int m0 = row0 + wm*64 + i*16 + gq;
            float v00 = acc[i][j][0] + b0, v01 = acc[i][j][1] + b1;
            float v10 = acc[i][j][2] + b0, v11 = acc[i][j][3] + b1;
            if (OUT == 0) {
                *(float2*)(C + (size_t)m0 * GK + n) = make_float2(v00, v01);
                *(float2*)(C + (size_t)(m0 + 8) * GK + n) = make_float2(v10, v11);
            } else if (OUT == 1) {
                __nv_bfloat16* Chi = (__nv_bfloat16*)Chi_v;
                __nv_bfloat16* Clo = (__nv_bfloat16*)Clo_v;
                __nv_bfloat16 h00 = __float2bfloat16_rn(v00);
                __nv_bfloat16 h01 = __float2bfloat16_rn(v01);
                __nv_bfloat16 h10 = __float2bfloat16_rn(v10);
                __nv_bfloat16 h11 = __float2bfloat16_rn(v11);
                *(__nv_bfloat162*)(Chi + (size_t)m0*GK + n) = __nv_bfloat162(h00, h01);
                *(__nv_bfloat162*)(Chi + (size_t)(m0+8)*GK + n) = __nv_bfloat162(h10, h11);
                *(__nv_bfloat162*)(Clo + (size_t)m0*GK + n) = __nv_bfloat162(
                    __float2bfloat16_rn(v00 - __bfloat162float(h00)),
                    __float2bfloat16_rn(v01 - __bfloat162float(h01)));
                *(__nv_bfloat162*)(Clo + (size_t)(m0+8)*GK + n) = __nv_bfloat162(
                    __float2bfloat16_rn(v10 - __bfloat162float(h10)),
                    __float2bfloat16_rn(v11 - __bfloat162float(h11)));
            } else if (OUT == 2) {
                __half* Chi = (__half*)Chi_v;
                __half* Clo = (__half*)Clo_v;
                __half h00 = __float2half_rn(v00);
                __half h01 = __float2half_rn(v01);
                __half h10 = __float2half_rn(v10);
                __half h11 = __float2half_rn(v11);
                *(__half2*)(Chi + (size_t)m0*GK + n) = __half2(h00, h01);
                *(__half2*)(Chi + (size_t)(m0+8)*GK + n) = __half2(h10, h11);
                *(__half2*)(Clo + (size_t)m0*GK + n) = __half2(
                    __float2half_rn(v00 - __half2float(h00)),
                    __float2half_rn(v01 - __half2float(h01)));
                *(__half2*)(Clo + (size_t)(m0+8)*GK + n) = __half2(
                    __float2half_rn(v10 - __half2float(h10)),
                    __float2half_rn(v11 - __half2float(h11)));
            } else {
                __half* Chi = (__half*)Chi_v;
                *(__half2*)(Chi + (size_t)m0*GK + n) =
                    __half2(__float2half_rn(v00), __float2half_rn(v01));
                *(__half2*)(Chi + (size_t)(m0+8)*GK + n) =
                    __half2(__float2half_rn(v10), __float2half_rn(v11));
            }
        }
    }
}

// ---------------- HMMA flash attention (causal) ------------------------------
// Br=128 (8 warps x 16 rows), Bc=64, d=64. All fp16 operands:
// QK: S = qh*(kh+kl), 2 MMAs. PV: P fp16 consistent-rounded, V hi/lo, 2 MMAs.
#define FL_QB   16384                  // 128 rows x 128B Q tile (fp16)
#define FL_TB   8192                   // 64 rows x 128B per K/V tile
#define FL_STG  (4*FL_TB)              // Kh|Kl|Vh|Vl = 32 KB
#define FL_SMEM (FL_QB + 2*FL_STG)     // 80 KB

__global__ __launch_bounds__(256, 2)
void flash_hmma_kernel(const __half* __restrict__ qh,
                       const __half* __restrict__ khi,
                       const __half* __restrict__ klo,
                       const __half* __restrict__ vhi,
                       const __half* __restrict__ vlo,
                       __nv_bfloat16* __restrict__ ohi,
                       __nv_bfloat16* __restrict__ olo) {
    extern __shared__ char sm[];
    const int tid  = threadIdx.x;
    const int wid  = tid >> 5;
    const int lane = tid & 31;
    const int qt = (int)(gridDim.x - 1 - blockIdx.x);   // heavy tiles first
    const int bh = blockIdx.y;
    const int b = bh >> 4, h = bh & 15;
    const int qrow0 = qt * 128;
    const size_t grow0 = (size_t)b * TT + qrow0;
    const int colb = h * HD;

    const uint32_t sb  = smem_u32(sm);
    const uint32_t qB  = sb;
    const uint32_t stB = sb + FL_QB;

    // ---- load Q tile ----
    #pragma unroll
    for (int it = 0; it < 4; it++) {
        int u = tid + 256 * it;          // 0..1023
        int r = u >> 3, c = u & 7;
        cp16(qB + r*128 + ((c ^ (r & 7)) * 16),
             qh + (grow0 + r) * EE + colb + c * 8);
    }
    const void* ksrc[4] = { khi, klo, vhi, vlo };
    auto load_stage = [&](int s, int kt) {
        const size_t krow = (size_t)b * TT + kt * 64;
        const uint32_t st = stB + s * FL_STG;
        #pragma unroll
        for (int t = 0; t < 4; t++) {
            #pragma unroll
            for (int it = 0; it < 2; it++) {
                int u = tid + 256 * it;          // 0..511
                int r = u >> 3, c = u & 7;
                const char* g = (const char*)ksrc[t] + ((krow + r) * EE + colb + c * 8) * 2;
                cp16(st + t*FL_TB + r*128 + ((c ^ (r & 7)) * 16), g);
            }
        }
    };
    load_stage(0, 0);
    CP_COMMIT();

    const int nkv = 2*qt + 2;
    CP_WAIT(0);
    __syncthreads();

    // ---- Q fragments to registers ----
    uint32_t qf[4][4];
    const int lr = lane & 15, lc = lane >> 4;
    #pragma unroll
    for (int k16 = 0; k16 < 4; k16++) {
        int row = wid*16 + lr;
        int c = k16*2 + lc;
        uint32_t off = row*128 + ((c ^ (row & 7)) * 16);
        ldsm_x4(qf[k16], qB + off);
    }

    float m0 = -INFINITY, m1 = -INFINITY, l0 = 0.f, l1 = 0.f;
    float o[8][4] = {};
    const int rg0 = qrow0 + wid*16 + (lane >> 2);
    const int tig = lane & 3;

    for (int kt = 0; kt < nkv; kt++) {
        if (kt + 1 < nkv) {
            load_stage((kt + 1) & 1, kt + 1);
            CP_COMMIT();
            CP_WAIT(1);
        } else {
            CP_WAIT(0);
        }
        __syncthreads();

        const uint32_t st  = stB + (kt & 1) * FL_STG;
        const uint32_t khB = st, klB = st + FL_TB;
        const uint32_t vhB = st + 2*FL_TB, vlB = st + 3*FL_TB;

        // ---- S = Q (Kh + Kl), fp16, 2 MMAs ----
        float s[8][4] = {};
        #pragma unroll
        for (int k16 = 0; k16 < 4; k16++) {
            uint32_t kh[8][2], kl[8][2];
            #pragma unroll
            for (int jj = 0; jj < 4; jj++) {
                int row = jj*16 + lr;
                int c = k16*2 + lc;
                uint32_t off = row*128 + ((c ^ (row & 7)) * 16);
                uint32_t t0[4], t1[4];
                ldsm_x4(t0, khB + off);
                kh[jj*2][0] = t0[0]; kh[jj*2][1] = t0[2];
                kh[jj*2+1][0] = t0[1]; kh[jj*2+1][1] = t0[3];
                ldsm_x4(t1, klB + off);
                kl[jj*2][0] = t1[0]; kl[jj*2][1] = t1[2];
                kl[jj*2+1][0] = t1[1]; kl[jj*2+1][1] = t1[3];
            }
            #pragma unroll
            for (int j = 0; j < 8; j++) {
                mma_fp16(s[j], qf[k16], kh[j]);
                mma_fp16(s[j], qf[k16], kl[j]);
            }
        }

        // ---- scale + causal mask ----
        const bool maskt = (kt >= 2*qt);
        #pragma unroll
        for (int j = 0; j < 8; j++) {
            s[j][0] *= 0.125f; s[j][1] *= 0.125f;
            s[j][2] *= 0.125f; s[j][3] *= 0.125f;
            if (maskt) {
                int c0 = kt*64 + j*8 + tig*2;
                if (c0     > rg0)     s[j][0] = -INFINITY;
                if (c0 + 1 > rg0)     s[j][1] = -INFINITY;
                if (c0     > rg0 + 8) s[j][2] = -INFINITY;
                if (c0 + 1 > rg0 + 8) s[j][3] = -INFINITY;
            }
        }

        // ---- online softmax; P rounded to fp16, l summed from ROUNDED p ----
        float tm0 = -INFINITY, tm1 = -INFINITY;
        #pragma unroll
        for (int j = 0; j < 8; j++) {
            tm0 = fmaxf(tm0, fmaxf(s[j][0], s[j][1]));
            tm1 = fmaxf(tm1, fmaxf(s[j][2], s[j][3]));
        }
        tm0 = fmaxf(tm0, __shfl_xor_sync(0xffffffff, tm0, 1));
        tm0 = fmaxf(tm0, __shfl_xor_sync(0xffffffff, tm0, 2));
        tm1 = fmaxf(tm1, __shfl_xor_sync(0xffffffff, tm1, 1));
        tm1 = fmaxf(tm1, __shfl_xor_sync(0xffffffff, tm1, 2));
        float mn0 = fmaxf(m0, tm0), mn1 = fmaxf(m1, tm1);
        float a0 = __expf(m0 - mn0), a1 = __expf(m1 - mn1);

        uint32_t pH01[8], pH23[8];
        float rs0 = 0.f, rs1 = 0.f;
        #pragma unroll
        for (int j = 0; j < 8; j++) {
            __half h0 = __float2half_rn(__expf(s[j][0] - mn0));
            __half h1 = __float2half_rn(__expf(s[j][1] - mn0));
            __half h2 = __float2half_rn(__expf(s[j][2] - mn1));
            __half h3 = __float2half_rn(__expf(s[j][3] - mn1));
            rs0 += __half2float(h0) + __half2float(h1);
            rs1 += __half2float(h2) + __half2float(h3);
            pH01[j] = ((uint32_t)*(uint16_t*)&h1 << 16) | *(uint16_t*)&h0;
            pH23[j] = ((uint32_t)*(uint16_t*)&h3 << 16) | *(uint16_t*)&h2;
        }
        rs0 += __shfl_xor_sync(0xffffffff, rs0, 1);
        rs0 += __shfl_xor_sync(0xffffffff, rs0, 2);
        rs1 += __shfl_xor_sync(0xffffffff, rs1, 1);
        rs1 += __shfl_xor_sync(0xffffffff, rs1, 2);
        l0 = l0 * a0 + rs0;
        l1 = l1 * a1 + rs1;
        m0 = mn0; m1 = mn1;

        #pragma unroll
        for (int j = 0; j < 8; j++) {
            o[j][0] *= a0; o[j][1] *= a0;
            o[j][2] *= a1; o[j][3] *= a1;
        }

        // ---- O += P (Vh + Vl), fp16 ----
        const int mi = lane >> 3, li = lane & 7;
        #pragma unroll
        for (int c16 = 0; c16 < 4; c16++) {
            uint32_t aH[4] = { pH01[2*c16], pH23[2*c16], pH01[2*c16+1], pH23[2*c16+1] };
            #pragma unroll
            for (int dj = 0; dj < 4; dj++) {
                int row = c16*16 + ((mi >> 1) ? 8 : 0) + li;
                int ch  = dj*2 + (mi & 1);
                uint32_t off = row*128 + ((ch ^ (row & 7)) * 16);
                uint32_t t0[4], t1[4];
                ldsm_x4_t(t0, vhB + off);
                ldsm_x4_t(t1, vlB + off);
                uint32_t vh0[2] = { t0[0], t0[2] }, vh1[2] = { t0[1], t0[3] };
                uint32_t vl0[2] = { t1[0], t1[2] }, vl1[2] = { t1[1], t1[3] };
                mma_fp16(o[dj*2],   aH, vh0);
                mma_fp16(o[dj*2],   aH, vl0);
                mma_fp16(o[dj*2+1], aH, vh1);
                mma_fp16(o[dj*2+1], aH, vl1);
            }
        }
        __syncthreads();   // compute done before next prefetch overwrites buffer
    }

    // ---- normalize + split-write output (bf16 hi/lo for O-proj GEMM) ----
    const float i0 = 1.f / l0, i1 = 1.f / l1;
    const size_t r0g = grow0 + wid*16 + (lane >> 2);
    #pragma unroll
    for (int j = 0; j < 8; j++) {
        const int n = colb + j*8 + tig*2;
        float v00 = o[j][0] * i0, v01 = o[j][1] * i0;
        float v10 = o[j][2] * i1, v11 = o[j][3] * i1;
        __nv_bfloat16 h00 = __float2bfloat16_rn(v00);
        __nv_bfloat16 h01 = __float2bfloat16_rn(v01);
        __nv_bfloat16 h10 = __float2bfloat16_rn(v10);
        __nv_bfloat16 h11 = __float2bfloat16_rn(v11);
        *(__nv_bfloat162*)(ohi + r0g*EE + n)     = __nv_bfloat162(h00, h01);
        *(__nv_bfloat162*)(ohi + (r0g+8)*EE + n) = __nv_bfloat162(h10, h11);
        *(__nv_bfloat162*)(olo + r0g*EE + n)     = __nv_bfloat162(
            __float2bfloat16_rn(v00 - __bfloat162float(h00)),
            __float2bfloat16_rn(v01 - __bfloat162float(h01)));
        *(__nv_bfloat162*)(olo + (r0g+8)*EE + n) = __nv_bfloat162(
            __float2bfloat16_rn(v10 - __bfloat162float(h10)),
            __float2bfloat16_rn(v11 - __bfloat162float(h11)));
    }
}

// ---------------- launch ----------------------------------------------------
extern "C" void kernel_launch(void* const* d_in, const int* in_sizes, int n_in,
                              void* d_out, int out_size) {
    const float* x  = (const float*)d_in[0];
    const float* Wq = (const float*)d_in[1];
    const float* Wk = (const float*)d_in[2];
    const float* Wv = (const float*)d_in[3];
    const float* Wo = (const float*)d_in[4];
    const float* bo = (const float*)d_in[5];
    float* out = (float*)d_out;

    __nv_bfloat16 *p_rxhi, *p_rxlo, *p_xhi, *p_xlo, *p_athi, *p_atlo;
    __half *p_qh, *p_khi, *p_klo, *p_vhi, *p_vlo;
    __nv_bfloat16 *p_wqhi, *p_wqlo, *p_wkhi, *p_wklo, *p_wvhi, *p_wvlo, *p_wohi, *p_wolo;
    cudaGetSymbolAddress((void**)&p_rxhi, g_rxhi);
    cudaGetSymbolAddress((void**)&p_rxlo, g_rxlo);
    cudaGetSymbolAddress((void**)&p_xhi,  g_xhi);
    cudaGetSymbolAddress((void**)&p_xlo,  g_xlo);
    cudaGetSymbolAddress((void**)&p_qh,   g_qh);
    cudaGetSymbolAddress((void**)&p_khi,  g_khi);
    cudaGetSymbolAddress((void**)&p_klo,  g_klo);
    cudaGetSymbolAddress((void**)&p_vhi,  g_vhi);
    cudaGetSymbolAddress((void**)&p_vlo,  g_vlo);
    cudaGetSymbolAddress((void**)&p_athi, g_athi);
    cudaGetSymbolAddress((void**)&p_atlo, g_atlo);
    cudaGetSymbolAddress((void**)&p_wqhi, g_wqhi);
    cudaGetSymbolAddress((void**)&p_wqlo, g_wqlo);
    cudaGetSymbolAddress((void**)&p_wkhi, g_wkhi);
    cudaGetSymbolAddress((void**)&p_wklo, g_wklo);
    cudaGetSymbolAddress((void**)&p_wvhi, g_wvhi);
    cudaGetSymbolAddress((void**)&p_wvlo, g_wvlo);
    cudaGetSymbolAddress((void**)&p_wohi, g_wohi);
    cudaGetSymbolAddress((void**)&p_wolo, g_wolo);

    cudaFuncSetAttribute(hmma_gemm_kernel<0>,
                         cudaFuncAttributeMaxDynamicSharedMemorySize, GEMM_SMEM);
    cudaFuncSetAttribute(hmma_gemm_kernel<2>,
                         cudaFuncAttributeMaxDynamicSharedMemorySize, GEMM_SMEM);
    cudaFuncSetAttribute(hmma_gemm_kernel<3>,
                         cudaFuncAttributeMaxDynamicSharedMemorySize, GEMM_SMEM);
    cudaFuncSetAttribute(flash_hmma_kernel,
                         cudaFuncAttributeMaxDynamicSharedMemorySize, FL_SMEM);

    theta_kernel<<<2, 256>>>();
    rope_fused_kernel<<<(MM*E2 + 255)/256, 256>>>(x);
    split_kernel<<<(EE*EE + 255)/256, 256>>>(Wq, p_wqhi, p_wqlo, EE*EE);
    split_kernel<<<(EE*EE + 255)/256, 256>>>(Wk, p_wkhi, p_wklo, EE*EE);
    split_kernel<<<(EE*EE + 255)/256, 256>>>(Wv, p_wvhi, p_wvlo, EE*EE);
    split_kernel<<<(EE*EE + 255)/256, 256>>>(Wo, p_wohi, p_wolo, EE*EE);

    dim3 mgrid(EE/128, MM/128);   // (8, 64)
    hmma_gemm_kernel<3><<<mgrid, 256, GEMM_SMEM>>>(p_rxhi, p_rxlo, p_wqhi, p_wqlo,
                                                   nullptr, p_qh, nullptr, nullptr);
    hmma_gemm_kernel<2><<<mgrid, 256, GEMM_SMEM>>>(p_rxhi, p_rxlo, p_wkhi, p_wklo,
                                                   nullptr, p_khi, p_klo, nullptr);
    hmma_gemm_kernel<2><<<mgrid, 256, GEMM_SMEM>>>(p_xhi,  p_xlo,  p_wvhi, p_wvlo,
                                                   nullptr, p_vhi, p_vlo, nullptr);

    dim3 fgrid(TT/128, BB*HH);    // (16, 64)
    flash_hmma_kernel<<<fgrid, 256, FL_SMEM>>>(p_qh, p_khi, p_klo,
                                               p_vhi, p_vlo, p_athi, p_atlo);

    hmma_gemm_kernel<0><<<mgrid, 256, GEMM_SMEM>>>(p_athi, p_atlo, p_wohi, p_wolo,
                                                   out, nullptr, nullptr, bo);
}

// round 8
// speedup vs baseline: 4.4524x; 1.3391x over previous
#include <cuda_runtime.h>
#include <cuda_bf16.h>
#include <cuda_fp16.h>
#include <math.h>
#include <stdint.h>

// Problem constants
#define BB 4
#define TT 2048
#define EE 1024
#define HH 16
#define HD 64
#define MM (BB*TT)          // 8192 rows
#define E2 (EE/2)           // 512 pairs
#define GK 1024

// ---------------- scratch (device globals; no allocation allowed) ----------
__device__ float g_theta[E2];

__device__ __align__(256) __half        g_rxh [MM*EE];   // RoPE(x), fp16
__device__ __align__(256) __half        g_xh  [MM*EE];   // x, fp16
__device__ __align__(256) __half        g_qh  [MM*EE];   // Q fp16
__device__ __align__(256) __half        g_kh  [MM*EE];   // K fp16
__device__ __align__(256) __half        g_vh  [MM*EE];   // V fp16
__device__ __align__(256) __nv_bfloat16 g_athi[MM*EE];   // attn out hi/lo (bf16)
__device__ __align__(256) __nv_bfloat16 g_atlo[MM*EE];
__device__ __align__(256) __half        g_wqhi[EE*EE];   // W fp16 hi/lo
__device__ __align__(256) __half        g_wqlo[EE*EE];
__device__ __align__(256) __half        g_wkhi[EE*EE];
__device__ __align__(256) __half        g_wklo[EE*EE];
__device__ __align__(256) __half        g_wvhi[EE*EE];
__device__ __align__(256) __half        g_wvlo[EE*EE];
__device__ __align__(256) __nv_bfloat16 g_wohi[EE*EE];   // Wo bf16 hi/lo
__device__ __align__(256) __nv_bfloat16 g_wolo[EE*EE];

// ================= helpers (compute_80-level PTX only!) =====================
__device__ __forceinline__ uint32_t smem_u32(const void* p) {
    uint32_t a;
    asm("{ .reg .u64 t; cvta.to.shared.u64 t, %1; cvt.u32.u64 %0, t; }"
        : "=r"(a) : "l"(p));
    return a;
}
__device__ __forceinline__ void cp16(uint32_t saddr, const void* g) {
    asm volatile("cp.async.cg.shared.global [%0], [%1], 16;"
                 :: "r"(saddr), "l"(g) : "memory");
}
#define CP_COMMIT() asm volatile("cp.async.commit_group;" ::: "memory")
#define CP_WAIT(n)  asm volatile("cp.async.wait_group %0;" :: "n"(n) : "memory")

__device__ __forceinline__ void ldsm_x4(uint32_t* r, uint32_t addr) {
    asm volatile("ldmatrix.sync.aligned.m8n8.x4.shared.b16 {%0,%1,%2,%3}, [%4];"
                 : "=r"(r[0]), "=r"(r[1]), "=r"(r[2]), "=r"(r[3]) : "r"(addr));
}
__device__ __forceinline__ void ldsm_x4_t(uint32_t* r, uint32_t addr) {
    asm volatile("ldmatrix.sync.aligned.m8n8.x4.trans.shared.b16 {%0,%1,%2,%3}, [%4];"
                 : "=r"(r[0]), "=r"(r[1]), "=r"(r[2]), "=r"(r[3]) : "r"(addr));
}
__device__ __forceinline__ void mma_bf16(float* c, const uint32_t* a,
                                         const uint32_t* b) {
    asm volatile(
        "mma.sync.aligned.m16n8k16.row.col.f32.bf16.bf16.f32 "
        "{%0,%1,%2,%3}, {%4,%5,%6,%7}, {%8,%9}, {%0,%1,%2,%3};"
        : "+f"(c[0]), "+f"(c[1]), "+f"(c[2]), "+f"(c[3])
        : "r"(a[0]), "r"(a[1]), "r"(a[2]), "r"(a[3]), "r"(b[0]), "r"(b[1]));
}
__device__ __forceinline__ void mma_fp16(float* c, const uint32_t* a,
                                         const uint32_t* b) {
    asm volatile(
        "mma.sync.aligned.m16n8k16.row.col.f32.f16.f16.f32 "
        "{%0,%1,%2,%3}, {%4,%5,%6,%7}, {%8,%9}, {%0,%1,%2,%3};"
        : "+f"(c[0]), "+f"(c[1]), "+f"(c[2]), "+f"(c[3])
        : "r"(a[0]), "r"(a[1]), "r"(a[2]), "r"(a[3]), "r"(b[0]), "r"(b[1]));
}

// ---------------- theta table ------------------------------------------------
__global__ void theta_kernel() {
    int p = blockIdx.x * blockDim.x + threadIdx.x;
    if (p >= E2) return;
    g_theta[p] = (float)exp((-(double)(2*p) / (double)EE) * log(10000.0));
}

// ---------------- fused RoPE (fp16 out) + x fp16 ------------------------------
#define P2HI 6.2831854820251465f
#define P2LO -1.7484555e-7f
#define INV2PI 0.15915494309189535f

__global__ void rope_fused_kernel(const float* __restrict__ x) {
    int idx = blockIdx.x * blockDim.x + threadIdx.x;   // over MM*E2 pairs
    if (idx >= MM*E2) return;
    int bt = idx / E2;
    int p  = idx % E2;
    int t  = bt % TT;
    float2 v = ((const float2*)x)[idx];
    float ang = (float)t * g_theta[p];      // fp32 rounding as in reference
    float n = rintf(ang * INV2PI);
    float r = fmaf(-n, P2HI, ang);
    r = fmaf(-n, P2LO, r);
    float s, c;
    sincosf(r, &s, &c);
    float rx = v.x * c - v.y * s;
    float ry = v.y * c + v.x * s;
    ((__half2*)g_rxh)[idx] = __floats2half2_rn(rx, ry);
    ((__half2*)g_xh)[idx]  = __floats2half2_rn(v.x, v.y);
}

// fp32 -> fp16 hi/lo split
__global__ void split16_kernel(const float* __restrict__ src,
                               __half* __restrict__ hi,
                               __half* __restrict__ lo, int n) {
    int i = blockIdx.x * blockDim.x + threadIdx.x;
    if (i >= n) return;
    float x = src[i];
    __half h = __float2half_rn(x);
    hi[i] = h;
    lo[i] = __float2half_rn(x - __half2float(h));
}

// fp32 -> bf16 hi/lo split
__global__ void split_kernel(const float* __restrict__ src,
                             __nv_bfloat16* __restrict__ hi,
                             __nv_bfloat16* __restrict__ lo, int n) {
    int i = blockIdx.x * blockDim.x + threadIdx.x;
    if (i >= n) return;
    float x = src[i];
    __nv_bfloat16 h = __float2bfloat16_rn(x);
    hi[i] = h;
    lo[i] = __float2bfloat16_rn(x - __bfloat162float(h));
}

// ---------------- 2-term fp16 NT GEMM: C = A*(Wh+Wl), fp16 out ---------------
// A: fp16 single. MMAs per (i,j,k16): 2.
#define KSTEPS (GK/64)          // 16
#define TILE_B 16384            // 128 rows x 128 bytes
#define STG16_B (3*TILE_B)      // A|Wh|Wl = 48 KB
#define NSTG 3
#define GEMM16_SMEM (NSTG*STG16_B)   // 144 KB

__global__ __launch_bounds__(256)
void hmma_gemm16_kernel(const __half* __restrict__ A,
                        const __half* __restrict__ Whi,
                        const __half* __restrict__ Wlo,
                        __half* __restrict__ Cout) {
    extern __shared__ char sm[];
    const int tid  = threadIdx.x;
    const int wid  = tid >> 5;
    const int lane = tid & 31;
    const int row0 = blockIdx.y * 128;
    const int col0 = blockIdx.x * 128;
    const uint32_t sbase = smem_u32(sm);
    const int wm = wid >> 2;
    const int wn = wid & 3;

    float acc[4][4][4] = {};
    const __half* srcs[3] = { A, Whi, Wlo };

    auto load_stage = [&](int s, int ks) {
        const int k0 = ks * 64;
        const uint32_t st = sbase + s * STG16_B;
        #pragma unroll
        for (int t = 0; t < 3; t++) {
            const int rb = (t == 0) ? row0 : col0;
            #pragma unroll
            for (int it = 0; it < 4; it++) {
                int u = tid + 256 * it;
                int r = u >> 3, c = u & 7;
                const __half* g = srcs[t] + (size_t)(rb + r) * GK + k0 + c * 8;
                uint32_t sa = st + t * TILE_B + r * 128 + ((c ^ (r & 7)) * 16);
                cp16(sa, g);
            }
        }
    };

    load_stage(0, 0); CP_COMMIT();
    load_stage(1, 1); CP_COMMIT();

    for (int ks = 0; ks < KSTEPS; ks++) {
        CP_WAIT(1);
        __syncthreads();
        if (ks + 2 < KSTEPS) load_stage((ks + 2) % NSTG, ks + 2);
        CP_COMMIT();

        const uint32_t st = sbase + (ks % NSTG) * STG16_B;
        const uint32_t aB = st;
        const uint32_t whB = st + TILE_B, wlB = st + 2*TILE_B;
        const int lr = lane & 15, lc = lane >> 4;

        #pragma unroll
        for (int k16 = 0; k16 < 4; k16++) {
            uint32_t a[4][4], wh[4][2], wl[4][2];
            #pragma unroll
            for (int i = 0; i < 4; i++) {
                int row = wm*64 + i*16 + lr;
                int c = k16*2 + lc;
                uint32_t off = row*128 + ((c ^ (row & 7)) * 16);
                ldsm_x4(a[i], aB + off);
            }
            #pragma unroll
            for (int jj = 0; jj < 2; jj++) {
                int row = wn*32 + jj*16 + lr;
                int c = k16*2 + lc;
                uint32_t off = row*128 + ((c ^ (row & 7)) * 16);
                uint32_t t0[4], t1[4];
                ldsm_x4(t0, whB + off);
                wh[jj*2][0] = t0[0]; wh[jj*2][1] = t0[2];
                wh[jj*2+1][0] = t0[1]; wh[jj*2+1][1] = t0[3];
                ldsm_x4(t1, wlB + off);
                wl[jj*2][0] = t1[0]; wl[jj*2][1] = t1[2];
                wl[jj*2+1][0] = t1[1]; wl[jj*2+1][1] = t1[3];
            }
            #pragma unroll
            for (int i = 0; i < 4; i++)
                #pragma unroll
                for (int j = 0; j < 4; j++) {
                    mma_fp16(acc[i][j], a[i], wh[j]);
                    mma_fp16(acc[i][j], a[i], wl[j]);
                }
        }
    }

    const int gq = lane >> 2, tig = lane & 3;
    #pragma unroll
    for (int j = 0; j < 4; j++) {
        const int n = col0 + wn*32 + j*8 + tig*2;
        #pragma unroll
        for (int i = 0; i < 4; i++) {
            const int m0 = row0 + wm*64 + i*16 + gq;
            *(__half2*)(Cout + (size_t)m0*GK + n) =
                __floats2half2_rn(acc[i][j][0], acc[i][j][1]);
            *(__half2*)(Cout + (size_t)(m0+8)*GK + n) =
                __floats2half2_rn(acc[i][j][2], acc[i][j][3]);
        }
    }
}

// ---------------- 3-term bf16 NT GEMM, fp32 out + bias (O-projection) --------
#define STAGE_B (4*TILE_B)      // Ahi|Alo|Whi|Wlo = 64 KB
#define GEMM_SMEM (NSTG*STAGE_B)   // 192 KB

__global__ __launch_bounds__(256)
void hmma_gemm_out_kernel(const __nv_bfloat16* __restrict__ Ahi,
                          const __nv_bfloat16* __restrict__ Alo,
                          const __nv_bfloat16* __restrict__ Whi,
                          const __nv_bfloat16* __restrict__ Wlo,
                          float* __restrict__ C,
                          const float* __restrict__ bias) {
    extern __shared__ char sm[];
    const int tid  = threadIdx.x;
    const int wid  = tid >> 5;
    const int lane = tid & 31;
    const int row0 = blockIdx.y * 128;
    const int col0 = blockIdx.x * 128;
    const uint32_t sbase = smem_u32(sm);
    const int wm = wid >> 2;
    const int wn = wid & 3;

    float acc[4][4][4] = {};
    const __nv_bfloat16* srcs[4] = { Ahi, Alo, Whi, Wlo };

    auto load_stage = [&](int s, int ks) {
        const int k0 = ks * 64;
        const uint32_t st = sbase + s * STAGE_B;
        #pragma unroll
        for (int t = 0; t < 4; t++) {
            const int rb = (t < 2) ? row0 : col0;
            #pragma unroll
            for (int it = 0; it < 4; it++) {
                int u = tid + 256 * it;
                int r = u >> 3, c = u & 7;
                const __nv_bfloat16* g = srcs[t] + (size_t)(rb + r) * GK + k0 + c * 8;
                uint32_t sa = st + t * TILE_B + r * 128 + ((c ^ (r & 7)) * 16);
                cp16(sa, g);
            }
        }
    };

    load_stage(0, 0); CP_COMMIT();
    load_stage(1, 1); CP_COMMIT();

    for (int ks = 0; ks < KSTEPS; ks++) {
        CP_WAIT(1);
        __syncthreads();
        if (ks + 2 < KSTEPS) load_stage((ks + 2) % NSTG, ks + 2);
        CP_COMMIT();

        const uint32_t st = sbase + (ks % NSTG) * STAGE_B;
        const uint32_t ahB = st, alB = st + TILE_B;
        const uint32_t whB = st + 2*TILE_B, wlB = st + 3*TILE_B;
        const int lr = lane & 15, lc = lane >> 4;

        #pragma unroll
        for (int k16 = 0; k16 < 4; k16++) {
            uint32_t ah[4][4], al[4][4], wh[4][2], wl[4][2];
            #pragma unroll
            for (int i = 0; i < 4; i++) {
                int row = wm*64 + i*16 + lr;
                int c = k16*2 + lc;
                uint32_t off = row*128 + ((c ^ (row & 7)) * 16);
                ldsm_x4(ah[i], ahB + off);
                ldsm_x4(al[i], alB + off);
            }
            #pragma unroll
            for (int jj = 0; jj < 2; jj++) {
                int row = wn*32 + jj*16 + lr;
                int c = k16*2 + lc;
                uint32_t off = row*128 + ((c ^ (row & 7)) * 16);
                uint32_t t0[4], t1[4];
                ldsm_x4(t0, whB + off);
                wh[jj*2][0] = t0[0]; wh[jj*2][1] = t0[2];
                wh[jj*2+1][0] = t0[1]; wh[jj*2+1][1] = t0[3];
                ldsm_x4(t1, wlB + off);
                wl[jj*2][0] = t1[0]; wl[jj*2][1] = t1[2];
                wl[jj*2+1][0] = t1[1]; wl[jj*2+1][1] = t1[3];
            }
            #pragma unroll
            for (int i = 0; i < 4; i++)
                #pragma unroll
                for (int j = 0; j < 4; j++) {
                    mma_bf16(acc[i][j], ah[i], wh[j]);
                    mma_bf16(acc[i][j], ah[i], wl[j]);
                    mma_bf16(acc[i][j], al[i], wh[j]);
                }
        }
    }

    const int gq = lane >> 2, tig = lane & 3;
    #pragma unroll
    for (int j = 0; j < 4; j++) {
        const int n = col0 + wn*32 + j*8 + tig*2;
        float b0 = bias[n], b1 = bias[n+1];
        #pragma unroll
        for (int i = 0; i < 4; i++) {
            const int m0 = row0 + wm*64 + i*16 + gq;
            *(float2*)(C + (size_t)m0 * GK + n) =
                make_float2(acc[i][j][0] + b0, acc[i][j][1] + b1);
            *(float2*)(C + (size_t)(m0 + 8) * GK + n) =
                make_float2(acc[i][j][2] + b0, acc[i][j][3] + b1);
        }
    }
}

// ---------------- HMMA flash attention (causal, single fp16 q/k/v) -----------
// Br=128 (8 warps x 16 rows), Bc=64, d=64. QK 1 MMA, PV 1 MMA term.
#define FL_QB   16384                  // 128 rows x 128B Q tile (fp16)
#define FL_TB   8192                   // 64 rows x 128B per K/V tile
#define FL_STG  (2*FL_TB)              // K|V = 16 KB
#define FL_SMEM (FL_QB + 2*FL_STG)     // 48 KB

__global__ __launch_bounds__(256, 2)
void flash_hmma_kernel(const __half* __restrict__ qh,
                       const __half* __restrict__ kh,
                       const __half* __restrict__ vh,
                       __nv_bfloat16* __restrict__ ohi,
                       __nv_bfloat16* __restrict__ olo) {
    extern __shared__ char sm[];
    const int tid  = threadIdx.x;
    const int wid  = tid >> 5;
    const int lane = tid & 31;
    const int qt = (int)(gridDim.x - 1 - blockIdx.x);   // heavy tiles first
    const int bh = blockIdx.y;
    const int b = bh >> 4, h = bh & 15;
    const int qrow0 = qt * 128;
    const size_t grow0 = (size_t)b * TT + qrow0;
    const int colb = h * HD;

    const uint32_t sb  = smem_u32(sm);
    const uint32_t qB  = sb;
    const uint32_t stB = sb + FL_QB;

    // ---- load Q tile ----
    #pragma unroll
    for (int it = 0; it < 4; it++) {
        int u = tid + 256 * it;          // 0..1023
        int r = u >> 3, c = u & 7;
        cp16(qB + r*128 + ((c ^ (r & 7)) * 16),
             qh + (grow0 + r) * EE + colb + c * 8);
    }
    const __half* ksrc[2] = { kh, vh };
    auto load_stage = [&](int s, int kt) {
        const size_t krow = (size_t)b * TT + kt * 64;
        const uint32_t st = stB + s * FL_STG;
        #pragma unroll
        for (int t = 0; t < 2; t++) {
            #pragma unroll
            for (int it = 0; it < 2; it++) {
                int u = tid + 256 * it;          // 0..511
                int r = u >> 3, c = u & 7;
                cp16(st + t*FL_TB + r*128 + ((c ^ (r & 7)) * 16),
                     ksrc[t] + (krow + r) * EE + colb + c * 8);
            }
        }
    };
    load_stage(0, 0);
    CP_COMMIT();

    const int nkv = 2*qt + 2;
    CP_WAIT(0);
    __syncthreads();

    // ---- Q fragments ----
    uint32_t qf[4][4];
    const int lr = lane & 15, lc = lane >> 4;
    #pragma unroll
    for (int k16 = 0; k16 < 4; k16++) {
        int row = wid*16 + lr;
        int c = k16*2 + lc;
        uint32_t off = row*128 + ((c ^ (row & 7)) * 16);
        ldsm_x4(qf[k16], qB + off);
    }

    float m0 = -INFINITY, m1 = -INFINITY, l0 = 0.f, l1 = 0.f;
    float o[8][4] = {};
    const int rg0 = qrow0 + wid*16 + (lane >> 2);
    const int tig = lane & 3;

    for (int kt = 0; kt < nkv; kt++) {
        if (kt + 1 < nkv) {
            load_stage((kt + 1) & 1, kt + 1);
            CP_COMMIT();
            CP_WAIT(1);
        } else {
            CP_WAIT(0);
        }
        __syncthreads();

        const uint32_t st  = stB + (kt & 1) * FL_STG;
        const uint32_t kB = st, vB = st + FL_TB;

        // ---- S = Q K^T, 1 MMA ----
        float s[8][4] = {};
        #pragma unroll
        for (int k16 = 0; k16 < 4; k16++) {
            uint32_t kf[8][2];
            #pragma unroll
            for (int jj = 0; jj < 4; jj++) {
                int row = jj*16 + lr;
                int c = k16*2 + lc;
                uint32_t off = row*128 + ((c ^ (row & 7)) * 16);
                uint32_t t0[4];
                ldsm_x4(t0, kB + off);
                kf[jj*2][0] = t0[0]; kf[jj*2][1] = t0[2];
                kf[jj*2+1][0] = t0[1]; kf[jj*2+1][1] = t0[3];
            }
            #pragma unroll
            for (int j = 0; j < 8; j++)
                mma_fp16(s[j], qf[k16], kf[j]);
        }

        // ---- scale + causal mask ----
        const bool maskt = (kt >= 2*qt);
        #pragma unroll
        for (int j = 0; j < 8; j++) {
            s[j][0] *= 0.125f; s[j][1] *= 0.125f;
            s[j][2] *= 0.125f; s[j][3] *= 0.125f;
            if (maskt) {
                int c0 = kt*64 + j*8 + tig*2;
                if (c0     > rg0)     s[j][0] = -INFINITY;
                if (c0 + 1 > rg0)     s[j][1] = -INFINITY;
                if (c0     > rg0 + 8) s[j][2] = -INFINITY;
                if (c0 + 1 > rg0 + 8) s[j][3] = -INFINITY;
            }
        }

        // ---- online softmax; P fp16 consistent-rounded ----
        float tm0 = -INFINITY, tm1 = -INFINITY;
        #pragma unroll
        for (int j = 0; j < 8; j++) {
            tm0 = fmaxf(tm0, fmaxf(s[j][0], s[j][1]));
            tm1 = fmaxf(tm1, fmaxf(s[j][2], s[j][3]));
        }
        tm0 = fmaxf(tm0, __shfl_xor_sync(0xffffffff, tm0, 1));
        tm0 = fmaxf(tm0, __shfl_xor_sync(0xffffffff, tm0, 2));
        tm1 = fmaxf(tm1, __shfl_xor_sync(0xffffffff, tm1, 1));
        tm1 = fmaxf(tm1, __shfl_xor_sync(0xffffffff, tm1, 2));
        float mn0 = fmaxf(m0, tm0), mn1 = fmaxf(m1, tm1);
        float a0 = __expf(m0 - mn0), a1 = __expf(m1 - mn1);

        uint32_t pH01[8], pH23[8];
        float rs0 = 0.f, rs1 = 0.f;
        #pragma unroll
        for (int j = 0; j < 8; j++) {
            __half h0 = __float2half_rn(__expf(s[j][0] - mn0));
            __half h1 = __float2half_rn(__expf(s[j][1] - mn0));
            __half h2 = __float2half_rn(__expf(s[j][2] - mn1));
            __half h3 = __float2half_rn(__expf(s[j][3] - mn1));
            rs0 += __half2float(h0) + __half2float(h1);
            rs1 += __half2float(h2) + __half2float(h3);
            pH01[j] = ((uint32_t)*(uint16_t*)&h1 << 16) | *(uint16_t*)&h0;
            pH23[j] = ((uint32_t)*(uint16_t*)&h3 << 16) | *(uint16_t*)&h2;
        }
        rs0 += __shfl_xor_sync(0xffffffff, rs0, 1);
        rs0 += __shfl_xor_sync(0xffffffff, rs0, 2);
        rs1 += __shfl_xor_sync(0xffffffff, rs1, 1);
        rs1 += __shfl_xor_sync(0xffffffff, rs1, 2);
        l0 = l0 * a0 + rs0;
        l1 = l1 * a1 + rs1;
        m0 = mn0; m1 = mn1;

        #pragma unroll
        for (int j = 0; j < 8; j++) {
            o[j][0] *= a0; o[j][1] *= a0;
            o[j][2] *= a1; o[j][3] *= a1;
        }

        // ---- O += P V ----
        const int mi = lane >> 3, li = lane & 7;
        #pragma unroll
        for (int c16 = 0; c16 < 4; c16++) {
            uint32_t aH[4] = { pH01[2*c16], pH23[2*c16], pH01[2*c16+1], pH23[2*c16+1] };
            #pragma unroll
            for (int dj = 0; dj < 4; dj++) {
                int row = c16*16 + ((mi >> 1) ? 8 : 0) + li;
                int ch  = dj*2 + (mi & 1);
                uint32_t off = row*128 + ((ch ^ (row & 7)) * 16);
                uint32_t t0[4];
                ldsm_x4_t(t0, vB + off);
                uint32_t v0[2] = { t0[0], t0[2] }, v1[2] = { t0[1], t0[3] };
                mma_fp16(o[dj*2],   aH, v0);
                mma_fp16(o[dj*2+1], aH, v1);
            }
        }
        __syncthreads();   // compute done before next prefetch overwrites buffer
    }

    // ---- normalize + split-write output (bf16 hi/lo for O-proj GEMM) ----
    const float i0 = 1.f / l0, i1 = 1.f / l1;
    const size_t r0g = grow0 + wid*16 + (lane >> 2);
    #pragma unroll
    for (int j = 0; j < 8; j++) {
        const int n = colb + j*8 + tig*2;
        float v00 = o[j][0] * i0, v01 = o[j][1] * i0;
        float v10 = o[j][2] * i1, v11 = o[j][3] * i1;
        __nv_bfloat16 h00 = __float2bfloat16_rn(v00);
        __nv_bfloat16 h01 = __float2bfloat16_rn(v01);
        __nv_bfloat16 h10 = __float2bfloat16_rn(v10);
        __nv_bfloat16 h11 = __float2bfloat16_rn(v11);
        *(__nv_bfloat162*)(ohi + r0g*EE + n)     = __nv_bfloat162(h00, h01);
        *(__nv_bfloat162*)(ohi + (r0g+8)*EE + n) = __nv_bfloat162(h10, h11);
        *(__nv_bfloat162*)(olo + r0g*EE + n)     = __nv_bfloat162(
            __float2bfloat16_rn(v00 - __bfloat162float(h00)),
            __float2bfloat16_rn(v01 - __bfloat162float(h01)));
        *(__nv_bfloat162*)(olo + (r0g+8)*EE + n) = __nv_bfloat162(
            __float2bfloat16_rn(v10 - __bfloat162float(h10)),
            __float2bfloat16_rn(v11 - __bfloat162float(h11)));
    }
}

// ---------------- launch ----------------------------------------------------
extern "C" void kernel_launch(void* const* d_in, const int* in_sizes, int n_in,
                              void* d_out, int out_size) {
    const float* x  = (const float*)d_in[0];
    const float* Wq = (const float*)d_in[1];
    const float* Wk = (const float*)d_in[2];
    const float* Wv = (const float*)d_in[3];
    const float* Wo = (const float*)d_in[4];
    const float* bo = (const float*)d_in[5];
    float* out = (float*)d_out;

    __half *p_rxh, *p_xh, *p_qh, *p_kh, *p_vh;
    __half *p_wqhi, *p_wqlo, *p_wkhi, *p_wklo, *p_wvhi, *p_wvlo;
    __nv_bfloat16 *p_athi, *p_atlo, *p_wohi, *p_wolo;
    cudaGetSymbolAddress((void**)&p_rxh,  g_rxh);
    cudaGetSymbolAddress((void**)&p_xh,   g_xh);
    cudaGetSymbolAddress((void**)&p_qh,   g_qh);
    cudaGetSymbolAddress((void**)&p_kh,   g_kh);
    cudaGetSymbolAddress((void**)&p_vh,   g_vh);
    cudaGetSymbolAddress((void**)&p_athi, g_athi);
    cudaGetSymbolAddress((void**)&p_atlo, g_atlo);
    cudaGetSymbolAddress((void**)&p_wqhi, g_wqhi);
    cudaGetSymbolAddress((void**)&p_wqlo, g_wqlo);
    cudaGetSymbolAddress((void**)&p_wkhi, g_wkhi);
    cudaGetSymbolAddress((void**)&p_wklo, g_wklo);
    cudaGetSymbolAddress((void**)&p_wvhi, g_wvhi);
    cudaGetSymbolAddress((void**)&p_wvlo, g_wvlo);
    cudaGetSymbolAddress((void**)&p_wohi, g_wohi);
    cudaGetSymbolAddress((void**)&p_wolo, g_wolo);

    cudaFuncSetAttribute(hmma_gemm16_kernel,
                         cudaFuncAttributeMaxDynamicSharedMemorySize, GEMM16_SMEM);
    cudaFuncSetAttribute(hmma_gemm_out_kernel,
                         cudaFuncAttributeMaxDynamicSharedMemorySize, GEMM_SMEM);
    cudaFuncSetAttribute(flash_hmma_kernel,
                         cudaFuncAttributeMaxDynamicSharedMemorySize, FL_SMEM);

    theta_kernel<<<2, 256>>>();
    rope_fused_kernel<<<(MM*E2 + 255)/256, 256>>>(x);
    split16_kernel<<<(EE*EE + 255)/256, 256>>>(Wq, p_wqhi, p_wqlo, EE*EE);
    split16_kernel<<<(EE*EE + 255)/256, 256>>>(Wk, p_wkhi, p_wklo, EE*EE);
    split16_kernel<<<(EE*EE + 255)/256, 256>>>(Wv, p_wvhi, p_wvlo, EE*EE);
    split_kernel<<<(EE*EE + 255)/256, 256>>>(Wo, p_wohi, p_wolo, EE*EE);

    dim3 mgrid(EE/128, MM/128);   // (8, 64)
    hmma_gemm16_kernel<<<mgrid, 256, GEMM16_SMEM>>>(p_rxh, p_wqhi, p_wqlo, p_qh);
    hmma_gemm16_kernel<<<mgrid, 256, GEMM16_SMEM>>>(p_rxh, p_wkhi, p_wklo, p_kh);
    hmma_gemm16_kernel<<<mgrid, 256, GEMM16_SMEM>>>(p_xh,  p_wvhi, p_wvlo, p_vh);

    dim3 fgrid(TT/128, BB*HH);    // (16, 64)
    flash_hmma_kernel<<<fgrid, 256, FL_SMEM>>>(p_qh, p_kh, p_vh, p_athi, p_atlo);

    hmma_gemm_out_kernel<<<mgrid, 256, GEMM_SMEM>>>(p_athi, p_atlo, p_wohi, p_wolo,
                                                    out, bo);
}

// round 9
// speedup vs baseline: 4.8704x; 1.0939x over previous
#include <cuda_runtime.h>
#include <cuda_fp16.h>
#include <math.h>
#include <stdint.h>

// Problem constants
#define BB 4
#define TT 2048
#define EE 1024
#define HH 16
#define HD 64
#define MM (BB*TT)          // 8192 rows
#define E2 (EE/2)           // 512 pairs
#define GK 1024

// ---------------- scratch (device globals; no allocation allowed) ----------
__device__ float g_theta[E2];

__device__ __align__(256) __half g_rxh [MM*EE];   // RoPE(x), fp16
__device__ __align__(256) __half g_xh  [MM*EE];   // x, fp16
__device__ __align__(256) __half g_qh  [MM*EE];   // Q fp16
__device__ __align__(256) __half g_kh  [MM*EE];   // K fp16
__device__ __align__(256) __half g_vh  [MM*EE];   // V fp16
__device__ __align__(256) __half g_ath [MM*EE];   // attention out fp16
__device__ __align__(256) __half g_whi [4][EE*EE];  // Wq,Wk,Wv,Wo hi
__device__ __align__(256) __half g_wlo [4][EE*EE];  // Wq,Wk,Wv,Wo lo

// ================= helpers (compute_80-level PTX only!) =====================
__device__ __forceinline__ uint32_t smem_u32(const void* p) {
    uint32_t a;
    asm("{ .reg .u64 t; cvta.to.shared.u64 t, %1; cvt.u32.u64 %0, t; }"
        : "=r"(a) : "l"(p));
    return a;
}
__device__ __forceinline__ void cp16(uint32_t saddr, const void* g) {
    asm volatile("cp.async.cg.shared.global [%0], [%1], 16;"
                 :: "r"(saddr), "l"(g) : "memory");
}
#define CP_COMMIT() asm volatile("cp.async.commit_group;" ::: "memory")
#define CP_WAIT(n)  asm volatile("cp.async.wait_group %0;" :: "n"(n) : "memory")

__device__ __forceinline__ void ldsm_x4(uint32_t* r, uint32_t addr) {
    asm volatile("ldmatrix.sync.aligned.m8n8.x4.shared.b16 {%0,%1,%2,%3}, [%4];"
                 : "=r"(r[0]), "=r"(r[1]), "=r"(r[2]), "=r"(r[3]) : "r"(addr));
}
__device__ __forceinline__ void ldsm_x4_t(uint32_t* r, uint32_t addr) {
    asm volatile("ldmatrix.sync.aligned.m8n8.x4.trans.shared.b16 {%0,%1,%2,%3}, [%4];"
                 : "=r"(r[0]), "=r"(r[1]), "=r"(r[2]), "=r"(r[3]) : "r"(addr));
}
__device__ __forceinline__ void mma_fp16(float* c, const uint32_t* a,
                                         const uint32_t* b) {
    asm volatile(
        "mma.sync.aligned.m16n8k16.row.col.f32.f16.f16.f32 "
        "{%0,%1,%2,%3}, {%4,%5,%6,%7}, {%8,%9}, {%0,%1,%2,%3};"
        : "+f"(c[0]), "+f"(c[1]), "+f"(c[2]), "+f"(c[3])
        : "r"(a[0]), "r"(a[1]), "r"(a[2]), "r"(a[3]), "r"(b[0]), "r"(b[1]));
}

// ---------------- theta table ------------------------------------------------
__global__ void theta_kernel() {
    int p = blockIdx.x * blockDim.x + threadIdx.x;
    if (p >= E2) return;
    g_theta[p] = (float)exp((-(double)(2*p) / (double)EE) * log(10000.0));
}

// ---------------- fused RoPE (fp16 out) + x fp16 ------------------------------
#define P2HI 6.2831854820251465f
#define P2LO -1.7484555e-7f
#define INV2PI 0.15915494309189535f

__global__ void rope_fused_kernel(const float* __restrict__ x) {
    int idx = blockIdx.x * blockDim.x + threadIdx.x;   // over MM*E2 pairs
    if (idx >= MM*E2) return;
    int bt = idx / E2;
    int p  = idx % E2;
    int t  = bt % TT;
    float2 v = ((const float2*)x)[idx];
    float ang = (float)t * g_theta[p];      // fp32 rounding as in reference
    float n = rintf(ang * INV2PI);
    float r = fmaf(-n, P2HI, ang);
    r = fmaf(-n, P2LO, r);
    float s, c;
    sincosf(r, &s, &c);
    float rx = v.x * c - v.y * s;
    float ry = v.y * c + v.x * s;
    ((__half2*)g_rxh)[idx] = __floats2half2_rn(rx, ry);
    ((__half2*)g_xh)[idx]  = __floats2half2_rn(v.x, v.y);
}

// ---------------- all-W fp16 hi/lo split (one launch) -------------------------
__global__ void split_all_kernel(const float* __restrict__ Wq,
                                 const float* __restrict__ Wk,
                                 const float* __restrict__ Wv,
                                 const float* __restrict__ Wo) {
    int i = blockIdx.x * blockDim.x + threadIdx.x;
    if (i >= EE*EE) return;
    int w = blockIdx.y;
    const float* src = (w == 0) ? Wq : (w == 1) ? Wk : (w == 2) ? Wv : Wo;
    float x = src[i];
    __half h = __float2half_rn(x);
    g_whi[w][i] = h;
    g_wlo[w][i] = __float2half_rn(x - __half2float(h));
}

// ---------------- 2-term fp16 NT GEMM: C = A*(Wh+Wl) -------------------------
// OUT: 0 = fp16 out, 1 = fp32 out + bias.
#define KSTEPS (GK/64)          // 16
#define TILE_B 16384            // 128 rows x 128 bytes
#define STG16_B (3*TILE_B)      // A|Wh|Wl = 48 KB
#define NSTG 3
#define GEMM16_SMEM (NSTG*STG16_B)   // 144 KB

template<int OUT>
__global__ __launch_bounds__(256)
void hmma_gemm16_kernel(const __half* __restrict__ A,
                        const __half* __restrict__ Whi,
                        const __half* __restrict__ Wlo,
                        void* __restrict__ Cout,
                        const float* __restrict__ bias) {
    extern __shared__ char sm[];
    const int tid  = threadIdx.x;
    const int wid  = tid >> 5;
    const int lane = tid & 31;
    const int row0 = blockIdx.y * 128;
    const int col0 = blockIdx.x * 128;
    const uint32_t sbase = smem_u32(sm);
    const int wm = wid >> 2;
    const int wn = wid & 3;

    float acc[4][4][4] = {};
    const __half* srcs[3] = { A, Whi, Wlo };

    auto load_stage = [&](int s, int ks) {
        const int k0 = ks * 64;
        const uint32_t st = sbase + s * STG16_B;
        #pragma unroll
        for (int t = 0; t < 3; t++) {
            const int rb = (t == 0) ? row0 : col0;
            #pragma unroll
            for (int it = 0; it < 4; it++) {
                int u = tid + 256 * it;
                int r = u >> 3, c = u & 7;
                const __half* g = srcs[t] + (size_t)(rb + r) * GK + k0 + c * 8;
                uint32_t sa = st + t * TILE_B + r * 128 + ((c ^ (r & 7)) * 16);
                cp16(sa, g);
            }
        }
    };

    load_stage(0, 0); CP_COMMIT();
    load_stage(1, 1); CP_COMMIT();

    for (int ks = 0; ks < KSTEPS; ks++) {
        CP_WAIT(1);
        __syncthreads();
        if (ks + 2 < KSTEPS) load_stage((ks + 2) % NSTG, ks + 2);
        CP_COMMIT();

        const uint32_t st = sbase + (ks % NSTG) * STG16_B;
        const uint32_t aB = st;
        const uint32_t whB = st + TILE_B, wlB = st + 2*TILE_B;
        const int lr = lane & 15, lc = lane >> 4;

        #pragma unroll
        for (int k16 = 0; k16 < 4; k16++) {
            uint32_t a[4][4], wh[4][2], wl[4][2];
            #pragma unroll
            for (int i = 0; i < 4; i++) {
                int row = wm*64 + i*16 + lr;
                int c = k16*2 + lc;
                uint32_t off = row*128 + ((c ^ (row & 7)) * 16);
                ldsm_x4(a[i], aB + off);
            }
            #pragma unroll
            for (int jj = 0; jj < 2; jj++) {
                int row = wn*32 + jj*16 + lr;
                int c = k16*2 + lc;
                uint32_t off = row*128 + ((c ^ (row & 7)) * 16);
                uint32_t t0[4], t1[4];
                ldsm_x4(t0, whB + off);
                wh[jj*2][0] = t0[0]; wh[jj*2][1] = t0[2];
                wh[jj*2+1][0] = t0[1]; wh[jj*2+1][1] = t0[3];
                ldsm_x4(t1, wlB + off);
                wl[jj*2][0] = t1[0]; wl[jj*2][1] = t1[2];
                wl[jj*2+1][0] = t1[1]; wl[jj*2+1][1] = t1[3];
            }
            #pragma unroll
            for (int i = 0; i < 4; i++)
                #pragma unroll
                for (int j = 0; j < 4; j++) {
                    mma_fp16(acc[i][j], a[i], wh[j]);
                    mma_fp16(acc[i][j], a[i], wl[j]);
                }
        }
    }

    const int gq = lane >> 2, tig = lane & 3;
    #pragma unroll
    for (int j = 0; j < 4; j++) {
        const int n = col0 + wn*32 + j*8 + tig*2;
        float b0 = 0.f, b1 = 0.f;
        if (OUT == 1) { b0 = bias[n]; b1 = bias[n+1]; }
        #pragma unroll
        for (int i = 0; i < 4; i++) {
            const int m0 = row0 + wm*64 + i*16 + gq;
            if (OUT == 0) {
                __half* C = (__half*)Cout;
                *(__half2*)(C + (size_t)m0*GK + n) =
                    __floats2half2_rn(acc[i][j][0], acc[i][j][1]);
                *(__half2*)(C + (size_t)(m0+8)*GK + n) =
                    __floats2half2_rn(acc[i][j][2], acc[i][j][3]);
            } else {
                float* C = (float*)Cout;
                *(float2*)(C + (size_t)m0 * GK + n) =
                    make_float2(acc[i][j][0] + b0, acc[i][j][1] + b1);
                *(float2*)(C + (size_t)(m0 + 8) * GK + n) =
                    make_float2(acc[i][j][2] + b0, acc[i][j][3] + b1);
            }
        }
    }
}

// ---------------- HMMA flash attention (causal, fp16, 3-stage) ---------------
// Br=128 (8 warps x 16 rows), Bc=64, d=64. QK 1 MMA, PV 1 MMA.
#define FL_QB   16384                  // 128 rows x 128B Q tile (fp16)
#define FL_TB   8192                   // 64 rows x 128B per K/V tile
#define FL_STG  (2*FL_TB)              // K|V = 16 KB
#define FL_NSTG 3
#define FL_SMEM (FL_QB + FL_NSTG*FL_STG)   // 64 KB

__global__ __launch_bounds__(256, 2)
void flash_hmma_kernel(const __half* __restrict__ qh,
                       const __half* __restrict__ kh,
                       const __half* __restrict__ vh,
                       __half* __restrict__ oh) {
    extern __shared__ char sm[];
    const int tid  = threadIdx.x;
    const int wid  = tid >> 5;
    const int lane = tid & 31;
    const int qt = (int)(gridDim.x - 1 - blockIdx.x);   // heavy tiles first
    const int bh = blockIdx.y;
    const int b = bh >> 4, h = bh & 15;
    const int qrow0 = qt * 128;
    const size_t grow0 = (size_t)b * TT + qrow0;
    const int colb = h * HD;

    const uint32_t sb  = smem_u32(sm);
    const uint32_t qB  = sb;
    const uint32_t stB = sb + FL_QB;

    // ---- load Q tile ----
    #pragma unroll
    for (int it = 0; it < 4; it++) {
        int u = tid + 256 * it;          // 0..1023
        int r = u >> 3, c = u & 7;
        cp16(qB + r*128 + ((c ^ (r & 7)) * 16),
             qh + (grow0 + r) * EE + colb + c * 8);
    }
    const __half* ksrc[2] = { kh, vh };
    auto load_stage = [&](int s, int kt) {
        const size_t krow = (size_t)b * TT + kt * 64;
        const uint32_t st = stB + s * FL_STG;
        #pragma unroll
        for (int t = 0; t < 2; t++) {
            #pragma unroll
            for (int it = 0; it < 2; it++) {
                int u = tid + 256 * it;          // 0..511
                int r = u >> 3, c = u & 7;
                cp16(st + t*FL_TB + r*128 + ((c ^ (r & 7)) * 16),
                     ksrc[t] + (krow + r) * EE + colb + c * 8);
            }
        }
    };
    const int nkv = 2*qt + 2;
    load_stage(0, 0); CP_COMMIT();
    if (1 < nkv) load_stage(1, 1);
    CP_COMMIT();

    // ---- Q fragments (first stage must be complete before ldsm on Q) ----
    CP_WAIT(1);
    __syncthreads();
    uint32_t qf[4][4];
    const int lr = lane & 15, lc = lane >> 4;
    #pragma unroll
    for (int k16 = 0; k16 < 4; k16++) {
        int row = wid*16 + lr;
        int c = k16*2 + lc;
        uint32_t off = row*128 + ((c ^ (row & 7)) * 16);
        ldsm_x4(qf[k16], qB + off);
    }

    float m0 = -INFINITY, m1 = -INFINITY, l0 = 0.f, l1 = 0.f;
    float o[8][4] = {};
    const int rg0 = qrow0 + wid*16 + (lane >> 2);
    const int tig = lane & 3;

    for (int kt = 0; kt < nkv; kt++) {
        if (kt > 0) {               // kt==0 already waited above
            CP_WAIT(1);
            __syncthreads();
        }
        if (kt + 2 < nkv) load_stage((kt + 2) % FL_NSTG, kt + 2);
        CP_COMMIT();

        const uint32_t st = stB + (kt % FL_NSTG) * FL_STG;
        const uint32_t kB = st, vB = st + FL_TB;

        // ---- S = Q K^T ----
        float s[8][4] = {};
        #pragma unroll
        for (int k16 = 0; k16 < 4; k16++) {
            uint32_t kf[8][2];
            #pragma unroll
            for (int jj = 0; jj < 4; jj++) {
                int row = jj*16 + lr;
                int c = k16*2 + lc;
                uint32_t off = row*128 + ((c ^ (row & 7)) * 16);
                uint32_t t0[4];
                ldsm_x4(t0, kB + off);
                kf[jj*2][0] = t0[0]; kf[jj*2][1] = t0[2];
                kf[jj*2+1][0] = t0[1]; kf[jj*2+1][1] = t0[3];
            }
            #pragma unroll
            for (int j = 0; j < 8; j++)
                mma_fp16(s[j], qf[k16], kf[j]);
        }

        // ---- scale + causal mask ----
        const bool maskt = (kt >= 2*qt);
        #pragma unroll
        for (int j = 0; j < 8; j++) {
            s[j][0] *= 0.125f; s[j][1] *= 0.125f;
            s[j][2] *= 0.125f; s[j][3] *= 0.125f;
            if (maskt) {
                int c0 = kt*64 + j*8 + tig*2;
                if (c0     > rg0)     s[j][0] = -INFINITY;
                if (c0 + 1 > rg0)     s[j][1] = -INFINITY;
                if (c0     > rg0 + 8) s[j][2] = -INFINITY;
                if (c0 + 1 > rg0 + 8) s[j][3] = -INFINITY;
            }
        }

        // ---- online softmax; P fp16 consistent-rounded ----
        float tm0 = -INFINITY, tm1 = -INFINITY;
        #pragma unroll
        for (int j = 0; j < 8; j++) {
            tm0 = fmaxf(tm0, fmaxf(s[j][0], s[j][1]));
            tm1 = fmaxf(tm1, fmaxf(s[j][2], s[j][3]));
        }
        tm0 = fmaxf(tm0, __shfl_xor_sync(0xffffffff, tm0, 1));
        tm0 = fmaxf(tm0, __shfl_xor_sync(0xffffffff, tm0, 2));
        tm1 = fmaxf(tm1, __shfl_xor_sync(0xffffffff, tm1, 1));
        tm1 = fmaxf(tm1, __shfl_xor_sync(0xffffffff, tm1, 2));
        float mn0 = fmaxf(m0, tm0), mn1 = fmaxf(m1, tm1);
        float a0 = __expf(m0 - mn0), a1 = __expf(m1 - mn1);

        uint32_t pH01[8], pH23[8];
        float rs0 = 0.f, rs1 = 0.f;
        #pragma unroll
        for (int j = 0; j < 8; j++) {
            __half h0 = __float2half_rn(__expf(s[j][0] - mn0));
            __half h1 = __float2half_rn(__expf(s[j][1] - mn0));
            __half h2 = __float2half_rn(__expf(s[j][2] - mn1));
            __half h3 = __float2half_rn(__expf(s[j][3] - mn1));
            rs0 += __half2float(h0) + __half2float(h1);
            rs1 += __half2float(h2) + __half2float(h3);
            pH01[j] = ((uint32_t)*(uint16_t*)&h1 << 16) | *(uint16_t*)&h0;
            pH23[j] = ((uint32_t)*(uint16_t*)&h3 << 16) | *(uint16_t*)&h2;
        }
        rs0 += __shfl_xor_sync(0xffffffff, rs0, 1);
        rs0 += __shfl_xor_sync(0xffffffff, rs0, 2);
        rs1 += __shfl_xor_sync(0xffffffff, rs1, 1);
        rs1 += __shfl_xor_sync(0xffffffff, rs1, 2);
        l0 = l0 * a0 + rs0;
        l1 = l1 * a1 + rs1;
        m0 = mn0; m1 = mn1;

        #pragma unroll
        for (int j = 0; j < 8; j++) {
            o[j][0] *= a0; o[j][1] *= a0;
            o[j][2] *= a1; o[j][3] *= a1;
        }

        // ---- O += P V ----
        const int mi = lane >> 3, li = lane & 7;
        #pragma unroll
        for (int c16 = 0; c16 < 4; c16++) {
            uint32_t aH[4] = { pH01[2*c16], pH23[2*c16], pH01[2*c16+1], pH23[2*c16+1] };
            #pragma unroll
            for (int dj = 0; dj < 4; dj++) {
                int row = c16*16 + ((mi >> 1) ? 8 : 0) + li;
                int ch  = dj*2 + (mi & 1);
                uint32_t off = row*128 + ((ch ^ (row & 7)) * 16);
                uint32_t t0[4];
                ldsm_x4_t(t0, vB + off);
                uint32_t v0[2] = { t0[0], t0[2] }, v1[2] = { t0[1], t0[3] };
                mma_fp16(o[dj*2],   aH, v0);
                mma_fp16(o[dj*2+1], aH, v1);
            }
        }
        // NOTE: no bottom barrier needed — the stage written by the load
        // issued at iter kt+1 ((kt+3)%3 == kt%3) is protected by kt+1's
        // top __syncthreads, which orders all warps past iter kt's reads.
    }

    // ---- normalize + fp16 output ----
    const float i0 = 1.f / l0, i1 = 1.f / l1;
    const size_t r0g = grow0 + wid*16 + (lane >> 2);
    #pragma unroll
    for (int j = 0; j < 8; j++) {
        const int n = colb + j*8 + tig*2;
        *(__half2*)(oh + r0g*EE + n)     = __floats2half2_rn(o[j][0]*i0, o[j][1]*i0);
        *(__half2*)(oh + (r0g+8)*EE + n) = __floats2half2_rn(o[j][2]*i1, o[j][3]*i1);
    }
}

// ---------------- launch ----------------------------------------------------
extern "C" void kernel_launch(void* const* d_in, const int* in_sizes, int n_in,
                              void* d_out, int out_size) {
    const float* x  = (const float*)d_in[0];
    const float* Wq = (const float*)d_in[1];
    const float* Wk = (const float*)d_in[2];
    const float* Wv = (const float*)d_in[3];
    const float* Wo = (const float*)d_in[4];
    const float* bo = (const float*)d_in[5];
    float* out = (float*)d_out;

    __half *p_rxh, *p_xh, *p_qh, *p_kh, *p_vh, *p_ath, *p_whi, *p_wlo;
    cudaGetSymbolAddress((void**)&p_rxh, g_rxh);
    cudaGetSymbolAddress((void**)&p_xh,  g_xh);
    cudaGetSymbolAddress((void**)&p_qh,  g_qh);
    cudaGetSymbolAddress((void**)&p_kh,  g_kh);
    cudaGetSymbolAddress((void**)&p_vh,  g_vh);
    cudaGetSymbolAddress((void**)&p_ath, g_ath);
    cudaGetSymbolAddress((void**)&p_whi, g_whi);
    cudaGetSymbolAddress((void**)&p_wlo, g_wlo);

    cudaFuncSetAttribute(hmma_gemm16_kernel<0>,
                         cudaFuncAttributeMaxDynamicSharedMemorySize, GEMM16_SMEM);
    cudaFuncSetAttribute(hmma_gemm16_kernel<1>,
                         cudaFuncAttributeMaxDynamicSharedMemorySize, GEMM16_SMEM);
    cudaFuncSetAttribute(flash_hmma_kernel,
                         cudaFuncAttributeMaxDynamicSharedMemorySize, FL_SMEM);

    theta_kernel<<<2, 256>>>();
    rope_fused_kernel<<<(MM*E2 + 255)/256, 256>>>(x);
    dim3 sgrid((EE*EE + 255)/256, 4);
    split_all_kernel<<<sgrid, 256>>>(Wq, Wk, Wv, Wo);

    dim3 mgrid(EE/128, MM/128);   // (8, 64)
    hmma_gemm16_kernel<0><<<mgrid, 256, GEMM16_SMEM>>>(
        p_rxh, p_whi + 0*(size_t)EE*EE, p_wlo + 0*(size_t)EE*EE, p_qh, nullptr);
    hmma_gemm16_kernel<0><<<mgrid, 256, GEMM16_SMEM>>>(
        p_rxh, p_whi + 1*(size_t)EE*EE, p_wlo + 1*(size_t)EE*EE, p_kh, nullptr);
    hmma_gemm16_kernel<0><<<mgrid, 256, GEMM16_SMEM>>>(
        p_xh,  p_whi + 2*(size_t)EE*EE, p_wlo + 2*(size_t)EE*EE, p_vh, nullptr);

    dim3 fgrid(TT/128, BB*HH);    // (16, 64)
    flash_hmma_kernel<<<fgrid, 256, FL_SMEM>>>(p_qh, p_kh, p_vh, p_ath);

    hmma_gemm16_kernel<1><<<mgrid, 256, GEMM16_SMEM>>>(
        p_ath, p_whi + 3*(size_t)EE*EE, p_wlo + 3*(size_t)EE*EE, out, bo);
}

// round 10
// speedup vs baseline: 5.4074x; 1.1102x over previous
#include <cuda_runtime.h>
#include <cuda_fp16.h>
#include <math.h>
#include <stdint.h>

// Problem constants
#define BB 4
#define TT 2048
#define EE 1024
#define HH 16
#define HD 64
#define MM (BB*TT)          // 8192 rows
#define E2 (EE/2)           // 512 pairs
#define GK 1024

// ---------------- scratch (device globals; no allocation allowed) ----------
__device__ float g_theta[E2];

__device__ __align__(256) __half g_rxh [MM*EE];   // RoPE(x), fp16
__device__ __align__(256) __half g_xh  [MM*EE];   // x, fp16
__device__ __align__(256) __half g_qh  [MM*EE];   // Q fp16
__device__ __align__(256) __half g_kh  [MM*EE];   // K fp16
__device__ __align__(256) __half g_vh  [MM*EE];   // V fp16
__device__ __align__(256) __half g_ath [MM*EE];   // attention out fp16
__device__ __align__(256) __half g_whi [4][EE*EE];  // Wq,Wk,Wv,Wo hi
__device__ __align__(256) __half g_wlo [4][EE*EE];  // Wq,Wk,Wv,Wo lo

// ================= helpers (compute_80-level PTX only!) =====================
__device__ __forceinline__ uint32_t smem_u32(const void* p) {
    uint32_t a;
    asm("{ .reg .u64 t; cvta.to.shared.u64 t, %1; cvt.u32.u64 %0, t; }"
        : "=r"(a) : "l"(p));
    return a;
}
__device__ __forceinline__ void cp16(uint32_t saddr, const void* g) {
    asm volatile("cp.async.cg.shared.global [%0], [%1], 16;"
                 :: "r"(saddr), "l"(g) : "memory");
}
#define CP_COMMIT() asm volatile("cp.async.commit_group;" ::: "memory")
#define CP_WAIT(n)  asm volatile("cp.async.wait_group %0;" :: "n"(n) : "memory")

__device__ __forceinline__ void ldsm_x4(uint32_t* r, uint32_t addr) {
    asm volatile("ldmatrix.sync.aligned.m8n8.x4.shared.b16 {%0,%1,%2,%3}, [%4];"
                 : "=r"(r[0]), "=r"(r[1]), "=r"(r[2]), "=r"(r[3]) : "r"(addr));
}
__device__ __forceinline__ void ldsm_x4_t(uint32_t* r, uint32_t addr) {
    asm volatile("ldmatrix.sync.aligned.m8n8.x4.trans.shared.b16 {%0,%1,%2,%3}, [%4];"
                 : "=r"(r[0]), "=r"(r[1]), "=r"(r[2]), "=r"(r[3]) : "r"(addr));
}
__device__ __forceinline__ void mma_fp16(float* c, const uint32_t* a,
                                         const uint32_t* b) {
    asm volatile(
        "mma.sync.aligned.m16n8k16.row.col.f32.f16.f16.f32 "
        "{%0,%1,%2,%3}, {%4,%5,%6,%7}, {%8,%9}, {%0,%1,%2,%3};"
        : "+f"(c[0]), "+f"(c[1]), "+f"(c[2]), "+f"(c[3])
        : "r"(a[0]), "r"(a[1]), "r"(a[2]), "r"(a[3]), "r"(b[0]), "r"(b[1]));
}

// ---------------- theta table ------------------------------------------------
__global__ void theta_kernel() {
    int p = blockIdx.x * blockDim.x + threadIdx.x;
    if (p >= E2) return;
    g_theta[p] = (float)exp((-(double)(2*p) / (double)EE) * log(10000.0));
}

// ---------------- fused RoPE (fp16 out) + x fp16 ------------------------------
#define P2HI 6.2831854820251465f
#define P2LO -1.7484555e-7f
#define INV2PI 0.15915494309189535f

__global__ void rope_fused_kernel(const float* __restrict__ x) {
    int idx = blockIdx.x * blockDim.x + threadIdx.x;   // over MM*E2 pairs
    if (idx >= MM*E2) return;
    int bt = idx / E2;
    int p  = idx % E2;
    int t  = bt % TT;
    float2 v = ((const float2*)x)[idx];
    float ang = (float)t * g_theta[p];      // fp32 rounding as in reference
    float n = rintf(ang * INV2PI);
    float r = fmaf(-n, P2HI, ang);
    r = fmaf(-n, P2LO, r);
    float s, c;
    sincosf(r, &s, &c);
    float rx = v.x * c - v.y * s;
    float ry = v.y * c + v.x * s;
    ((__half2*)g_rxh)[idx] = __floats2half2_rn(rx, ry);
    ((__half2*)g_xh)[idx]  = __floats2half2_rn(v.x, v.y);
}

// ---------------- all-W fp16 hi/lo split (one launch) -------------------------
__global__ void split_all_kernel(const float* __restrict__ Wq,
                                 const float* __restrict__ Wk,
                                 const float* __restrict__ Wv,
                                 const float* __restrict__ Wo) {
    int i = blockIdx.x * blockDim.x + threadIdx.x;
    if (i >= EE*EE) return;
    int w = blockIdx.y;
    const float* src = (w == 0) ? Wq : (w == 1) ? Wk : (w == 2) ? Wv : Wo;
    float x = src[i];
    __half h = __float2half_rn(x);
    g_whi[w][i] = h;
    g_wlo[w][i] = __float2half_rn(x - __half2float(h));
}

// ---------------- 2-term fp16 NT GEMM, 2-stage, 2 CTAs/SM --------------------
// OUT: 0 = fp16 out (fused QKV via blockIdx.z), 1 = fp32 out + bias.
#define KSTEPS (GK/64)          // 16
#define TILE_B 16384            // 128 rows x 128 bytes
#define STG16_B (3*TILE_B)      // A|Wh|Wl = 48 KB
#define NSTG 2
#define GEMM16_SMEM (NSTG*STG16_B)   // 96 KB -> 2 CTAs/SM

template<int OUT>
__global__ __launch_bounds__(256, 2)
void hmma_gemm16_kernel(const __half* __restrict__ A0,
                        const __half* __restrict__ A2,   // A for z==2 (V uses x)
                        const __half* __restrict__ Whi0,
                        const __half* __restrict__ Wlo0,
                        __half* __restrict__ C16_0,
                        __half* __restrict__ C16_1,
                        __half* __restrict__ C16_2,
                        float* __restrict__ C32,
                        const float* __restrict__ bias) {
    extern __shared__ char sm[];
    const int tid  = threadIdx.x;
    const int wid  = tid >> 5;
    const int lane = tid & 31;
    const int row0 = blockIdx.y * 128;
    const int col0 = blockIdx.x * 128;
    const int z    = blockIdx.z;
    const uint32_t sbase = smem_u32(sm);
    const int wm = wid >> 2;
    const int wn = wid & 3;

    const __half* A   = (OUT == 0 && z == 2) ? A2 : A0;
    const __half* Whi = Whi0 + (size_t)z * EE * EE;
    const __half* Wlo = Wlo0 + (size_t)z * EE * EE;
    __half* C16 = (OUT == 0) ? ((z == 0) ? C16_0 : (z == 1) ? C16_1 : C16_2)
                             : nullptr;

    float acc[4][4][4] = {};
    const __half* srcs[3] = { A, Whi, Wlo };

    auto load_stage = [&](int s, int ks) {
        const int k0 = ks * 64;
        const uint32_t st = sbase + s * STG16_B;
        #pragma unroll
        for (int t = 0; t < 3; t++) {
            const int rb = (t == 0) ? row0 : col0;
            #pragma unroll
            for (int it = 0; it < 4; it++) {
                int u = tid + 256 * it;
                int r = u >> 3, c = u & 7;
                const __half* g = srcs[t] + (size_t)(rb + r) * GK + k0 + c * 8;
                uint32_t sa = st + t * TILE_B + r * 128 + ((c ^ (r & 7)) * 16);
                cp16(sa, g);
            }
        }
    };

    load_stage(0, 0); CP_COMMIT();
    load_stage(1, 1); CP_COMMIT();

    for (int ks = 0; ks < KSTEPS; ks++) {
        CP_WAIT(1);
        __syncthreads();

        const uint32_t st = sbase + (ks & 1) * STG16_B;
        const uint32_t aB = st;
        const uint32_t whB = st + TILE_B, wlB = st + 2*TILE_B;
        const int lr = lane & 15, lc = lane >> 4;

        #pragma unroll
        for (int k16 = 0; k16 < 4; k16++) {
            uint32_t a[4][4], wh[4][2], wl[4][2];
            #pragma unroll
            for (int i = 0; i < 4; i++) {
                int row = wm*64 + i*16 + lr;
                int c = k16*2 + lc;
                uint32_t off = row*128 + ((c ^ (row & 7)) * 16);
                ldsm_x4(a[i], aB + off);
            }
            #pragma unroll
            for (int jj = 0; jj < 2; jj++) {
                int row = wn*32 + jj*16 + lr;
                int c = k16*2 + lc;
                uint32_t off = row*128 + ((c ^ (row & 7)) * 16);
                uint32_t t0[4], t1[4];
                ldsm_x4(t0, whB + off);
                wh[jj*2][0] = t0[0]; wh[jj*2][1] = t0[2];
                wh[jj*2+1][0] = t0[1]; wh[jj*2+1][1] = t0[3];
                ldsm_x4(t1, wlB + off);
                wl[jj*2][0] = t1[0]; wl[jj*2][1] = t1[2];
                wl[jj*2+1][0] = t1[1]; wl[jj*2+1][1] = t1[3];
            }
            #pragma unroll
            for (int i = 0; i < 4; i++)
                #pragma unroll
                for (int j = 0; j < 4; j++) {
                    mma_fp16(acc[i][j], a[i], wh[j]);
                    mma_fp16(acc[i][j], a[i], wl[j]);
                }
        }

        __syncthreads();                 // all reads of stage ks&1 done
        if (ks + 2 < KSTEPS) load_stage(ks & 1, ks + 2);
        CP_COMMIT();                     // commit (possibly empty) to keep count
    }

    const int gq = lane >> 2, tig = lane & 3;
    #pragma unroll
    for (int j = 0; j < 4; j++) {
        const int n = col0 + wn*32 + j*8 + tig*2;
        float b0 = 0.f, b1 = 0.f;
        if (OUT == 1) { b0 = bias[n]; b1 = bias[n+1]; }
        #pragma unroll
        for (int i = 0; i < 4; i++) {
            const int m0 = row0 + wm*64 + i*16 + gq;
            if (OUT == 0) {
                *(__half2*)(C16 + (size_t)m0*GK + n) =
                    __floats2half2_rn(acc[i][j][0], acc[i][j][1]);
                *(__half2*)(C16 + (size_t)(m0+8)*GK + n) =
                    __floats2half2_rn(acc[i][j][2], acc[i][j][3]);
            } else {
                *(float2*)(C32 + (size_t)m0 * GK + n) =
                    make_float2(acc[i][j][0] + b0, acc[i][j][1] + b1);
                *(float2*)(C32 + (size_t)(m0 + 8) * GK + n) =
                    make_float2(acc[i][j][2] + b0, acc[i][j][3] + b1);
            }
        }
    }
}

// ---------------- HMMA flash attention (causal, fp16, 3-stage) ---------------
// Br=128 (8 warps x 16 rows), Bc=64, d=64. QK 1 MMA, PV 1 MMA.
#define FL_QB   16384                  // 128 rows x 128B Q tile (fp16)
#define FL_TB   8192                   // 64 rows x 128B per K/V tile
#define FL_STG  (2*FL_TB)              // K|V = 16 KB
#define FL_NSTG 3
#define FL_SMEM (FL_QB + FL_NSTG*FL_STG)   // 64 KB

__global__ __launch_bounds__(256, 2)
void flash_hmma_kernel(const __half* __restrict__ qh,
                       const __half* __restrict__ kh,
                       const __half* __restrict__ vh,
                       __half* __restrict__ oh) {
    extern __shared__ char sm[];
    const int tid  = threadIdx.x;
    const int wid  = tid >> 5;
    const int lane = tid & 31;
    const int qt = (int)(gridDim.x - 1 - blockIdx.x);   // heavy tiles first
    const int bh = blockIdx.y;
    const int b = bh >> 4, h = bh & 15;
    const int qrow0 = qt * 128;
    const size_t grow0 = (size_t)b * TT + qrow0;
    const int colb = h * HD;

    const uint32_t sb  = smem_u32(sm);
    const uint32_t qB  = sb;
    const uint32_t stB = sb + FL_QB;

    // ---- load Q tile ----
    #pragma unroll
    for (int it = 0; it < 4; it++) {
        int u = tid + 256 * it;          // 0..1023
        int r = u >> 3, c = u & 7;
        cp16(qB + r*128 + ((c ^ (r & 7)) * 16),
             qh + (grow0 + r) * EE + colb + c * 8);
    }
    const __half* ksrc[2] = { kh, vh };
    auto load_stage = [&](int s, int kt) {
        const size_t krow = (size_t)b * TT + kt * 64;
        const uint32_t st = stB + s * FL_STG;
        #pragma unroll
        for (int t = 0; t < 2; t++) {
            #pragma unroll
            for (int it = 0; it < 2; it++) {
                int u = tid + 256 * it;          // 0..511
                int r = u >> 3, c = u & 7;
                cp16(st + t*FL_TB + r*128 + ((c ^ (r & 7)) * 16),
                     ksrc[t] + (krow + r) * EE + colb + c * 8);
            }
        }
    };
    const int nkv = 2*qt + 2;
    load_stage(0, 0); CP_COMMIT();
    if (1 < nkv) load_stage(1, 1);
    CP_COMMIT();

    // ---- Q fragments ----
    CP_WAIT(1);
    __syncthreads();
    uint32_t qf[4][4];
    const int lr = lane & 15, lc = lane >> 4;
    #pragma unroll
    for (int k16 = 0; k16 < 4; k16++) {
        int row = wid*16 + lr;
        int c = k16*2 + lc;
        uint32_t off = row*128 + ((c ^ (row & 7)) * 16);
        ldsm_x4(qf[k16], qB + off);
    }

    float m0 = -INFINITY, m1 = -INFINITY, l0 = 0.f, l1 = 0.f;
    float o[8][4] = {};
    const int rg0 = qrow0 + wid*16 + (lane >> 2);
    const int tig = lane & 3;

    for (int kt = 0; kt < nkv; kt++) {
        if (kt > 0) {
            CP_WAIT(1);
            __syncthreads();
        }
        if (kt + 2 < nkv) load_stage((kt + 2) % FL_NSTG, kt + 2);
        CP_COMMIT();

        const uint32_t st = stB + (kt % FL_NSTG) * FL_STG;
        const uint32_t kB = st, vB = st + FL_TB;

        // ---- S = Q K^T ----
        float s[8][4] = {};
        #pragma unroll
        for (int k16 = 0; k16 < 4; k16++) {
            uint32_t kf[8][2];
            #pragma unroll
            for (int jj = 0; jj < 4; jj++) {
                int row = jj*16 + lr;
                int c = k16*2 + lc;
                uint32_t off = row*128 + ((c ^ (row & 7)) * 16);
                uint32_t t0[4];
                ldsm_x4(t0, kB + off);
                kf[jj*2][0] = t0[0]; kf[jj*2][1] = t0[2];
                kf[jj*2+1][0] = t0[1]; kf[jj*2+1][1] = t0[3];
            }
            #pragma unroll
            for (int j = 0; j < 8; j++)
                mma_fp16(s[j], qf[k16], kf[j]);
        }

        // ---- scale + causal mask ----
        const bool maskt = (kt >= 2*qt);
        #pragma unroll
        for (int j = 0; j < 8; j++) {
            s[j][0] *= 0.125f; s[j][1] *= 0.125f;
            s[j][2] *= 0.125f; s[j][3] *= 0.125f;
            if (maskt) {
                int c0 = kt*64 + j*8 + tig*2;
                if (c0     > rg0)     s[j][0] = -INFINITY;
                if (c0 + 1 > rg0)     s[j][1] = -INFINITY;
                if (c0     > rg0 + 8) s[j][2] = -INFINITY;
                if (c0 + 1 > rg0 + 8) s[j][3] = -INFINITY;
            }
        }

        // ---- online softmax; P fp16 consistent-rounded ----
        float tm0 = -INFINITY, tm1 = -INFINITY;
        #pragma unroll
        for (int j = 0; j < 8; j++) {
            tm0 = fmaxf(tm0, fmaxf(s[j][0], s[j][1]));
            tm1 = fmaxf(tm1, fmaxf(s[j][2], s[j][3]));
        }
        tm0 = fmaxf(tm0, __shfl_xor_sync(0xffffffff, tm0, 1));
        tm0 = fmaxf(tm0, __shfl_xor_sync(0xffffffff, tm0, 2));
        tm1 = fmaxf(tm1, __shfl_xor_sync(0xffffffff, tm1, 1));
        tm1 = fmaxf(tm1, __shfl_xor_sync(0xffffffff, tm1, 2));
        float mn0 = fmaxf(m0, tm0), mn1 = fmaxf(m1, tm1);
        float a0 = __expf(m0 - mn0), a1 = __expf(m1 - mn1);

        uint32_t pH01[8], pH23[8];
        float rs0 = 0.f, rs1 = 0.f;
        #pragma unroll
        for (int j = 0; j < 8; j++) {
            __half h0 = __float2half_rn(__expf(s[j][0] - mn0));
            __half h1 = __float2half_rn(__expf(s[j][1] - mn0));
            __half h2 = __float2half_rn(__expf(s[j][2] - mn1));
            __half h3 = __float2half_rn(__expf(s[j][3] - mn1));
            rs0 += __half2float(h0) + __half2float(h1);
            rs1 += __half2float(h2) + __half2float(h3);
            pH01[j] = ((uint32_t)*(uint16_t*)&h1 << 16) | *(uint16_t*)&h0;
            pH23[j] = ((uint32_t)*(uint16_t*)&h3 << 16) | *(uint16_t*)&h2;
        }
        rs0 += __shfl_xor_sync(0xffffffff, rs0, 1);
        rs0 += __shfl_xor_sync(0xffffffff, rs0, 2);
        rs1 += __shfl_xor_sync(0xffffffff, rs1, 1);
        rs1 += __shfl_xor_sync(0xffffffff, rs1, 2);
        l0 = l0 * a0 + rs0;
        l1 = l1 * a1 + rs1;
        m0 = mn0; m1 = mn1;

        #pragma unroll
        for (int j = 0; j < 8; j++) {
            o[j][0] *= a0; o[j][1] *= a0;
            o[j][2] *= a1; o[j][3] *= a1;
        }

        // ---- O += P V ----
        const int mi = lane >> 3, li = lane & 7;
        #pragma unroll
        for (int c16 = 0; c16 < 4; c16++) {
            uint32_t aH[4] = { pH01[2*c16], pH23[2*c16], pH01[2*c16+1], pH23[2*c16+1] };
            #pragma unroll
            for (int dj = 0; dj < 4; dj++) {
                int row = c16*16 + ((mi >> 1) ? 8 : 0) + li;
                int ch  = dj*2 + (mi & 1);
                uint32_t off = row*128 + ((ch ^ (row & 7)) * 16);
                uint32_t t0[4];
                ldsm_x4_t(t0, vB + off);
                uint32_t v0[2] = { t0[0], t0[2] }, v1[2] = { t0[1], t0[3] };
                mma_fp16(o[dj*2],   aH, v0);
                mma_fp16(o[dj*2+1], aH, v1);
            }
        }
    }

    // ---- normalize + fp16 output ----
    const float i0 = 1.f / l0, i1 = 1.f / l1;
    const size_t r0g = grow0 + wid*16 + (lane >> 2);
    #pragma unroll
    for (int j = 0; j < 8; j++) {
        const int n = colb + j*8 + tig*2;
        *(__half2*)(oh + r0g*EE + n)     = __floats2half2_rn(o[j][0]*i0, o[j][1]*i0);
        *(__half2*)(oh + (r0g+8)*EE + n) = __floats2half2_rn(o[j][2]*i1, o[j][3]*i1);
    }
}

// ---------------- launch ----------------------------------------------------
extern "C" void kernel_launch(void* const* d_in, const int* in_sizes, int n_in,
                              void* d_out, int out_size) {
    const float* x  = (const float*)d_in[0];
    const float* Wq = (const float*)d_in[1];
    const float* Wk = (const float*)d_in[2];
    const float* Wv = (const float*)d_in[3];
    const float* Wo = (const float*)d_in[4];
    const float* bo = (const float*)d_in[5];
    float* out = (float*)d_out;

    __half *p_rxh, *p_xh, *p_qh, *p_kh, *p_vh, *p_ath, *p_whi, *p_wlo;
    cudaGetSymbolAddress((void**)&p_rxh, g_rxh);
    cudaGetSymbolAddress((void**)&p_xh,  g_xh);
    cudaGetSymbolAddress((void**)&p_qh,  g_qh);
    cudaGetSymbolAddress((void**)&p_kh,  g_kh);
    cudaGetSymbolAddress((void**)&p_vh,  g_vh);
    cudaGetSymbolAddress((void**)&p_ath, g_ath);
    cudaGetSymbolAddress((void**)&p_whi, g_whi);
    cudaGetSymbolAddress((void**)&p_wlo, g_wlo);

    cudaFuncSetAttribute(hmma_gemm16_kernel<0>,
                         cudaFuncAttributeMaxDynamicSharedMemorySize, GEMM16_SMEM);
    cudaFuncSetAttribute(hmma_gemm16_kernel<1>,
                         cudaFuncAttributeMaxDynamicSharedMemorySize, GEMM16_SMEM);
    cudaFuncSetAttribute(flash_hmma_kernel,
                         cudaFuncAttributeMaxDynamicSharedMemorySize, FL_SMEM);

    theta_kernel<<<2, 256>>>();
    rope_fused_kernel<<<(MM*E2 + 255)/256, 256>>>(x);
    dim3 sgrid((EE*EE + 255)/256, 4);
    split_all_kernel<<<sgrid, 256>>>(Wq, Wk, Wv, Wo);

    // fused Q/K/V projection: blockIdx.z selects (A, W, C)
    dim3 qkvgrid(EE/128, MM/128, 3);   // (8, 64, 3)
    hmma_gemm16_kernel<0><<<qkvgrid, 256, GEMM16_SMEM>>>(
        p_rxh, p_xh, p_whi, p_wlo, p_qh, p_kh, p_vh, nullptr, nullptr);

    dim3 fgrid(TT/128, BB*HH);         // (16, 64)
    flash_hmma_kernel<<<fgrid, 256, FL_SMEM>>>(p_qh, p_kh, p_vh, p_ath);

    dim3 ogrid(EE/128, MM/128, 1);
    hmma_gemm16_kernel<1><<<ogrid, 256, GEMM16_SMEM>>>(
        p_ath, nullptr, p_whi + 3*(size_t)EE*EE, p_wlo + 3*(size_t)EE*EE,
        nullptr, nullptr, nullptr, out, bo);
}

// round 12
// speedup vs baseline: 5.4348x; 1.0051x over previous
#include <cuda_runtime.h>
#include <cuda_fp16.h>
#include <math.h>
#include <stdint.h>

// Problem constants
#define BB 4
#define TT 2048
#define EE 1024
#define HH 16
#define HD 64
#define MM (BB*TT)          // 8192 rows
#define E2 (EE/2)           // 512 pairs
#define GK 1024

// ---------------- scratch (device globals; no allocation allowed) ----------
__device__ float g_theta[E2];

__device__ __align__(256) __half g_rxh [MM*EE];   // RoPE(x), fp16
__device__ __align__(256) __half g_xh  [MM*EE];   // x, fp16
__device__ __align__(256) __half g_qh  [MM*EE];   // Q fp16
__device__ __align__(256) __half g_kh  [MM*EE];   // K fp16
__device__ __align__(256) __half g_vh  [MM*EE];   // V fp16
__device__ __align__(256) __half g_ath [MM*EE];   // attention out fp16
__device__ __align__(256) __half g_whi [4][EE*EE];  // Wq,Wk,Wv,Wo hi
__device__ __align__(256) __half g_wlo [4][EE*EE];  // Wq,Wk,Wv,Wo lo

// ================= helpers (compute_80-level PTX only!) =====================
__device__ __forceinline__ uint32_t smem_u32(const void* p) {
    uint32_t a;
    asm("{ .reg .u64 t; cvta.to.shared.u64 t, %1; cvt.u32.u64 %0, t; }"
        : "=r"(a) : "l"(p));
    return a;
}
__device__ __forceinline__ void cp16(uint32_t saddr, const void* g) {
    asm volatile("cp.async.cg.shared.global [%0], [%1], 16;"
                 :: "r"(saddr), "l"(g) : "memory");
}
#define CP_COMMIT() asm volatile("cp.async.commit_group;" ::: "memory")
#define CP_WAIT(n)  asm volatile("cp.async.wait_group %0;" :: "n"(n) : "memory")

__device__ __forceinline__ void ldsm_x4(uint32_t* r, uint32_t addr) {
    asm volatile("ldmatrix.sync.aligned.m8n8.x4.shared.b16 {%0,%1,%2,%3}, [%4];"
                 : "=r"(r[0]), "=r"(r[1]), "=r"(r[2]), "=r"(r[3]) : "r"(addr));
}
__device__ __forceinline__ void ldsm_x4_t(uint32_t* r, uint32_t addr) {
    asm volatile("ldmatrix.sync.aligned.m8n8.x4.trans.shared.b16 {%0,%1,%2,%3}, [%4];"
                 : "=r"(r[0]), "=r"(r[1]), "=r"(r[2]), "=r"(r[3]) : "r"(addr));
}
__device__ __forceinline__ void mma_fp16(float* c, const uint32_t* a,
                                         const uint32_t* b) {
    asm volatile(
        "mma.sync.aligned.m16n8k16.row.col.f32.f16.f16.f32 "
        "{%0,%1,%2,%3}, {%4,%5,%6,%7}, {%8,%9}, {%0,%1,%2,%3};"
        : "+f"(c[0]), "+f"(c[1]), "+f"(c[2]), "+f"(c[3])
        : "r"(a[0]), "r"(a[1]), "r"(a[2]), "r"(a[3]), "r"(b[0]), "r"(b[1]));
}

// ---------------- theta table ------------------------------------------------
__global__ void theta_kernel() {
    int p = blockIdx.x * blockDim.x + threadIdx.x;
    if (p >= E2) return;
    g_theta[p] = (float)exp((-(double)(2*p) / (double)EE) * log(10000.0));
}

// ---------------- fused RoPE (fp16 out) + x fp16 ------------------------------
#define P2HI 6.2831854820251465f
#define P2LO -1.7484555e-7f
#define INV2PI 0.15915494309189535f

__global__ void rope_fused_kernel(const float* __restrict__ x) {
    int idx = blockIdx.x * blockDim.x + threadIdx.x;   // over MM*E2 pairs
    if (idx >= MM*E2) return;
    int bt = idx / E2;
    int p  = idx % E2;
    int t  = bt % TT;
    float2 v = ((const float2*)x)[idx];
    float ang = (float)t * g_theta[p];      // fp32 rounding as in reference
    float n = rintf(ang * INV2PI);
    float r = fmaf(-n, P2HI, ang);
    r = fmaf(-n, P2LO, r);
    float s, c;
    sincosf(r, &s, &c);
    float rx = v.x * c - v.y * s;
    float ry = v.y * c + v.x * s;
    ((__half2*)g_rxh)[idx] = __floats2half2_rn(rx, ry);
    ((__half2*)g_xh)[idx]  = __floats2half2_rn(v.x, v.y);
}

// ---------------- all-W fp16 hi/lo split (one launch) -------------------------
__global__ void split_all_kernel(const float* __restrict__ Wq,
                                 const float* __restrict__ Wk,
                                 const float* __restrict__ Wv,
                                 const float* __restrict__ Wo) {
    int i = blockIdx.x * blockDim.x + threadIdx.x;
    if (i >= EE*EE) return;
    int w = blockIdx.y;
    const float* src = (w == 0) ? Wq : (w == 1) ? Wk : (w == 2) ? Wv : Wo;
    float x = src[i];
    __half h = __float2half_rn(x);
    g_whi[w][i] = h;
    g_wlo[w][i] = __float2half_rn(x - __half2float(h));
}

// ---------------- persistent 2-term fp16 NT GEMM, 2-stage, 2 CTAs/SM ---------
// OUT: 0 = fused QKV (1536 tiles, fp16 out), 1 = O-proj (512 tiles, fp32+bias).
// Whi0/Wlo0 are ALWAYS the base of g_whi/g_wlo; tile_of's z does the offset.
#define KSTEPS (GK/64)          // 16
#define TILE_B 16384            // 128 rows x 128 bytes
#define STG16_B (3*TILE_B)      // A|Wh|Wl = 48 KB
#define GEMM16_SMEM (2*STG16_B) // 96 KB -> 2 CTAs/SM
#define GPERS_GRID 304          // 152 SMs x 2 CTAs

template<int OUT>
__global__ __launch_bounds__(256, 2)
void hmma_gemm16_kernel(const __half* __restrict__ A0,
                        const __half* __restrict__ A2,
                        const __half* __restrict__ Whi0,
                        const __half* __restrict__ Wlo0,
                        __half* __restrict__ C16_0,
                        __half* __restrict__ C16_1,
                        __half* __restrict__ C16_2,
                        float* __restrict__ C32,
                        const float* __restrict__ bias) {
    extern __shared__ char sm[];
    const int tid  = threadIdx.x;
    const int wid  = tid >> 5;
    const int lane = tid & 31;
    const uint32_t sbase = smem_u32(sm);
    const int wm = wid >> 2;
    const int wn = wid & 3;
    const int G  = (int)gridDim.x;
    const int bx = (int)blockIdx.x;
    const int T  = (OUT == 0) ? 1536 : 512;
    const int nt = (T - bx + G - 1) / G;     // tiles for this CTA (>=1)
    const int NC = nt << 4;                  // chunks

    // chunk -> tile params
    auto tile_of = [&](int c, int& z, int& r0, int& c0) {
        int t = bx + (c >> 4) * G;
        if (OUT == 0) { z = t / 512; int rem = t & 511; r0 = (rem >> 3) << 7; c0 = (rem & 7) << 7; }
        else          { z = 3;       r0 = (t >> 3) << 7; c0 = (t & 7) << 7; }
    };

    auto load_chunk = [&](int s, int c) {
        if (c >= NC) return;
        int z, r0, c0; tile_of(c, z, r0, c0);
        const int k0 = (c & 15) * 64;
        const __half* A   = (OUT == 0 && z == 2) ? A2 : A0;
        const __half* srcs[3] = { A, Whi0 + (size_t)z*EE*EE, Wlo0 + (size_t)z*EE*EE };
        const uint32_t st = sbase + s * STG16_B;
        #pragma unroll
        for (int t = 0; t < 3; t++) {
            const int rb = (t == 0) ? r0 : c0;
            #pragma unroll
            for (int it = 0; it < 4; it++) {
                int u = tid + 256 * it;
                int r = u >> 3, cc = u & 7;
                const __half* g = srcs[t] + (size_t)(rb + r) * GK + k0 + cc * 8;
                uint32_t sa = st + t * TILE_B + r * 128 + ((cc ^ (r & 7)) * 16);
                cp16(sa, g);
            }
        }
    };

    load_chunk(0, 0); CP_COMMIT();
    load_chunk(1, 1); CP_COMMIT();

    float acc[4][4][4] = {};
    const int lr = lane & 15, lc = lane >> 4;

    for (int c = 0; c < NC; c++) {
        CP_WAIT(1);
        __syncthreads();

        const uint32_t st = sbase + (c & 1) * STG16_B;
        const uint32_t aB = st;
        const uint32_t whB = st + TILE_B, wlB = st + 2*TILE_B;

        #pragma unroll
        for (int k16 = 0; k16 < 4; k16++) {
            uint32_t a[4][4], wh[4][2], wl[4][2];
            #pragma unroll
            for (int i = 0; i < 4; i++) {
                int row = wm*64 + i*16 + lr;
                int cc = k16*2 + lc;
                uint32_t off = row*128 + ((cc ^ (row & 7)) * 16);
                ldsm_x4(a[i], aB + off);
            }
            #pragma unroll
            for (int jj = 0; jj < 2; jj++) {
                int row = wn*32 + jj*16 + lr;
                int cc = k16*2 + lc;
                uint32_t off = row*128 + ((cc ^ (row & 7)) * 16);
                uint32_t t0[4], t1[4];
                ldsm_x4(t0, whB + off);
                wh[jj*2][0] = t0[0]; wh[jj*2][1] = t0[2];
                wh[jj*2+1][0] = t0[1]; wh[jj*2+1][1] = t0[3];
                ldsm_x4(t1, wlB + off);
                wl[jj*2][0] = t1[0]; wl[jj*2][1] = t1[2];
                wl[jj*2+1][0] = t1[1]; wl[jj*2+1][1] = t1[3];
            }
            if (k16 == 3) {
                // all smem reads of this stage issued & ordered by the barrier;
                // overlap next-chunk cp.async with the final MMA batch.
                __syncthreads();
                load_chunk(c & 1, c + 2);
                CP_COMMIT();
            }
            #pragma unroll
            for (int i = 0; i < 4; i++)
                #pragma unroll
                for (int j = 0; j < 4; j++) {
                    mma_fp16(acc[i][j], a[i], wh[j]);
                    mma_fp16(acc[i][j], a[i], wl[j]);
                }
        }

        if ((c & 15) == 15) {
            // epilogue for this tile (registers -> global; no smem involved)
            int z, r0, c0; tile_of(c, z, r0, c0);
            const int gq = lane >> 2, tig = lane & 3;
            __half* C16 = (OUT == 0)
                ? ((z == 0) ? C16_0 : (z == 1) ? C16_1 : C16_2) : nullptr;
            #pragma unroll
            for (int j = 0; j < 4; j++) {
                const int n = c0 + wn*32 + j*8 + tig*2;
                float b0 = 0.f, b1 = 0.f;
                if (OUT == 1) { b0 = bias[n]; b1 = bias[n+1]; }
                #pragma unroll
                for (int i = 0; i < 4; i++) {
                    const int m0 = r0 + wm*64 + i*16 + gq;
                    if (OUT == 0) {
                        *(__half2*)(C16 + (size_t)m0*GK + n) =
                            __floats2half2_rn(acc[i][j][0], acc[i][j][1]);
                        *(__half2*)(C16 + (size_t)(m0+8)*GK + n) =
                            __floats2half2_rn(acc[i][j][2], acc[i][j][3]);
                    } else {
                        *(float2*)(C32 + (size_t)m0 * GK + n) =
                            make_float2(acc[i][j][0] + b0, acc[i][j][1] + b1);
                        *(float2*)(C32 + (size_t)(m0 + 8) * GK + n) =
                            make_float2(acc[i][j][2] + b0, acc[i][j][3] + b1);
                    }
                }
            }
            #pragma unroll
            for (int i = 0; i < 4; i++)
                #pragma unroll
                for (int j = 0; j < 4; j++) {
                    acc[i][j][0] = 0.f; acc[i][j][1] = 0.f;
                    acc[i][j][2] = 0.f; acc[i][j][3] = 0.f;
                }
        }
    }
}

// ---------------- HMMA flash attention (causal, fp16, 3-stage) ---------------
#define FL_QB   16384
#define FL_TB   8192
#define FL_STG  (2*FL_TB)
#define FL_NSTG 3
#define FL_SMEM (FL_QB + FL_NSTG*FL_STG)   // 64 KB

__global__ __launch_bounds__(256, 2)
void flash_hmma_kernel(const __half* __restrict__ qh,
                       const __half* __restrict__ kh,
                       const __half* __restrict__ vh,
                       __half* __restrict__ oh) {
    extern __shared__ char sm[];
    const int tid  = threadIdx.x;
    const int wid  = tid >> 5;
    const int lane = tid & 31;
    const int qt = (int)(gridDim.x - 1 - blockIdx.x);   // heavy tiles first
    const int bh = blockIdx.y;
    const int b = bh >> 4, h = bh & 15;
    const int qrow0 = qt * 128;
    const size_t grow0 = (size_t)b * TT + qrow0;
    const int colb = h * HD;

    const uint32_t sb  = smem_u32(sm);
    const uint32_t qB  = sb;
    const uint32_t stB = sb + FL_QB;

    #pragma unroll
    for (int it = 0; it < 4; it++) {
        int u = tid + 256 * it;
        int r = u >> 3, c = u & 7;
        cp16(qB + r*128 + ((c ^ (r & 7)) * 16),
             qh + (grow0 + r) * EE + colb + c * 8);
    }
    const __half* ksrc[2] = { kh, vh };
    auto load_stage = [&](int s, int kt) {
        const size_t krow = (size_t)b * TT + kt * 64;
        const uint32_t st = stB + s * FL_STG;
        #pragma unroll
        for (int t = 0; t < 2; t++) {
            #pragma unroll
            for (int it = 0; it < 2; it++) {
                int u = tid + 256 * it;
                int r = u >> 3, c = u & 7;
                cp16(st + t*FL_TB + r*128 + ((c ^ (r & 7)) * 16),
                     ksrc[t] + (krow + r) * EE + colb + c * 8);
            }
        }
    };
    const int nkv = 2*qt + 2;
    load_stage(0, 0); CP_COMMIT();
    if (1 < nkv) load_stage(1, 1);
    CP_COMMIT();

    CP_WAIT(1);
    __syncthreads();
    uint32_t qf[4][4];
    const int lr = lane & 15, lc = lane >> 4;
    #pragma unroll
    for (int k16 = 0; k16 < 4; k16++) {
        int row = wid*16 + lr;
        int c = k16*2 + lc;
        uint32_t off = row*128 + ((c ^ (row & 7)) * 16);
        ldsm_x4(qf[k16], qB + off);
    }

    float m0 = -INFINITY, m1 = -INFINITY, l0 = 0.f, l1 = 0.f;
    float o[8][4] = {};
    const int rg0 = qrow0 + wid*16 + (lane >> 2);
    const int tig = lane & 3;

    for (int kt = 0; kt < nkv; kt++) {
        if (kt > 0) {
            CP_WAIT(1);
            __syncthreads();
        }
        if (kt + 2 < nkv) load_stage((kt + 2) % FL_NSTG, kt + 2);
        CP_COMMIT();

        const uint32_t st = stB + (kt % FL_NSTG) * FL_STG;
        const uint32_t kB = st, vB = st + FL_TB;

        float s[8][4] = {};
        #pragma unroll
        for (int k16 = 0; k16 < 4; k16++) {
            uint32_t kf[8][2];
            #pragma unroll
            for (int jj = 0; jj < 4; jj++) {
                int row = jj*16 + lr;
                int c = k16*2 + lc;
                uint32_t off = row*128 + ((c ^ (row & 7)) * 16);
                uint32_t t0[4];
                ldsm_x4(t0, kB + off);
                kf[jj*2][0] = t0[0]; kf[jj*2][1] = t0[2];
                kf[jj*2+1][0] = t0[1]; kf[jj*2+1][1] = t0[3];
            }
            #pragma unroll
            for (int j = 0; j < 8; j++)
                mma_fp16(s[j], qf[k16], kf[j]);
        }

        const bool maskt = (kt >= 2*qt);
        #pragma unroll
        for (int j = 0; j < 8; j++) {
            s[j][0] *= 0.125f; s[j][1] *= 0.125f;
            s[j][2] *= 0.125f; s[j][3] *= 0.125f;
            if (maskt) {
                int c0 = kt*64 + j*8 + tig*2;
                if (c0     > rg0)     s[j][0] = -INFINITY;
                if (c0 + 1 > rg0)     s[j][1] = -INFINITY;
                if (c0     > rg0 + 8) s[j][2] = -INFINITY;
                if (c0 + 1 > rg0 + 8) s[j][3] = -INFINITY;
            }
        }

        float tm0 = -INFINITY, tm1 = -INFINITY;
        #pragma unroll
        for (int j = 0; j < 8; j++) {
            tm0 = fmaxf(tm0, fmaxf(s[j][0], s[j][1]));
            tm1 = fmaxf(tm1, fmaxf(s[j][2], s[j][3]));
        }
        tm0 = fmaxf(tm0, __shfl_xor_sync(0xffffffff, tm0, 1));
        tm0 = fmaxf(tm0, __shfl_xor_sync(0xffffffff, tm0, 2));
        tm1 = fmaxf(tm1, __shfl_xor_sync(0xffffffff, tm1, 1));
        tm1 = fmaxf(tm1, __shfl_xor_sync(0xffffffff, tm1, 2));
        float mn0 = fmaxf(m0, tm0), mn1 = fmaxf(m1, tm1);
        float a0 = __expf(m0 - mn0), a1 = __expf(m1 - mn1);

        uint32_t pH01[8], pH23[8];
        float rs0 = 0.f, rs1 = 0.f;
        #pragma unroll
        for (int j = 0; j < 8; j++) {
            __half h0 = __float2half_rn(__expf(s[j][0] - mn0));
            __half h1 = __float2half_rn(__expf(s[j][1] - mn0));
            __half h2 = __float2half_rn(__expf(s[j][2] - mn1));
            __half h3 = __float2half_rn(__expf(s[j][3] - mn1));
            rs0 += __half2float(h0) + __half2float(h1);
            rs1 += __half2float(h2) + __half2float(h3);
            pH01[j] = ((uint32_t)*(uint16_t*)&h1 << 16) | *(uint16_t*)&h0;
            pH23[j] = ((uint32_t)*(uint16_t*)&h3 << 16) | *(uint16_t*)&h2;
        }
        rs0 += __shfl_xor_sync(0xffffffff, rs0, 1);
        rs0 += __shfl_xor_sync(0xffffffff, rs0, 2);
        rs1 += __shfl_xor_sync(0xffffffff, rs1, 1);
        rs1 += __shfl_xor_sync(0xffffffff, rs1, 2);
        l0 = l0 * a0 + rs0;
        l1 = l1 * a1 + rs1;
        m0 = mn0; m1 = mn1;

        #pragma unroll
        for (int j = 0; j < 8; j++) {
            o[j][0] *= a0; o[j][1] *= a0;
            o[j][2] *= a1; o[j][3] *= a1;
        }

        const int mi = lane >> 3, li = lane & 7;
        #pragma unroll
        for (int c16 = 0; c16 < 4; c16++) {
            uint32_t aH[4] = { pH01[2*c16], pH23[2*c16], pH01[2*c16+1], pH23[2*c16+1] };
            #pragma unroll
            for (int dj = 0; dj < 4; dj++) {
                int row = c16*16 + ((mi >> 1) ? 8 : 0) + li;
                int ch  = dj*2 + (mi & 1);
                uint32_t off = row*128 + ((ch ^ (row & 7)) * 16);
                uint32_t t0[4];
                ldsm_x4_t(t0, vB + off);
                uint32_t v0[2] = { t0[0], t0[2] }, v1[2] = { t0[1], t0[3] };
                mma_fp16(o[dj*2],   aH, v0);
                mma_fp16(o[dj*2+1], aH, v1);
            }
        }
    }

    const float i0 = 1.f / l0, i1 = 1.f / l1;
    const size_t r0g = grow0 + wid*16 + (lane >> 2);
    #pragma unroll
    for (int j = 0; j < 8; j++) {
        const int n = colb + j*8 + tig*2;
        *(__half2*)(oh + r0g*EE + n)     = __floats2half2_rn(o[j][0]*i0, o[j][1]*i0);
        *(__half2*)(oh + (r0g+8)*EE + n) = __floats2half2_rn(o[j][2]*i1, o[j][3]*i1);
    }
}

// ---------------- launch ----------------------------------------------------
extern "C" void kernel_launch(void* const* d_in, const int* in_sizes, int n_in,
                              void* d_out, int out_size) {
    const float* x  = (const float*)d_in[0];
    const float* Wq = (const float*)d_in[1];
    const float* Wk = (const float*)d_in[2];
    const float* Wv = (const float*)d_in[3];
    const float* Wo = (const float*)d_in[4];
    const float* bo = (const float*)d_in[5];
    float* out = (float*)d_out;

    __half *p_rxh, *p_xh, *p_qh, *p_kh, *p_vh, *p_ath, *p_whi, *p_wlo;
    cudaGetSymbolAddress((void**)&p_rxh, g_rxh);
    cudaGetSymbolAddress((void**)&p_xh,  g_xh);
    cudaGetSymbolAddress((void**)&p_qh,  g_qh);
    cudaGetSymbolAddress((void**)&p_kh,  g_kh);
    cudaGetSymbolAddress((void**)&p_vh,  g_vh);
    cudaGetSymbolAddress((void**)&p_ath, g_ath);
    cudaGetSymbolAddress((void**)&p_whi, g_whi);
    cudaGetSymbolAddress((void**)&p_wlo, g_wlo);

    cudaFuncSetAttribute(hmma_gemm16_kernel<0>,
                         cudaFuncAttributeMaxDynamicSharedMemorySize, GEMM16_SMEM);
    cudaFuncSetAttribute(hmma_gemm16_kernel<1>,
                         cudaFuncAttributeMaxDynamicSharedMemorySize, GEMM16_SMEM);
    cudaFuncSetAttribute(flash_hmma_kernel,
                         cudaFuncAttributeMaxDynamicSharedMemorySize, FL_SMEM);

    theta_kernel<<<2, 256>>>();
    rope_fused_kernel<<<(MM*E2 + 255)/256, 256>>>(x);
    dim3 sgrid((EE*EE + 255)/256, 4);
    split_all_kernel<<<sgrid, 256>>>(Wq, Wk, Wv, Wo);

    // persistent fused Q/K/V projection (1536 tiles over 304 CTAs)
    hmma_gemm16_kernel<0><<<GPERS_GRID, 256, GEMM16_SMEM>>>(
        p_rxh, p_xh, p_whi, p_wlo, p_qh, p_kh, p_vh, nullptr, nullptr);

    dim3 fgrid(TT/128, BB*HH);         // (16, 64)
    flash_hmma_kernel<<<fgrid, 256, FL_SMEM>>>(p_qh, p_kh, p_vh, p_ath);

    // persistent O-projection (512 tiles over 304 CTAs).
    // NOTE: pass BASE weight pointers — tile_of's z=3 applies the Wo offset
    // exactly once (round-11 IMA was a double offset here).
    hmma_gemm16_kernel<1><<<GPERS_GRID, 256, GEMM16_SMEM>>>(
        p_ath, nullptr, p_whi, p_wlo,
        nullptr, nullptr, nullptr, out, bo);
}

// round 13
// speedup vs baseline: 5.4812x; 1.0085x over previous
#include <cuda_runtime.h>
#include <cuda_fp16.h>
#include <math.h>
#include <stdint.h>

// Problem constants
#define BB 4
#define TT 2048
#define EE 1024
#define HH 16
#define HD 64
#define MM (BB*TT)          // 8192 rows
#define E2 (EE/2)           // 512 pairs
#define GK 1024

// ---------------- scratch (device globals; no allocation allowed) ----------
__device__ float g_theta[E2];

__device__ __align__(256) __half g_rxh [MM*EE];   // RoPE(x), fp16
__device__ __align__(256) __half g_xh  [MM*EE];   // x, fp16
__device__ __align__(256) __half g_qh  [MM*EE];   // Q fp16
__device__ __align__(256) __half g_kh  [MM*EE];   // K fp16
__device__ __align__(256) __half g_vh  [MM*EE];   // V fp16
__device__ __align__(256) __half g_ath [MM*EE];   // attention out fp16
__device__ __align__(256) __half g_whi [4][EE*EE];  // Wq,Wk,Wv,Wo hi
__device__ __align__(256) __half g_wlo [4][EE*EE];  // Wq,Wk,Wv,Wo lo

// ================= helpers (compute_80-level PTX only!) =====================
__device__ __forceinline__ uint32_t smem_u32(const void* p) {
    uint32_t a;
    asm("{ .reg .u64 t; cvta.to.shared.u64 t, %1; cvt.u32.u64 %0, t; }"
        : "=r"(a) : "l"(p));
    return a;
}
__device__ __forceinline__ void cp16(uint32_t saddr, const void* g) {
    asm volatile("cp.async.cg.shared.global [%0], [%1], 16;"
                 :: "r"(saddr), "l"(g) : "memory");
}
#define CP_COMMIT() asm volatile("cp.async.commit_group;" ::: "memory")
#define CP_WAIT(n)  asm volatile("cp.async.wait_group %0;" :: "n"(n) : "memory")

__device__ __forceinline__ void ldsm_x4(uint32_t* r, uint32_t addr) {
    asm volatile("ldmatrix.sync.aligned.m8n8.x4.shared.b16 {%0,%1,%2,%3}, [%4];"
                 : "=r"(r[0]), "=r"(r[1]), "=r"(r[2]), "=r"(r[3]) : "r"(addr));
}
__device__ __forceinline__ void ldsm_x4_t(uint32_t* r, uint32_t addr) {
    asm volatile("ldmatrix.sync.aligned.m8n8.x4.trans.shared.b16 {%0,%1,%2,%3}, [%4];"
                 : "=r"(r[0]), "=r"(r[1]), "=r"(r[2]), "=r"(r[3]) : "r"(addr));
}
__device__ __forceinline__ void mma_fp16(float* c, const uint32_t* a,
                                         const uint32_t* b) {
    asm volatile(
        "mma.sync.aligned.m16n8k16.row.col.f32.f16.f16.f32 "
        "{%0,%1,%2,%3}, {%4,%5,%6,%7}, {%8,%9}, {%0,%1,%2,%3};"
        : "+f"(c[0]), "+f"(c[1]), "+f"(c[2]), "+f"(c[3])
        : "r"(a[0]), "r"(a[1]), "r"(a[2]), "r"(a[3]), "r"(b[0]), "r"(b[1]));
}

// ---------------- theta table ------------------------------------------------
__global__ void theta_kernel() {
    int p = blockIdx.x * blockDim.x + threadIdx.x;
    if (p >= E2) return;
    g_theta[p] = (float)exp((-(double)(2*p) / (double)EE) * log(10000.0));
}

// ---------------- fused RoPE (fp16 out) + x fp16 ------------------------------
#define P2HI 6.2831854820251465f
#define P2LO -1.7484555e-7f
#define INV2PI 0.15915494309189535f

__global__ void rope_fused_kernel(const float* __restrict__ x) {
    int idx = blockIdx.x * blockDim.x + threadIdx.x;   // over MM*E2 pairs
    if (idx >= MM*E2) return;
    int bt = idx / E2;
    int p  = idx % E2;
    int t  = bt % TT;
    float2 v = ((const float2*)x)[idx];
    float ang = (float)t * g_theta[p];      // fp32 rounding as in reference
    float n = rintf(ang * INV2PI);
    float r = fmaf(-n, P2HI, ang);
    r = fmaf(-n, P2LO, r);
    float s, c;
    sincosf(r, &s, &c);
    float rx = v.x * c - v.y * s;
    float ry = v.y * c + v.x * s;
    ((__half2*)g_rxh)[idx] = __floats2half2_rn(rx, ry);
    ((__half2*)g_xh)[idx]  = __floats2half2_rn(v.x, v.y);
}

// ---------------- all-W fp16 hi/lo split (one launch) -------------------------
__global__ void split_all_kernel(const float* __restrict__ Wq,
                                 const float* __restrict__ Wk,
                                 const float* __restrict__ Wv,
                                 const float* __restrict__ Wo) {
    int i = blockIdx.x * blockDim.x + threadIdx.x;
    if (i >= EE*EE) return;
    int w = blockIdx.y;
    const float* src = (w == 0) ? Wq : (w == 1) ? Wk : (w == 2) ? Wv : Wo;
    float x = src[i];
    __half h = __float2half_rn(x);
    g_whi[w][i] = h;
    g_wlo[w][i] = __float2half_rn(x - __half2float(h));
}

// ---------------- persistent 2-term fp16 NT GEMM, 2-stage, 2 CTAs/SM ---------
// One barrier per k-chunk: prefetch(c+1) issued right after chunk c's top
// barrier (its target stage was consumed in chunk c-1, ordered by this bar).
#define KSTEPS (GK/64)          // 16
#define TILE_B 16384            // 128 rows x 128 bytes
#define STG16_B (3*TILE_B)      // A|Wh|Wl = 48 KB
#define GEMM16_SMEM (2*STG16_B) // 96 KB -> 2 CTAs/SM
#define GPERS_GRID 304          // 152 SMs x 2 CTAs

template<int OUT>
__global__ __launch_bounds__(256, 2)
void hmma_gemm16_kernel(const __half* __restrict__ A0,
                        const __half* __restrict__ A2,
                        const __half* __restrict__ Whi0,
                        const __half* __restrict__ Wlo0,
                        __half* __restrict__ C16_0,
                        __half* __restrict__ C16_1,
                        __half* __restrict__ C16_2,
                        float* __restrict__ C32,
                        const float* __restrict__ bias) {
    extern __shared__ char sm[];
    const int tid  = threadIdx.x;
    const int wid  = tid >> 5;
    const int lane = tid & 31;
    const uint32_t sbase = smem_u32(sm);
    const int wm = wid >> 2;
    const int wn = wid & 3;
    const int G  = (int)gridDim.x;
    const int bx = (int)blockIdx.x;
    const int T  = (OUT == 0) ? 1536 : 512;
    const int nt = (T - bx + G - 1) / G;
    const int NC = nt << 4;

    auto tile_of = [&](int c, int& z, int& r0, int& c0) {
        int t = bx + (c >> 4) * G;
        if (OUT == 0) { z = t / 512; int rem = t & 511; r0 = (rem >> 3) << 7; c0 = (rem & 7) << 7; }
        else          { z = 3;       r0 = (t >> 3) << 7; c0 = (t & 7) << 7; }
    };

    auto load_chunk = [&](int s, int c) {
        if (c >= NC) return;
        int z, r0, c0; tile_of(c, z, r0, c0);
        const int k0 = (c & 15) * 64;
        const __half* A   = (OUT == 0 && z == 2) ? A2 : A0;
        const __half* srcs[3] = { A, Whi0 + (size_t)z*EE*EE, Wlo0 + (size_t)z*EE*EE };
        const uint32_t st = sbase + s * STG16_B;
        #pragma unroll
        for (int t = 0; t < 3; t++) {
            const int rb = (t == 0) ? r0 : c0;
            #pragma unroll
            for (int it = 0; it < 4; it++) {
                int u = tid + 256 * it;
                int r = u >> 3, cc = u & 7;
                const __half* g = srcs[t] + (size_t)(rb + r) * GK + k0 + cc * 8;
                uint32_t sa = st + t * TILE_B + r * 128 + ((cc ^ (r & 7)) * 16);
                cp16(sa, g);
            }
        }
    };

    load_chunk(0, 0); CP_COMMIT();

    float acc[4][4][4] = {};
    const int lr = lane & 15, lc = lane >> 4;

    // ---- hoisted swizzled offsets (row&7 == lr&7 since strides are mult of 8)
    // addr = stage + base + i*2048 + sw[k16]
    uint32_t sw[4];
    #pragma unroll
    for (int k16 = 0; k16 < 4; k16++)
        sw[k16] = (uint32_t)(((k16*2 + lc) ^ (lr & 7)) * 16);
    const uint32_t baseA = (uint32_t)((wm*64 + lr) * 128);
    const uint32_t baseW = (uint32_t)((wn*32 + lr) * 128);

    for (int c = 0; c < NC; c++) {
        CP_WAIT(0);
        __syncthreads();
        load_chunk((c + 1) & 1, c + 1);   // target stage consumed in chunk c-1
        CP_COMMIT();

        const uint32_t st = sbase + (c & 1) * STG16_B;
        const uint32_t aB = st + baseA;
        const uint32_t whB = st + TILE_B + baseW, wlB = st + 2*TILE_B + baseW;

        #pragma unroll
        for (int k16 = 0; k16 < 4; k16++) {
            const uint32_t s16 = sw[k16];
            uint32_t a[4][4], wh[4][2], wl[4][2];
            #pragma unroll
            for (int i = 0; i < 4; i++)
                ldsm_x4(a[i], aB + i*2048 + s16);
            #pragma unroll
            for (int jj = 0; jj < 2; jj++) {
                uint32_t t0[4], t1[4];
                ldsm_x4(t0, whB + jj*2048 + s16);
                wh[jj*2][0] = t0[0]; wh[jj*2][1] = t0[2];
                wh[jj*2+1][0] = t0[1]; wh[jj*2+1][1] = t0[3];
                ldsm_x4(t1, wlB + jj*2048 + s16);
                wl[jj*2][0] = t1[0]; wl[jj*2][1] = t1[2];
                wl[jj*2+1][0] = t1[1]; wl[jj*2+1][1] = t1[3];
            }
            #pragma unroll
            for (int i = 0; i < 4; i++)
                #pragma unroll
                for (int j = 0; j < 4; j++) {
                    mma_fp16(acc[i][j], a[i], wh[j]);
                    mma_fp16(acc[i][j], a[i], wl[j]);
                }
        }

        if ((c & 15) == 15) {
            int z, r0, c0; tile_of(c, z, r0, c0);
            const int gq = lane >> 2, tig = lane & 3;
            __half* C16 = (OUT == 0)
                ? ((z == 0) ? C16_0 : (z == 1) ? C16_1 : C16_2) : nullptr;
            #pragma unroll
            for (int j = 0; j < 4; j++) {
                const int n = c0 + wn*32 + j*8 + tig*2;
                float b0 = 0.f, b1 = 0.f;
                if (OUT == 1) { b0 = bias[n]; b1 = bias[n+1]; }
                #pragma unroll
                for (int i = 0; i < 4; i++) {
                    const int m0 = r0 + wm*64 + i*16 + gq;
                    if (OUT == 0) {
                        *(__half2*)(C16 + (size_t)m0*GK + n) =
                            __floats2half2_rn(acc[i][j][0], acc[i][j][1]);
                        *(__half2*)(C16 + (size_t)(m0+8)*GK + n) =
                            __floats2half2_rn(acc[i][j][2], acc[i][j][3]);
                    } else {
                        *(float2*)(C32 + (size_t)m0 * GK + n) =
                            make_float2(acc[i][j][0] + b0, acc[i][j][1] + b1);
                        *(float2*)(C32 + (size_t)(m0 + 8) * GK + n) =
                            make_float2(acc[i][j][2] + b0, acc[i][j][3] + b1);
                    }
                }
            }
            #pragma unroll
            for (int i = 0; i < 4; i++)
                #pragma unroll
                for (int j = 0; j < 4; j++) {
                    acc[i][j][0] = 0.f; acc[i][j][1] = 0.f;
                    acc[i][j][2] = 0.f; acc[i][j][3] = 0.f;
                }
        }
    }
}

// ---------------- HMMA flash attention (causal, fp16, 3-stage) ---------------
#define FL_QB   16384
#define FL_TB   8192
#define FL_STG  (2*FL_TB)
#define FL_NSTG 3
#define FL_SMEM (FL_QB + FL_NSTG*FL_STG)   // 64 KB

__global__ __launch_bounds__(256, 2)
void flash_hmma_kernel(const __half* __restrict__ qh,
                       const __half* __restrict__ kh,
                       const __half* __restrict__ vh,
                       __half* __restrict__ oh) {
    extern __shared__ char sm[];
    const int tid  = threadIdx.x;
    const int wid  = tid >> 5;
    const int lane = tid & 31;
    const int qt = (int)(gridDim.x - 1 - blockIdx.x);   // heavy tiles first
    const int bh = blockIdx.y;
    const int b = bh >> 4, h = bh & 15;
    const int qrow0 = qt * 128;
    const size_t grow0 = (size_t)b * TT + qrow0;
    const int colb = h * HD;

    const uint32_t sb  = smem_u32(sm);
    const uint32_t qB  = sb;
    const uint32_t stB = sb + FL_QB;

    #pragma unroll
    for (int it = 0; it < 4; it++) {
        int u = tid + 256 * it;
        int r = u >> 3, c = u & 7;
        cp16(qB + r*128 + ((c ^ (r & 7)) * 16),
             qh + (grow0 + r) * EE + colb + c * 8);
    }
    const __half* ksrc[2] = { kh, vh };
    auto load_stage = [&](int s, int kt) {
        const size_t krow = (size_t)b * TT + kt * 64;
        const uint32_t st = stB + s * FL_STG;
        #pragma unroll
        for (int t = 0; t < 2; t++) {
            #pragma unroll
            for (int it = 0; it < 2; it++) {
                int u = tid + 256 * it;
                int r = u >> 3, c = u & 7;
                cp16(st + t*FL_TB + r*128 + ((c ^ (r & 7)) * 16),
                     ksrc[t] + (krow + r) * EE + colb + c * 8);
            }
        }
    };
    const int nkv = 2*qt + 2;
    load_stage(0, 0); CP_COMMIT();
    if (1 < nkv) load_stage(1, 1);
    CP_COMMIT();

    CP_WAIT(1);
    __syncthreads();

    // hoisted swizzle offsets
    const int lr = lane & 15, lc = lane >> 4;
    uint32_t sw[4];
    #pragma unroll
    for (int k16 = 0; k16 < 4; k16++)
        sw[k16] = (uint32_t)(((k16*2 + lc) ^ (lr & 7)) * 16);
    const uint32_t baseQ = (uint32_t)((wid*16 + lr) * 128);
    const uint32_t baseK = (uint32_t)(lr * 128);

    const int mi = lane >> 3, li = lane & 7;
    uint32_t swv[4];
    #pragma unroll
    for (int dj = 0; dj < 4; dj++)
        swv[dj] = (uint32_t)(((dj*2 + (mi & 1)) ^ (li & 7)) * 16);
    const uint32_t baseV = (uint32_t)((((mi >> 1) ? 8 : 0) + li) * 128);

    uint32_t qf[4][4];
    #pragma unroll
    for (int k16 = 0; k16 < 4; k16++)
        ldsm_x4(qf[k16], qB + baseQ + sw[k16]);

    float m0 = -INFINITY, m1 = -INFINITY, l0 = 0.f, l1 = 0.f;
    float o[8][4] = {};
    const int rg0 = qrow0 + wid*16 + (lane >> 2);
    const int tig = lane & 3;

    for (int kt = 0; kt < nkv; kt++) {
        if (kt > 0) {
            CP_WAIT(1);
            __syncthreads();
        }
        if (kt + 2 < nkv) load_stage((kt + 2) % FL_NSTG, kt + 2);
        CP_COMMIT();

        const uint32_t st = stB + (kt % FL_NSTG) * FL_STG;
        const uint32_t kB = st + baseK, vB = st + FL_TB + baseV;

        float s[8][4] = {};
        #pragma unroll
        for (int k16 = 0; k16 < 4; k16++) {
            uint32_t kf[8][2];
            #pragma unroll
            for (int jj = 0; jj < 4; jj++) {
                uint32_t t0[4];
                ldsm_x4(t0, kB + jj*2048 + sw[k16]);
                kf[jj*2][0] = t0[0]; kf[jj*2][1] = t0[2];
                kf[jj*2+1][0] = t0[1]; kf[jj*2+1][1] = t0[3];
            }
            #pragma unroll
            for (int j = 0; j < 8; j++)
                mma_fp16(s[j], qf[k16], kf[j]);
        }

        const bool maskt = (kt >= 2*qt);
        #pragma unroll
        for (int j = 0; j < 8; j++) {
            s[j][0] *= 0.125f; s[j][1] *= 0.125f;
            s[j][2] *= 0.125f; s[j][3] *= 0.125f;
            if (maskt) {
                int c0 = kt*64 + j*8 + tig*2;
                if (c0     > rg0)     s[j][0] = -INFINITY;
                if (c0 + 1 > rg0)     s[j][1] = -INFINITY;
                if (c0     > rg0 + 8) s[j][2] = -INFINITY;
                if (c0 + 1 > rg0 + 8) s[j][3] = -INFINITY;
            }
        }

        float tm0 = -INFINITY, tm1 = -INFINITY;
        #pragma unroll
        for (int j = 0; j < 8; j++) {
            tm0 = fmaxf(tm0, fmaxf(s[j][0], s[j][1]));
            tm1 = fmaxf(tm1, fmaxf(s[j][2], s[j][3]));
        }
        tm0 = fmaxf(tm0, __shfl_xor_sync(0xffffffff, tm0, 1));
        tm0 = fmaxf(tm0, __shfl_xor_sync(0xffffffff, tm0, 2));
        tm1 = fmaxf(tm1, __shfl_xor_sync(0xffffffff, tm1, 1));
        tm1 = fmaxf(tm1, __shfl_xor_sync(0xffffffff, tm1, 2));
        float mn0 = fmaxf(m0, tm0), mn1 = fmaxf(m1, tm1);
        float a0 = __expf(m0 - mn0), a1 = __expf(m1 - mn1);

        uint32_t pH01[8], pH23[8];
        float rs0 = 0.f, rs1 = 0.f;
        #pragma unroll
        for (int j = 0; j < 8; j++) {
            __half h0 = __float2half_rn(__expf(s[j][0] - mn0));
            __half h1 = __float2half_rn(__expf(s[j][1] - mn0));
            __half h2 = __float2half_rn(__expf(s[j][2] - mn1));
            __half h3 = __float2half_rn(__expf(s[j][3] - mn1));
            rs0 += __half2float(h0) + __half2float(h1);
            rs1 += __half2float(h2) + __half2float(h3);
            pH01[j] = ((uint32_t)*(uint16_t*)&h1 << 16) | *(uint16_t*)&h0;
            pH23[j] = ((uint32_t)*(uint16_t*)&h3 << 16) | *(uint16_t*)&h2;
        }
        rs0 += __shfl_xor_sync(0xffffffff, rs0, 1);
        rs0 += __shfl_xor_sync(0xffffffff, rs0, 2);
        rs1 += __shfl_xor_sync(0xffffffff, rs1, 1);
        rs1 += __shfl_xor_sync(0xffffffff, rs1, 2);
        l0 = l0 * a0 + rs0;
        l1 = l1 * a1 + rs1;
        m0 = mn0; m1 = mn1;

        #pragma unroll
        for (int j = 0; j < 8; j++) {
            o[j][0] *= a0; o[j][1] *= a0;
            o[j][2] *= a1; o[j][3] *= a1;
        }

        #pragma unroll
        for (int c16 = 0; c16 < 4; c16++) {
            uint32_t aH[4] = { pH01[2*c16], pH23[2*c16], pH01[2*c16+1], pH23[2*c16+1] };
            #pragma unroll
            for (int dj = 0; dj < 4; dj++) {
                uint32_t t0[4];
                ldsm_x4_t(t0, vB + c16*2048 + swv[dj]);
                uint32_t v0[2] = { t0[0], t0[2] }, v1[2] = { t0[1], t0[3] };
                mma_fp16(o[dj*2],   aH, v0);
                mma_fp16(o[dj*2+1], aH, v1);
            }
        }
    }

    const float i0 = 1.f / l0, i1 = 1.f / l1;
    const size_t r0g = grow0 + wid*16 + (lane >> 2);
    #pragma unroll
    for (int j = 0; j < 8; j++) {
        const int n = colb + j*8 + tig*2;
        *(__half2*)(oh + r0g*EE + n)     = __floats2half2_rn(o[j][0]*i0, o[j][1]*i0);
        *(__half2*)(oh + (r0g+8)*EE + n) = __floats2half2_rn(o[j][2]*i1, o[j][3]*i1);
    }
}

// ---------------- launch ----------------------------------------------------
extern "C" void kernel_launch(void* const* d_in, const int* in_sizes, int n_in,
                              void* d_out, int out_size) {
    const float* x  = (const float*)d_in[0];
    const float* Wq = (const float*)d_in[1];
    const float* Wk = (const float*)d_in[2];
    const float* Wv = (const float*)d_in[3];
    const float* Wo = (const float*)d_in[4];
    const float* bo = (const float*)d_in[5];
    float* out = (float*)d_out;

    __half *p_rxh, *p_xh, *p_qh, *p_kh, *p_vh, *p_ath, *p_whi, *p_wlo;
    cudaGetSymbolAddress((void**)&p_rxh, g_rxh);
    cudaGetSymbolAddress((void**)&p_xh,  g_xh);
    cudaGetSymbolAddress((void**)&p_qh,  g_qh);
    cudaGetSymbolAddress((void**)&p_kh,  g_kh);
    cudaGetSymbolAddress((void**)&p_vh,  g_vh);
    cudaGetSymbolAddress((void**)&p_ath, g_ath);
    cudaGetSymbolAddress((void**)&p_whi, g_whi);
    cudaGetSymbolAddress((void**)&p_wlo, g_wlo);

    cudaFuncSetAttribute(hmma_gemm16_kernel<0>,
                         cudaFuncAttributeMaxDynamicSharedMemorySize, GEMM16_SMEM);
    cudaFuncSetAttribute(hmma_gemm16_kernel<1>,
                         cudaFuncAttributeMaxDynamicSharedMemorySize, GEMM16_SMEM);
    cudaFuncSetAttribute(flash_hmma_kernel,
                         cudaFuncAttributeMaxDynamicSharedMemorySize, FL_SMEM);

    theta_kernel<<<2, 256>>>();
    rope_fused_kernel<<<(MM*E2 + 255)/256, 256>>>(x);
    dim3 sgrid((EE*EE + 255)/256, 4);
    split_all_kernel<<<sgrid, 256>>>(Wq, Wk, Wv, Wo);

    // persistent fused Q/K/V projection (1536 tiles over 304 CTAs)
    hmma_gemm16_kernel<0><<<GPERS_GRID, 256, GEMM16_SMEM>>>(
        p_rxh, p_xh, p_whi, p_wlo, p_qh, p_kh, p_vh, nullptr, nullptr);

    dim3 fgrid(TT/128, BB*HH);         // (16, 64)
    flash_hmma_kernel<<<fgrid, 256, FL_SMEM>>>(p_qh, p_kh, p_vh, p_ath);

    // persistent O-projection (512 tiles over 304 CTAs); BASE weight pointers,
    // tile_of's z=3 applies the Wo offset exactly once.
    hmma_gemm16_kernel<1><<<GPERS_GRID, 256, GEMM16_SMEM>>>(
        p_ath, nullptr, p_whi, p_wlo,
        nullptr, nullptr, nullptr, out, bo);
}

// round 14
// speedup vs baseline: 5.7210x; 1.0437x over previous
#include <cuda_runtime.h>
#include <cuda_fp16.h>
#include <math.h>
#include <stdint.h>

// Problem constants
#define BB 4
#define TT 2048
#define EE 1024
#define HH 16
#define HD 64
#define MM (BB*TT)          // 8192 rows
#define E2 (EE/2)           // 512 pairs
#define GK 1024

// Q is pre-scaled by 0.125*log2(e) so flash softmax runs in base-2 domain.
#define QSCALE 0.18033688011112042f

// ---------------- scratch (device globals; no allocation allowed) ----------
__device__ float g_theta[E2];

__device__ __align__(256) __half g_rxh [MM*EE];   // RoPE(x), fp16
__device__ __align__(256) __half g_xh  [MM*EE];   // x, fp16
__device__ __align__(256) __half g_qh  [MM*EE];   // Q fp16 (pre-scaled)
__device__ __align__(256) __half g_kh  [MM*EE];   // K fp16
__device__ __align__(256) __half g_vh  [MM*EE];   // V fp16
__device__ __align__(256) __half g_ath [MM*EE];   // attention out fp16
__device__ __align__(256) __half g_whi [4][EE*EE];  // Wq,Wk,Wv,Wo hi
__device__ __align__(256) __half g_wlo [4][EE*EE];  // Wq,Wk,Wv,Wo lo

// ================= helpers (compute_80-level PTX only!) =====================
__device__ __forceinline__ uint32_t smem_u32(const void* p) {
    uint32_t a;
    asm("{ .reg .u64 t; cvta.to.shared.u64 t, %1; cvt.u32.u64 %0, t; }"
        : "=r"(a) : "l"(p));
    return a;
}
__device__ __forceinline__ void cp16(uint32_t saddr, const void* g) {
    asm volatile("cp.async.cg.shared.global [%0], [%1], 16;"
                 :: "r"(saddr), "l"(g) : "memory");
}
#define CP_COMMIT() asm volatile("cp.async.commit_group;" ::: "memory")
#define CP_WAIT(n)  asm volatile("cp.async.wait_group %0;" :: "n"(n) : "memory")

__device__ __forceinline__ void ldsm_x4(uint32_t* r, uint32_t addr) {
    asm volatile("ldmatrix.sync.aligned.m8n8.x4.shared.b16 {%0,%1,%2,%3}, [%4];"
                 : "=r"(r[0]), "=r"(r[1]), "=r"(r[2]), "=r"(r[3]) : "r"(addr));
}
__device__ __forceinline__ void ldsm_x4_t(uint32_t* r, uint32_t addr) {
    asm volatile("ldmatrix.sync.aligned.m8n8.x4.trans.shared.b16 {%0,%1,%2,%3}, [%4];"
                 : "=r"(r[0]), "=r"(r[1]), "=r"(r[2]), "=r"(r[3]) : "r"(addr));
}
__device__ __forceinline__ void mma_fp16(float* c, const uint32_t* a,
                                         const uint32_t* b) {
    asm volatile(
        "mma.sync.aligned.m16n8k16.row.col.f32.f16.f16.f32 "
        "{%0,%1,%2,%3}, {%4,%5,%6,%7}, {%8,%9}, {%0,%1,%2,%3};"
        : "+f"(c[0]), "+f"(c[1]), "+f"(c[2]), "+f"(c[3])
        : "r"(a[0]), "r"(a[1]), "r"(a[2]), "r"(a[3]), "r"(b[0]), "r"(b[1]));
}
// packed half2 2^x (one MUFU for two elements)
__device__ __forceinline__ uint32_t h2ex2(uint32_t x) {
    uint32_t r;
    asm("ex2.approx.f16x2 %0, %1;" : "=r"(r) : "r"(x));
    return r;
}

// ---------------- theta table ------------------------------------------------
__global__ void theta_kernel() {
    int p = blockIdx.x * blockDim.x + threadIdx.x;
    if (p >= E2) return;
    g_theta[p] = (float)exp((-(double)(2*p) / (double)EE) * log(10000.0));
}

// ---------------- fused RoPE (fp16 out) + x fp16 ------------------------------
#define P2HI 6.2831854820251465f
#define P2LO -1.7484555e-7f
#define INV2PI 0.15915494309189535f

__global__ void rope_fused_kernel(const float* __restrict__ x) {
    int idx = blockIdx.x * blockDim.x + threadIdx.x;   // over MM*E2 pairs
    if (idx >= MM*E2) return;
    int bt = idx / E2;
    int p  = idx % E2;
    int t  = bt % TT;
    float2 v = ((const float2*)x)[idx];
    float ang = (float)t * g_theta[p];      // fp32 rounding as in reference
    float n = rintf(ang * INV2PI);
    float r = fmaf(-n, P2HI, ang);
    r = fmaf(-n, P2LO, r);
    float s, c;
    sincosf(r, &s, &c);
    float rx = v.x * c - v.y * s;
    float ry = v.y * c + v.x * s;
    ((__half2*)g_rxh)[idx] = __floats2half2_rn(rx, ry);
    ((__half2*)g_xh)[idx]  = __floats2half2_rn(v.x, v.y);
}

// ---------------- all-W fp16 hi/lo split (one launch) -------------------------
__global__ void split_all_kernel(const float* __restrict__ Wq,
                                 const float* __restrict__ Wk,
                                 const float* __restrict__ Wv,
                                 const float* __restrict__ Wo) {
    int i = blockIdx.x * blockDim.x + threadIdx.x;
    if (i >= EE*EE) return;
    int w = blockIdx.y;
    const float* src = (w == 0) ? Wq : (w == 1) ? Wk : (w == 2) ? Wv : Wo;
    float x = src[i];
    __half h = __float2half_rn(x);
    g_whi[w][i] = h;
    g_wlo[w][i] = __float2half_rn(x - __half2float(h));
}

// ---------------- persistent 2-term fp16 NT GEMM, 2-stage, 2 CTAs/SM ---------
#define KSTEPS (GK/64)          // 16
#define TILE_B 16384            // 128 rows x 128 bytes
#define STG16_B (3*TILE_B)      // A|Wh|Wl = 48 KB
#define GEMM16_SMEM (2*STG16_B) // 96 KB -> 2 CTAs/SM
#define GPERS_GRID 304          // 152 SMs x 2 CTAs

template<int OUT>
__global__ __launch_bounds__(256, 2)
void hmma_gemm16_kernel(const __half* __restrict__ A0,
                        const __half* __restrict__ A2,
                        const __half* __restrict__ Whi0,
                        const __half* __restrict__ Wlo0,
                        __half* __restrict__ C16_0,
                        __half* __restrict__ C16_1,
                        __half* __restrict__ C16_2,
                        float* __restrict__ C32,
                        const float* __restrict__ bias) {
    extern __shared__ char sm[];
    const int tid  = threadIdx.x;
    const int wid  = tid >> 5;
    const int lane = tid & 31;
    const uint32_t sbase = smem_u32(sm);
    const int wm = wid >> 2;
    const int wn = wid & 3;
    const int G  = (int)gridDim.x;
    const int bx = (int)blockIdx.x;
    const int T  = (OUT == 0) ? 1536 : 512;
    const int nt = (T - bx + G - 1) / G;
    const int NC = nt << 4;

    auto tile_of = [&](int c, int& z, int& r0, int& c0) {
        int t = bx + (c >> 4) * G;
        if (OUT == 0) { z = t / 512; int rem = t & 511; r0 = (rem >> 3) << 7; c0 = (rem & 7) << 7; }
        else          { z = 3;       r0 = (t >> 3) << 7; c0 = (t & 7) << 7; }
    };

    auto load_chunk = [&](int s, int c) {
        if (c >= NC) return;
        int z, r0, c0; tile_of(c, z, r0, c0);
        const int k0 = (c & 15) * 64;
        const __half* A   = (OUT == 0 && z == 2) ? A2 : A0;
        const __half* srcs[3] = { A, Whi0 + (size_t)z*EE*EE, Wlo0 + (size_t)z*EE*EE };
        const uint32_t st = sbase + s * STG16_B;
        #pragma unroll
        for (int t = 0; t < 3; t++) {
            const int rb = (t == 0) ? r0 : c0;
            #pragma unroll
            for (int it = 0; it < 4; it++) {
                int u = tid + 256 * it;
                int r = u >> 3, cc = u & 7;
                const __half* g = srcs[t] + (size_t)(rb + r) * GK + k0 + cc * 8;
                uint32_t sa = st + t * TILE_B + r * 128 + ((cc ^ (r & 7)) * 16);
                cp16(sa, g);
            }
        }
    };

    load_chunk(0, 0); CP_COMMIT();

    float acc[4][4][4] = {};
    const int lr = lane & 15, lc = lane >> 4;

    uint32_t sw[4];
    #pragma unroll
    for (int k16 = 0; k16 < 4; k16++)
        sw[k16] = (uint32_t)(((k16*2 + lc) ^ (lr & 7)) * 16);
    const uint32_t baseA = (uint32_t)((wm*64 + lr) * 128);
    const uint32_t baseW = (uint32_t)((wn*32 + lr) * 128);

    for (int c = 0; c < NC; c++) {
        CP_WAIT(0);
        __syncthreads();
        load_chunk((c + 1) & 1, c + 1);
        CP_COMMIT();

        const uint32_t st = sbase + (c & 1) * STG16_B;
        const uint32_t aB = st + baseA;
        const uint32_t whB = st + TILE_B + baseW, wlB = st + 2*TILE_B + baseW;

        #pragma unroll
        for (int k16 = 0; k16 < 4; k16++) {
            const uint32_t s16 = sw[k16];
            uint32_t a[4][4], wh[4][2], wl[4][2];
            #pragma unroll
            for (int i = 0; i < 4; i++)
                ldsm_x4(a[i], aB + i*2048 + s16);
            #pragma unroll
            for (int jj = 0; jj < 2; jj++) {
                uint32_t t0[4], t1[4];
                ldsm_x4(t0, whB + jj*2048 + s16);
                wh[jj*2][0] = t0[0]; wh[jj*2][1] = t0[2];
                wh[jj*2+1][0] = t0[1]; wh[jj*2+1][1] = t0[3];
                ldsm_x4(t1, wlB + jj*2048 + s16);
                wl[jj*2][0] = t1[0]; wl[jj*2][1] = t1[2];
                wl[jj*2+1][0] = t1[1]; wl[jj*2+1][1] = t1[3];
            }
            #pragma unroll
            for (int i = 0; i < 4; i++)
                #pragma unroll
                for (int j = 0; j < 4; j++) {
                    mma_fp16(acc[i][j], a[i], wh[j]);
                    mma_fp16(acc[i][j], a[i], wl[j]);
                }
        }

        if ((c & 15) == 15) {
            int z, r0, c0; tile_of(c, z, r0, c0);
            const int gq = lane >> 2, tig = lane & 3;
            __half* C16 = (OUT == 0)
                ? ((z == 0) ? C16_0 : (z == 1) ? C16_1 : C16_2) : nullptr;
            const float osc = (OUT == 0 && z == 0) ? QSCALE : 1.f;
            #pragma unroll
            for (int j = 0; j < 4; j++) {
                const int n = c0 + wn*32 + j*8 + tig*2;
                float b0 = 0.f, b1 = 0.f;
                if (OUT == 1) { b0 = bias[n]; b1 = bias[n+1]; }
                #pragma unroll
                for (int i = 0; i < 4; i++) {
                    const int m0 = r0 + wm*64 + i*16 + gq;
                    if (OUT == 0) {
                        *(__half2*)(C16 + (size_t)m0*GK + n) =
                            __floats2half2_rn(acc[i][j][0]*osc, acc[i][j][1]*osc);
                        *(__half2*)(C16 + (size_t)(m0+8)*GK + n) =
                            __floats2half2_rn(acc[i][j][2]*osc, acc[i][j][3]*osc);
                    } else {
                        *(float2*)(C32 + (size_t)m0 * GK + n) =
                            make_float2(acc[i][j][0] + b0, acc[i][j][1] + b1);
                        *(float2*)(C32 + (size_t)(m0 + 8) * GK + n) =
                            make_float2(acc[i][j][2] + b0, acc[i][j][3] + b1);
                    }
                }
            }
            #pragma unroll
            for (int i = 0; i < 4; i++)
                #pragma unroll
                for (int j = 0; j < 4; j++) {
                    acc[i][j][0] = 0.f; acc[i][j][1] = 0.f;
                    acc[i][j][2] = 0.f; acc[i][j][3] = 0.f;
                }
        }
    }
}

// ---------------- HMMA flash attention (causal, fp16, base-2 softmax) --------
#define FL_QB   16384
#define FL_TB   8192
#define FL_STG  (2*FL_TB)
#define FL_NSTG 3
#define FL_SMEM (FL_QB + FL_NSTG*FL_STG)   // 64 KB

__global__ __launch_bounds__(256, 2)
void flash_hmma_kernel(const __half* __restrict__ qh,
                       const __half* __restrict__ kh,
                       const __half* __restrict__ vh,
                       __half* __restrict__ oh) {
    extern __shared__ char sm[];
    const int tid  = threadIdx.x;
    const int wid  = tid >> 5;
    const int lane = tid & 31;
    const int qt = (int)(gridDim.x - 1 - blockIdx.x);   // heavy tiles first
    const int bh = blockIdx.y;
    const int b = bh >> 4, h = bh & 15;
    const int qrow0 = qt * 128;
    const size_t grow0 = (size_t)b * TT + qrow0;
    const int colb = h * HD;

    const uint32_t sb  = smem_u32(sm);
    const uint32_t qB  = sb;
    const uint32_t stB = sb + FL_QB;

    #pragma unroll
    for (int it = 0; it < 4; it++) {
        int u = tid + 256 * it;
        int r = u >> 3, c = u & 7;
        cp16(qB + r*128 + ((c ^ (r & 7)) * 16),
             qh + (grow0 + r) * EE + colb + c * 8);
    }
    const __half* ksrc[2] = { kh, vh };
    auto load_stage = [&](int s, int kt) {
        const size_t krow = (size_t)b * TT + kt * 64;
        const uint32_t st = stB + s * FL_STG;
        #pragma unroll
        for (int t = 0; t < 2; t++) {
            #pragma unroll
            for (int it = 0; it < 2; it++) {
                int u = tid + 256 * it;
                int r = u >> 3, c = u & 7;
                cp16(st + t*FL_TB + r*128 + ((c ^ (r & 7)) * 16),
                     ksrc[t] + (krow + r) * EE + colb + c * 8);
            }
        }
    };
    const int nkv = 2*qt + 2;
    load_stage(0, 0); CP_COMMIT();
    if (1 < nkv) load_stage(1, 1);
    CP_COMMIT();

    CP_WAIT(1);
    __syncthreads();

    const int lr = lane & 15, lc = lane >> 4;
    uint32_t sw[4];
    #pragma unroll
    for (int k16 = 0; k16 < 4; k16++)
        sw[k16] = (uint32_t)(((k16*2 + lc) ^ (lr & 7)) * 16);
    const uint32_t baseQ = (uint32_t)((wid*16 + lr) * 128);
    const uint32_t baseK = (uint32_t)(lr * 128);

    const int mi = lane >> 3, li = lane & 7;
    uint32_t swv[4];
    #pragma unroll
    for (int dj = 0; dj < 4; dj++)
        swv[dj] = (uint32_t)(((dj*2 + (mi & 1)) ^ (li & 7)) * 16);
    const uint32_t baseV = (uint32_t)((((mi >> 1) ? 8 : 0) + li) * 128);

    uint32_t qf[4][4];
    #pragma unroll
    for (int k16 = 0; k16 < 4; k16++)
        ldsm_x4(qf[k16], qB + baseQ + sw[k16]);

    float m0 = -INFINITY, m1 = -INFINITY, l0 = 0.f, l1 = 0.f;
    float o[8][4] = {};
    const int rg0 = qrow0 + wid*16 + (lane >> 2);
    const int tig = lane & 3;

    for (int kt = 0; kt < nkv; kt++) {
        if (kt > 0) {
            CP_WAIT(1);
            __syncthreads();
        }
        if (kt + 2 < nkv) load_stage((kt + 2) % FL_NSTG, kt + 2);
        CP_COMMIT();

        const uint32_t st = stB + (kt % FL_NSTG) * FL_STG;
        const uint32_t kB = st + baseK, vB = st + FL_TB + baseV;

        // ---- S (log2-domain: Q pre-scaled by 0.125*log2e) ----
        float s[8][4] = {};
        #pragma unroll
        for (int k16 = 0; k16 < 4; k16++) {
            uint32_t kf[8][2];
            #pragma unroll
            for (int jj = 0; jj < 4; jj++) {
                uint32_t t0[4];
                ldsm_x4(t0, kB + jj*2048 + sw[k16]);
                kf[jj*2][0] = t0[0]; kf[jj*2][1] = t0[2];
                kf[jj*2+1][0] = t0[1]; kf[jj*2+1][1] = t0[3];
            }
            #pragma unroll
            for (int j = 0; j < 8; j++)
                mma_fp16(s[j], qf[k16], kf[j]);
        }

        // ---- causal mask (no scale needed) ----
        if (kt >= 2*qt) {
            #pragma unroll
            for (int j = 0; j < 8; j++) {
                int c0 = kt*64 + j*8 + tig*2;
                if (c0     > rg0)     s[j][0] = -INFINITY;
                if (c0 + 1 > rg0)     s[j][1] = -INFINITY;
                if (c0     > rg0 + 8) s[j][2] = -INFINITY;
                if (c0 + 1 > rg0 + 8) s[j][3] = -INFINITY;
            }
        }

        // ---- online softmax in base 2; P via packed ex2.approx.f16x2 ----
        float tm0 = -INFINITY, tm1 = -INFINITY;
        #pragma unroll
        for (int j = 0; j < 8; j++) {
            tm0 = fmaxf(tm0, fmaxf(s[j][0], s[j][1]));
            tm1 = fmaxf(tm1, fmaxf(s[j][2], s[j][3]));
        }
        tm0 = fmaxf(tm0, __shfl_xor_sync(0xffffffff, tm0, 1));
        tm0 = fmaxf(tm0, __shfl_xor_sync(0xffffffff, tm0, 2));
        tm1 = fmaxf(tm1, __shfl_xor_sync(0xffffffff, tm1, 1));
        tm1 = fmaxf(tm1, __shfl_xor_sync(0xffffffff, tm1, 2));
        float mn0 = fmaxf(m0, tm0), mn1 = fmaxf(m1, tm1);
        float a0 = exp2f(m0 - mn0), a1 = exp2f(m1 - mn1);

        uint32_t pH01[8], pH23[8];
        float rs0 = 0.f, rs1 = 0.f;
        #pragma unroll
        for (int j = 0; j < 8; j++) {
            __half2 d01 = __floats2half2_rn(fmaxf(s[j][0] - mn0, -30.f),
                                            fmaxf(s[j][1] - mn0, -30.f));
            __half2 d23 = __floats2half2_rn(fmaxf(s[j][2] - mn1, -30.f),
                                            fmaxf(s[j][3] - mn1, -30.f));
            uint32_t e01 = h2ex2(*(uint32_t*)&d01);
            uint32_t e23 = h2ex2(*(uint32_t*)&d23);
            pH01[j] = e01;
            pH23[j] = e23;
            float2 f01 = __half22float2(*(__half2*)&e01);
            float2 f23 = __half22float2(*(__half2*)&e23);
            rs0 += f01.x + f01.y;
            rs1 += f23.x + f23.y;
        }
        rs0 += __shfl_xor_sync(0xffffffff, rs0, 1);
        rs0 += __shfl_xor_sync(0xffffffff, rs0, 2);
        rs1 += __shfl_xor_sync(0xffffffff, rs1, 1);
        rs1 += __shfl_xor_sync(0xffffffff, rs1, 2);
        l0 = l0 * a0 + rs0;
        l1 = l1 * a1 + rs1;
        m0 = mn0; m1 = mn1;

        #pragma unroll
        for (int j = 0; j < 8; j++) {
            o[j][0] *= a0; o[j][1] *= a0;
            o[j][2] *= a1; o[j][3] *= a1;
        }

        // ---- O += P V ----
        #pragma unroll
        for (int c16 = 0; c16 < 4; c16++) {
            uint32_t aH[4] = { pH01[2*c16], pH23[2*c16], pH01[2*c16+1], pH23[2*c16+1] };
            #pragma unroll
            for (int dj = 0; dj < 4; dj++) {
                uint32_t t0[4];
                ldsm_x4_t(t0, vB + c16*2048 + swv[dj]);
                uint32_t v0[2] = { t0[0], t0[2] }, v1[2] = { t0[1], t0[3] };
                mma_fp16(o[dj*2],   aH, v0);
                mma_fp16(o[dj*2+1], aH, v1);
            }
        }
    }

    const float i0 = 1.f / l0, i1 = 1.f / l1;
    const size_t r0g = grow0 + wid*16 + (lane >> 2);
    #pragma unroll
    for (int j = 0; j < 8; j++) {
        const int n = colb + j*8 + tig*2;
        *(__half2*)(oh + r0g*EE + n)     = __floats2half2_rn(o[j][0]*i0, o[j][1]*i0);
        *(__half2*)(oh + (r0g+8)*EE + n) = __floats2half2_rn(o[j][2]*i1, o[j][3]*i1);
    }
}

// ---------------- launch ----------------------------------------------------
extern "C" void kernel_launch(void* const* d_in, const int* in_sizes, int n_in,
                              void* d_out, int out_size) {
    const float* x  = (const float*)d_in[0];
    const float* Wq = (const float*)d_in[1];
    const float* Wk = (const float*)d_in[2];
    const float* Wv = (const float*)d_in[3];
    const float* Wo = (const float*)d_in[4];
    const float* bo = (const float*)d_in[5];
    float* out = (float*)d_out;

    __half *p_rxh, *p_xh, *p_qh, *p_kh, *p_vh, *p_ath, *p_whi, *p_wlo;
    cudaGetSymbolAddress((void**)&p_rxh, g_rxh);
    cudaGetSymbolAddress((void**)&p_xh,  g_xh);
    cudaGetSymbolAddress((void**)&p_qh,  g_qh);
    cudaGetSymbolAddress((void**)&p_kh,  g_kh);
    cudaGetSymbolAddress((void**)&p_vh,  g_vh);
    cudaGetSymbolAddress((void**)&p_ath, g_ath);
    cudaGetSymbolAddress((void**)&p_whi, g_whi);
    cudaGetSymbolAddress((void**)&p_wlo, g_wlo);

    cudaFuncSetAttribute(hmma_gemm16_kernel<0>,
                         cudaFuncAttributeMaxDynamicSharedMemorySize, GEMM16_SMEM);
    cudaFuncSetAttribute(hmma_gemm16_kernel<1>,
                         cudaFuncAttributeMaxDynamicSharedMemorySize, GEMM16_SMEM);
    cudaFuncSetAttribute(flash_hmma_kernel,
                         cudaFuncAttributeMaxDynamicSharedMemorySize, FL_SMEM);

    theta_kernel<<<2, 256>>>();
    rope_fused_kernel<<<(MM*E2 + 255)/256, 256>>>(x);
    dim3 sgrid((EE*EE + 255)/256, 4);
    split_all_kernel<<<sgrid, 256>>>(Wq, Wk, Wv, Wo);

    // persistent fused Q/K/V projection (Q output pre-scaled by QSCALE)
    hmma_gemm16_kernel<0><<<GPERS_GRID, 256, GEMM16_SMEM>>>(
        p_rxh, p_xh, p_whi, p_wlo, p_qh, p_kh, p_vh, nullptr, nullptr);

    dim3 fgrid(TT/128, BB*HH);         // (16, 64)
    flash_hmma_kernel<<<fgrid, 256, FL_SMEM>>>(p_qh, p_kh, p_vh, p_ath);

    // persistent O-projection; BASE weight pointers (z=3 offsets once).
    hmma_gemm16_kernel<1><<<GPERS_GRID, 256, GEMM16_SMEM>>>(
        p_ath, nullptr, p_whi, p_wlo,
        nullptr, nullptr, nullptr, out, bo);
}

// round 15
// speedup vs baseline: 8.0583x; 1.4085x over previous
#include <cuda_runtime.h>
#include <cuda_fp16.h>
#include <math.h>
#include <stdint.h>

// Problem constants
#define BB 4
#define TT 2048
#define EE 1024
#define HH 16
#define HD 64
#define MM (BB*TT)          // 8192 rows
#define E2 (EE/2)           // 512 pairs
#define GK 1024

// Q is pre-scaled by 0.125*log2(e) so flash softmax runs in base-2 domain.
#define QSCALE 0.18033688011112042f

// ---------------- scratch (device globals; no allocation allowed) ----------
__device__ float g_theta[E2];

__device__ __align__(256) __half g_rxh [MM*EE];   // RoPE(x), fp16
__device__ __align__(256) __half g_xh  [MM*EE];   // x, fp16
__device__ __align__(256) __half g_qh  [MM*EE];   // Q fp16 (pre-scaled)
__device__ __align__(256) __half g_kh  [MM*EE];   // K fp16
__device__ __align__(256) __half g_vh  [MM*EE];   // V fp16
__device__ __align__(256) __half g_ath [MM*EE];   // attention out fp16
__device__ __align__(256) __half g_wh  [4][EE*EE];  // Wq,Wk,Wv,Wo fp16

// ================= helpers (compute_80-level PTX only!) =====================
__device__ __forceinline__ uint32_t smem_u32(const void* p) {
    uint32_t a;
    asm("{ .reg .u64 t; cvta.to.shared.u64 t, %1; cvt.u32.u64 %0, t; }"
        : "=r"(a) : "l"(p));
    return a;
}
__device__ __forceinline__ void cp16(uint32_t saddr, const void* g) {
    asm volatile("cp.async.cg.shared.global [%0], [%1], 16;"
                 :: "r"(saddr), "l"(g) : "memory");
}
#define CP_COMMIT() asm volatile("cp.async.commit_group;" ::: "memory")
#define CP_WAIT(n)  asm volatile("cp.async.wait_group %0;" :: "n"(n) : "memory")

__device__ __forceinline__ void ldsm_x4(uint32_t* r, uint32_t addr) {
    asm volatile("ldmatrix.sync.aligned.m8n8.x4.shared.b16 {%0,%1,%2,%3}, [%4];"
                 : "=r"(r[0]), "=r"(r[1]), "=r"(r[2]), "=r"(r[3]) : "r"(addr));
}
__device__ __forceinline__ void ldsm_x4_t(uint32_t* r, uint32_t addr) {
    asm volatile("ldmatrix.sync.aligned.m8n8.x4.trans.shared.b16 {%0,%1,%2,%3}, [%4];"
                 : "=r"(r[0]), "=r"(r[1]), "=r"(r[2]), "=r"(r[3]) : "r"(addr));
}
__device__ __forceinline__ void mma_fp16(float* c, const uint32_t* a,
                                         const uint32_t* b) {
    asm volatile(
        "mma.sync.aligned.m16n8k16.row.col.f32.f16.f16.f32 "
        "{%0,%1,%2,%3}, {%4,%5,%6,%7}, {%8,%9}, {%0,%1,%2,%3};"
        : "+f"(c[0]), "+f"(c[1]), "+f"(c[2]), "+f"(c[3])
        : "r"(a[0]), "r"(a[1]), "r"(a[2]), "r"(a[3]), "r"(b[0]), "r"(b[1]));
}
// packed half2 2^x (one MUFU for two elements)
__device__ __forceinline__ uint32_t h2ex2(uint32_t x) {
    uint32_t r;
    asm("ex2.approx.f16x2 %0, %1;" : "=r"(r) : "r"(x));
    return r;
}

// ---------------- theta table ------------------------------------------------
__global__ void theta_kernel() {
    int p = blockIdx.x * blockDim.x + threadIdx.x;
    if (p >= E2) return;
    g_theta[p] = (float)exp((-(double)(2*p) / (double)EE) * log(10000.0));
}

// ---------------- fused RoPE (fp16 out) + x fp16 ------------------------------
#define P2HI 6.2831854820251465f
#define P2LO -1.7484555e-7f
#define INV2PI 0.15915494309189535f

__global__ void rope_fused_kernel(const float* __restrict__ x) {
    int idx = blockIdx.x * blockDim.x + threadIdx.x;   // over MM*E2 pairs
    if (idx >= MM*E2) return;
    int bt = idx / E2;
    int p  = idx % E2;
    int t  = bt % TT;
    float2 v = ((const float2*)x)[idx];
    float ang = (float)t * g_theta[p];      // fp32 rounding as in reference
    float n = rintf(ang * INV2PI);
    float r = fmaf(-n, P2HI, ang);
    r = fmaf(-n, P2LO, r);
    float s, c;
    sincosf(r, &s, &c);
    float rx = v.x * c - v.y * s;
    float ry = v.y * c + v.x * s;
    ((__half2*)g_rxh)[idx] = __floats2half2_rn(rx, ry);
    ((__half2*)g_xh)[idx]  = __floats2half2_rn(v.x, v.y);
}

// ---------------- all-W fp16 convert (one launch) -----------------------------
__global__ void split_all_kernel(const float* __restrict__ Wq,
                                 const float* __restrict__ Wk,
                                 const float* __restrict__ Wv,
                                 const float* __restrict__ Wo) {
    int i = blockIdx.x * blockDim.x + threadIdx.x;
    if (i >= EE*EE) return;
    int w = blockIdx.y;
    const float* src = (w == 0) ? Wq : (w == 1) ? Wk : (w == 2) ? Wv : Wo;
    g_wh[w][i] = __float2half_rn(src[i]);
}

// ---------------- persistent single-term fp16 NT GEMM, 3-stage, 2 CTAs/SM ----
// OUT: 0 = fused QKV (1536 tiles, fp16 out), 1 = O-proj (512 tiles, fp32+bias).
#define KSTEPS (GK/64)          // 16
#define TILE_B 16384            // 128 rows x 128 bytes
#define STG16_B (2*TILE_B)      // A|W = 32 KB
#define GEMM16_SMEM (3*STG16_B) // 96 KB -> 2 CTAs/SM
#define GPERS_GRID 304          // 152 SMs x 2 CTAs

template<int OUT>
__global__ __launch_bounds__(256, 2)
void hmma_gemm16_kernel(const __half* __restrict__ A0,
                        const __half* __restrict__ A2,
                        const __half* __restrict__ W0,
                        __half* __restrict__ C16_0,
                        __half* __restrict__ C16_1,
                        __half* __restrict__ C16_2,
                        float* __restrict__ C32,
                        const float* __restrict__ bias) {
    extern __shared__ char sm[];
    const int tid  = threadIdx.x;
    const int wid  = tid >> 5;
    const int lane = tid & 31;
    const uint32_t sbase = smem_u32(sm);
    const int wm = wid >> 2;
    const int wn = wid & 3;
    const int G  = (int)gridDim.x;
    const int bx = (int)blockIdx.x;
    const int T  = (OUT == 0) ? 1536 : 512;
    const int nt = (T - bx + G - 1) / G;
    const int NC = nt << 4;

    auto tile_of = [&](int c, int& z, int& r0, int& c0) {
        int t = bx + (c >> 4) * G;
        if (OUT == 0) { z = t / 512; int rem = t & 511; r0 = (rem >> 3) << 7; c0 = (rem & 7) << 7; }
        else          { z = 3;       r0 = (t >> 3) << 7; c0 = (t & 7) << 7; }
    };

    auto load_chunk = [&](int s, int c) {
        if (c >= NC) return;
        int z, r0, c0; tile_of(c, z, r0, c0);
        const int k0 = (c & 15) * 64;
        const __half* A = (OUT == 0 && z == 2) ? A2 : A0;
        const __half* srcs[2] = { A, W0 + (size_t)z*EE*EE };
        const uint32_t st = sbase + s * STG16_B;
        #pragma unroll
        for (int t = 0; t < 2; t++) {
            const int rb = (t == 0) ? r0 : c0;
            #pragma unroll
            for (int it = 0; it < 4; it++) {
                int u = tid + 256 * it;
                int r = u >> 3, cc = u & 7;
                const __half* g = srcs[t] + (size_t)(rb + r) * GK + k0 + cc * 8;
                uint32_t sa = st + t * TILE_B + r * 128 + ((cc ^ (r & 7)) * 16);
                cp16(sa, g);
            }
        }
    };

    load_chunk(0, 0); CP_COMMIT();
    load_chunk(1, 1); CP_COMMIT();

    float acc[4][4][4] = {};
    const int lr = lane & 15, lc = lane >> 4;

    uint32_t sw[4];
    #pragma unroll
    for (int k16 = 0; k16 < 4; k16++)
        sw[k16] = (uint32_t)(((k16*2 + lc) ^ (lr & 7)) * 16);
    const uint32_t baseA = (uint32_t)((wm*64 + lr) * 128);
    const uint32_t baseW = (uint32_t)((wn*32 + lr) * 128);

    for (int c = 0; c < NC; c++) {
        CP_WAIT(1);
        __syncthreads();
        // stage (c+2)%3 was consumed in chunk c-1 (ordered by this barrier)
        load_chunk((c + 2) % 3, c + 2);
        CP_COMMIT();

        const uint32_t st = sbase + (c % 3) * STG16_B;
        const uint32_t aB = st + baseA;
        const uint32_t whB = st + TILE_B + baseW;

        #pragma unroll
        for (int k16 = 0; k16 < 4; k16++) {
            const uint32_t s16 = sw[k16];
            uint32_t a[4][4], wh[4][2];
            #pragma unroll
            for (int i = 0; i < 4; i++)
                ldsm_x4(a[i], aB + i*2048 + s16);
            #pragma unroll
            for (int jj = 0; jj < 2; jj++) {
                uint32_t t0[4];
                ldsm_x4(t0, whB + jj*2048 + s16);
                wh[jj*2][0] = t0[0]; wh[jj*2][1] = t0[2];
                wh[jj*2+1][0] = t0[1]; wh[jj*2+1][1] = t0[3];
            }
            #pragma unroll
            for (int i = 0; i < 4; i++)
                #pragma unroll
                for (int j = 0; j < 4; j++)
                    mma_fp16(acc[i][j], a[i], wh[j]);
        }

        if ((c & 15) == 15) {
            int z, r0, c0; tile_of(c, z, r0, c0);
            const int gq = lane >> 2, tig = lane & 3;
            __half* C16 = (OUT == 0)
                ? ((z == 0) ? C16_0 : (z == 1) ? C16_1 : C16_2) : nullptr;
            const float osc = (OUT == 0 && z == 0) ? QSCALE : 1.f;
            #pragma unroll
            for (int j = 0; j < 4; j++) {
                const int n = c0 + wn*32 + j*8 + tig*2;
                float b0 = 0.f, b1 = 0.f;
                if (OUT == 1) { b0 = bias[n]; b1 = bias[n+1]; }
                #pragma unroll
                for (int i = 0; i < 4; i++) {
                    const int m0 = r0 + wm*64 + i*16 + gq;
                    if (OUT == 0) {
                        *(__half2*)(C16 + (size_t)m0*GK + n) =
                            __floats2half2_rn(acc[i][j][0]*osc, acc[i][j][1]*osc);
                        *(__half2*)(C16 + (size_t)(m0+8)*GK + n) =
                            __floats2half2_rn(acc[i][j][2]*osc, acc[i][j][3]*osc);
                    } else {
                        *(float2*)(C32 + (size_t)m0 * GK + n) =
                            make_float2(acc[i][j][0] + b0, acc[i][j][1] + b1);
                        *(float2*)(C32 + (size_t)(m0 + 8) * GK + n) =
                            make_float2(acc[i][j][2] + b0, acc[i][j][3] + b1);
                    }
                }
            }
            #pragma unroll
            for (int i = 0; i < 4; i++)
                #pragma unroll
                for (int j = 0; j < 4; j++) {
                    acc[i][j][0] = 0.f; acc[i][j][1] = 0.f;
                    acc[i][j][2] = 0.f; acc[i][j][3] = 0.f;
                }
        }
    }
}

// ---------------- HMMA flash attention (causal, fp16, base-2 softmax) --------
#define FL_QB   16384
#define FL_TB   8192
#define FL_STG  (2*FL_TB)
#define FL_NSTG 3
#define FL_SMEM (FL_QB + FL_NSTG*FL_STG)   // 64 KB

__global__ __launch_bounds__(256, 2)
void flash_hmma_kernel(const __half* __restrict__ qh,
                       const __half* __restrict__ kh,
                       const __half* __restrict__ vh,
                       __half* __restrict__ oh) {
    extern __shared__ char sm[];
    const int tid  = threadIdx.x;
    const int wid  = tid >> 5;
    const int lane = tid & 31;
    const int qt = (int)(gridDim.x - 1 - blockIdx.x);   // heavy tiles first
    const int bh = blockIdx.y;
    const int b = bh >> 4, h = bh & 15;
    const int qrow0 = qt * 128;
    const size_t grow0 = (size_t)b * TT + qrow0;
    const int colb = h * HD;

    const uint32_t sb  = smem_u32(sm);
    const uint32_t qB  = sb;
    const uint32_t stB = sb + FL_QB;

    #pragma unroll
    for (int it = 0; it < 4; it++) {
        int u = tid + 256 * it;
        int r = u >> 3, c = u & 7;
        cp16(qB + r*128 + ((c ^ (r & 7)) * 16),
             qh + (grow0 + r) * EE + colb + c * 8);
    }
    const __half* ksrc[2] = { kh, vh };
    auto load_stage = [&](int s, int kt) {
        const size_t krow = (size_t)b * TT + kt * 64;
        const uint32_t st = stB + s * FL_STG;
        #pragma unroll
        for (int t = 0; t < 2; t++) {
            #pragma unroll
            for (int it = 0; it < 2; it++) {
                int u = tid + 256 * it;
                int r = u >> 3, c = u & 7;
                cp16(st + t*FL_TB + r*128 + ((c ^ (r & 7)) * 16),
                     ksrc[t] + (krow + r) * EE + colb + c * 8);
            }
        }
    };
    const int nkv = 2*qt + 2;
    load_stage(0, 0); CP_COMMIT();
    if (1 < nkv) load_stage(1, 1);
    CP_COMMIT();

    CP_WAIT(1);
    __syncthreads();

    const int lr = lane & 15, lc = lane >> 4;
    uint32_t sw[4];
    #pragma unroll
    for (int k16 = 0; k16 < 4; k16++)
        sw[k16] = (uint32_t)(((k16*2 + lc) ^ (lr & 7)) * 16);
    const uint32_t baseQ = (uint32_t)((wid*16 + lr) * 128);
    const uint32_t baseK = (uint32_t)(lr * 128);

    const int mi = lane >> 3, li = lane & 7;
    uint32_t swv[4];
    #pragma unroll
    for (int dj = 0; dj < 4; dj++)
        swv[dj] = (uint32_t)(((dj*2 + (mi & 1)) ^ (li & 7)) * 16);
    const uint32_t baseV = (uint32_t)((((mi >> 1) ? 8 : 0) + li) * 128);

    uint32_t qf[4][4];
    #pragma unroll
    for (int k16 = 0; k16 < 4; k16++)
        ldsm_x4(qf[k16], qB + baseQ + sw[k16]);

    float m0 = -INFINITY, m1 = -INFINITY, l0 = 0.f, l1 = 0.f;
    float o[8][4] = {};
    const int rg0 = qrow0 + wid*16 + (lane >> 2);
    const int tig = lane & 3;

    for (int kt = 0; kt < nkv; kt++) {
        if (kt > 0) {
            CP_WAIT(1);
            __syncthreads();
        }
        if (kt + 2 < nkv) load_stage((kt + 2) % FL_NSTG, kt + 2);
        CP_COMMIT();

        const uint32_t st = stB + (kt % FL_NSTG) * FL_STG;
        const uint32_t kB = st + baseK, vB = st + FL_TB + baseV;

        // ---- S (log2-domain: Q pre-scaled by 0.125*log2e) ----
        float s[8][4] = {};
        #pragma unroll
        for (int k16 = 0; k16 < 4; k16++) {
            uint32_t kf[8][2];
            #pragma unroll
            for (int jj = 0; jj < 4; jj++) {
                uint32_t t0[4];
                ldsm_x4(t0, kB + jj*2048 + sw[k16]);
                kf[jj*2][0] = t0[0]; kf[jj*2][1] = t0[2];
                kf[jj*2+1][0] = t0[1]; kf[jj*2+1][1] = t0[3];
            }
            #pragma unroll
            for (int j = 0; j < 8; j++)
                mma_fp16(s[j], qf[k16], kf[j]);
        }

        if (kt >= 2*qt) {
            #pragma unroll
            for (int j = 0; j < 8; j++) {
                int c0 = kt*64 + j*8 + tig*2;
                if (c0     > rg0)     s[j][0] = -INFINITY;
                if (c0 + 1 > rg0)     s[j][1] = -INFINITY;
                if (c0     > rg0 + 8) s[j][2] = -INFINITY;
                if (c0 + 1 > rg0 + 8) s[j][3] = -INFINITY;
            }
        }

        float tm0 = -INFINITY, tm1 = -INFINITY;
        #pragma unroll
        for (int j = 0; j < 8; j++) {
            tm0 = fmaxf(tm0, fmaxf(s[j][0], s[j][1]));
            tm1 = fmaxf(tm1, fmaxf(s[j][2], s[j][3]));
        }
        tm0 = fmaxf(tm0, __shfl_xor_sync(0xffffffff, tm0, 1));
        tm0 = fmaxf(tm0, __shfl_xor_sync(0xffffffff, tm0, 2));
        tm1 = fmaxf(tm1, __shfl_xor_sync(0xffffffff, tm1, 1));
        tm1 = fmaxf(tm1, __shfl_xor_sync(0xffffffff, tm1, 2));
        float mn0 = fmaxf(m0, tm0), mn1 = fmaxf(m1, tm1);
        float a0 = exp2f(m0 - mn0), a1 = exp2f(m1 - mn1);

        uint32_t pH01[8], pH23[8];
        float rs0 = 0.f, rs1 = 0.f;
        #pragma unroll
        for (int j = 0; j < 8; j++) {
            __half2 d01 = __floats2half2_rn(fmaxf(s[j][0] - mn0, -30.f),
                                            fmaxf(s[j][1] - mn0, -30.f));
            __half2 d23 = __floats2half2_rn(fmaxf(s[j][2] - mn1, -30.f),
                                            fmaxf(s[j][3] - mn1, -30.f));
            uint32_t e01 = h2ex2(*(uint32_t*)&d01);
            uint32_t e23 = h2ex2(*(uint32_t*)&d23);
            pH01[j] = e01;
            pH23[j] = e23;
            float2 f01 = __half22float2(*(__half2*)&e01);
            float2 f23 = __half22float2(*(__half2*)&e23);
            rs0 += f01.x + f01.y;
            rs1 += f23.x + f23.y;
        }
        rs0 += __shfl_xor_sync(0xffffffff, rs0, 1);
        rs0 += __shfl_xor_sync(0xffffffff, rs0, 2);
        rs1 += __shfl_xor_sync(0xffffffff, rs1, 1);
        rs1 += __shfl_xor_sync(0xffffffff, rs1, 2);
        l0 = l0 * a0 + rs0;
        l1 = l1 * a1 + rs1;
        m0 = mn0; m1 = mn1;

        #pragma unroll
        for (int j = 0; j < 8; j++) {
            o[j][0] *= a0; o[j][1] *= a0;
            o[j][2] *= a1; o[j][3] *= a1;
        }

        #pragma unroll
        for (int c16 = 0; c16 < 4; c16++) {
            uint32_t aH[4] = { pH01[2*c16], pH23[2*c16], pH01[2*c16+1], pH23[2*c16+1] };
            #pragma unroll
            for (int dj = 0; dj < 4; dj++) {
                uint32_t t0[4];
                ldsm_x4_t(t0, vB + c16*2048 + swv[dj]);
                uint32_t v0[2] = { t0[0], t0[2] }, v1[2] = { t0[1], t0[3] };
                mma_fp16(o[dj*2],   aH, v0);
                mma_fp16(o[dj*2+1], aH, v1);
            }
        }
    }

    const float i0 = 1.f / l0, i1 = 1.f / l1;
    const size_t r0g = grow0 + wid*16 + (lane >> 2);
    #pragma unroll
    for (int j = 0; j < 8; j++) {
        const int n = colb + j*8 + tig*2;
        *(__half2*)(oh + r0g*EE + n)     = __floats2half2_rn(o[j][0]*i0, o[j][1]*i0);
        *(__half2*)(oh + (r0g+8)*EE + n) = __floats2half2_rn(o[j][2]*i1, o[j][3]*i1);
    }
}

// ---------------- launch ----------------------------------------------------
extern "C" void kernel_launch(void* const* d_in, const int* in_sizes, int n_in,
                              void* d_out, int out_size) {
    const float* x  = (const float*)d_in[0];
    const float* Wq = (const float*)d_in[1];
    const float* Wk = (const float*)d_in[2];
    const float* Wv = (const float*)d_in[3];
    const float* Wo = (const float*)d_in[4];
    const float* bo = (const float*)d_in[5];
    float* out = (float*)d_out;

    __half *p_rxh, *p_xh, *p_qh, *p_kh, *p_vh, *p_ath, *p_wh;
    cudaGetSymbolAddress((void**)&p_rxh, g_rxh);
    cudaGetSymbolAddress((void**)&p_xh,  g_xh);
    cudaGetSymbolAddress((void**)&p_qh,  g_qh);
    cudaGetSymbolAddress((void**)&p_kh,  g_kh);
    cudaGetSymbolAddress((void**)&p_vh,  g_vh);
    cudaGetSymbolAddress((void**)&p_ath, g_ath);
    cudaGetSymbolAddress((void**)&p_wh,  g_wh);

    cudaFuncSetAttribute(hmma_gemm16_kernel<0>,
                         cudaFuncAttributeMaxDynamicSharedMemorySize, GEMM16_SMEM);
    cudaFuncSetAttribute(hmma_gemm16_kernel<1>,
                         cudaFuncAttributeMaxDynamicSharedMemorySize, GEMM16_SMEM);
    cudaFuncSetAttribute(flash_hmma_kernel,
                         cudaFuncAttributeMaxDynamicSharedMemorySize, FL_SMEM);

    theta_kernel<<<2, 256>>>();
    rope_fused_kernel<<<(MM*E2 + 255)/256, 256>>>(x);
    dim3 sgrid((EE*EE + 255)/256, 4);
    split_all_kernel<<<sgrid, 256>>>(Wq, Wk, Wv, Wo);

    // persistent fused Q/K/V projection (Q output pre-scaled by QSCALE)
    hmma_gemm16_kernel<0><<<GPERS_GRID, 256, GEMM16_SMEM>>>(
        p_rxh, p_xh, p_wh, p_qh, p_kh, p_vh, nullptr, nullptr);

    dim3 fgrid(TT/128, BB*HH);         // (16, 64)
    flash_hmma_kernel<<<fgrid, 256, FL_SMEM>>>(p_qh, p_kh, p_vh, p_ath);

    // persistent O-projection; base weight pointer (z=3 offsets once).
    hmma_gemm16_kernel<1><<<GPERS_GRID, 256, GEMM16_SMEM>>>(
        p_ath, nullptr, p_wh, nullptr, nullptr, nullptr, out, bo);
}